// round 1
// baseline (speedup 1.0000x reference)
#include <cuda_runtime.h>
#include <cuda_bf16.h>
#include <math.h>

// Problem constants
#define B_  4
#define T_  2048
#define C_  1024
#define H_  16
#define HD_ 64
#define M_  (B_ * T_)   // 8192

// ---------------------------------------------------------------------------
// Scratch (allocation-free rule: __device__ globals)
// ---------------------------------------------------------------------------
__device__ float g_Q[(size_t)B_ * H_ * T_ * HD_];    // [B,H,T,HD]
__device__ float g_K[(size_t)B_ * H_ * T_ * HD_];
__device__ float g_V[(size_t)B_ * H_ * T_ * HD_];
__device__ float g_CTX[(size_t)B_ * T_ * C_];        // [B,T,C]

// ---------------------------------------------------------------------------
// SGEMM:  out[m,n] = sum_k A[m,k] * W[n,k]   (A:[M,K] row-major, W:[N,K] row-major)
// 128x128 tile, BK=16, 256 threads, 8x8 register blocking.
// mode 0: out row-major [M,N]
// mode 1: out in [B,H,T,HD] head layout (QKV projections)
// ---------------------------------------------------------------------------
__global__ void __launch_bounds__(256) gemm128_nt(
    const float* __restrict__ A, const float* __restrict__ W,
    float* __restrict__ out, int M, int N, int K, int mode)
{
    __shared__ float As[16][128];
    __shared__ float Ws[16][128];

    const int bm = blockIdx.y * 128;
    const int bn = blockIdx.x * 128;
    const int tid = threadIdx.x;
    const int tr = tid >> 4;      // 0..15
    const int tc = tid & 15;      // 0..15

    float acc[8][8];
    #pragma unroll
    for (int i = 0; i < 8; i++)
        #pragma unroll
        for (int j = 0; j < 8; j++) acc[i][j] = 0.f;

    for (int k0 = 0; k0 < K; k0 += 16) {
        // Load tiles: 128 rows x 16 cols each = 512 float4 per tile
        #pragma unroll
        for (int u = 0; u < 2; u++) {
            int i   = tid + u * 256;     // 0..511
            int row = i >> 2;
            int c4  = (i & 3) * 4;
            float4 va = *(const float4*)&A[(size_t)(bm + row) * K + k0 + c4];
            As[c4 + 0][row] = va.x; As[c4 + 1][row] = va.y;
            As[c4 + 2][row] = va.z; As[c4 + 3][row] = va.w;
            float4 vw = *(const float4*)&W[(size_t)(bn + row) * K + k0 + c4];
            Ws[c4 + 0][row] = vw.x; Ws[c4 + 1][row] = vw.y;
            Ws[c4 + 2][row] = vw.z; Ws[c4 + 3][row] = vw.w;
        }
        __syncthreads();

        #pragma unroll
        for (int k = 0; k < 16; k++) {
            float a[8], b[8];
            *(float4*)&a[0] = *(const float4*)&As[k][tr * 8 + 0];
            *(float4*)&a[4] = *(const float4*)&As[k][tr * 8 + 4];
            *(float4*)&b[0] = *(const float4*)&Ws[k][tc * 8 + 0];
            *(float4*)&b[4] = *(const float4*)&Ws[k][tc * 8 + 4];
            #pragma unroll
            for (int i = 0; i < 8; i++)
                #pragma unroll
                for (int j = 0; j < 8; j++)
                    acc[i][j] = fmaf(a[i], b[j], acc[i][j]);
        }
        __syncthreads();
    }

    // Epilogue
    if (mode == 0) {
        #pragma unroll
        for (int i = 0; i < 8; i++) {
            int m = bm + tr * 8 + i;
            #pragma unroll
            for (int j = 0; j < 8; j += 4) {
                int n = bn + tc * 8 + j;
                float4 r = make_float4(acc[i][j], acc[i][j+1], acc[i][j+2], acc[i][j+3]);
                *(float4*)&out[(size_t)m * N + n] = r;
            }
        }
    } else {
        // [B,H,T,HD] layout: m = b*T + t ; n = h*HD + d
        #pragma unroll
        for (int i = 0; i < 8; i++) {
            int m = bm + tr * 8 + i;
            int b = m >> 11;            // /T_ (2048)
            int t = m & (T_ - 1);
            #pragma unroll
            for (int j = 0; j < 8; j += 4) {
                int n = bn + tc * 8 + j;
                int h = n >> 6;         // /HD_
                int d = n & (HD_ - 1);
                float4 r = make_float4(acc[i][j], acc[i][j+1], acc[i][j+2], acc[i][j+3]);
                *(float4*)&out[(((size_t)b * H_ + h) * T_ + t) * HD_ + d] = r;
            }
        }
    }
}

// ---------------------------------------------------------------------------
// Flash attention, fp32, causal, BQ=BK=64, HD=64, 256 threads (16x16, 4x4 tiles)
// Q,K,V: [B,H,T,HD].  Output ctx: [B,T,C] (heads re-interleaved).
// ---------------------------------------------------------------------------
#define AT_STRIDE 68   // 64 + 4 pad, keeps float4 alignment
#define AT_SMEM_FLOATS (4 * 64 * AT_STRIDE)
#define AT_SMEM_BYTES  (AT_SMEM_FLOATS * 4)

__global__ void __launch_bounds__(256) flash_attn_kernel(
    const float* __restrict__ Q, const float* __restrict__ K,
    const float* __restrict__ V, float* __restrict__ ctx)
{
    extern __shared__ float sm[];
    float* Qs = sm;                   // [64][68]
    float* Ks = Qs + 64 * AT_STRIDE;
    float* Vs = Ks + 64 * AT_STRIDE;
    float* Ps = Vs + 64 * AT_STRIDE;

    const int qb = blockIdx.x;        // query block 0..31
    const int bh = blockIdx.y;        // b*H + h, 0..63
    const int q0 = qb * 64;
    const size_t base = (size_t)bh * T_ * HD_;

    const int tid = threadIdx.x;
    const int ty = tid >> 4;          // 0..15 -> query rows ty*4..ty*4+3
    const int tx = tid & 15;          // 0..15 -> key cols  tx*4..tx*4+3

    // Load Q tile (64x64 = 1024 float4)
    #pragma unroll
    for (int u = 0; u < 4; u++) {
        int i   = tid + u * 256;
        int row = i >> 4;
        int c   = (i & 15) * 4;
        *(float4*)&Qs[row * AT_STRIDE + c] =
            *(const float4*)&Q[base + (size_t)(q0 + row) * HD_ + c];
    }

    float o[4][4];
    float mrow[4], lrow[4];
    #pragma unroll
    for (int i = 0; i < 4; i++) {
        mrow[i] = -1e30f; lrow[i] = 0.f;
        #pragma unroll
        for (int j = 0; j < 4; j++) o[i][j] = 0.f;
    }

    const float scale = 0.125f;       // 1/sqrt(64)
    const int nkv = qb + 1;           // causal: only blocks <= diagonal

    for (int kb = 0; kb < nkv; kb++) {
        const int k0 = kb * 64;
        // Load K,V tiles
        #pragma unroll
        for (int u = 0; u < 4; u++) {
            int i   = tid + u * 256;
            int row = i >> 4;
            int c   = (i & 15) * 4;
            *(float4*)&Ks[row * AT_STRIDE + c] =
                *(const float4*)&K[base + (size_t)(k0 + row) * HD_ + c];
            *(float4*)&Vs[row * AT_STRIDE + c] =
                *(const float4*)&V[base + (size_t)(k0 + row) * HD_ + c];
        }
        __syncthreads();

        // S = Q @ K^T  (each thread 4x4)
        float s[4][4];
        #pragma unroll
        for (int i = 0; i < 4; i++)
            #pragma unroll
            for (int j = 0; j < 4; j++) s[i][j] = 0.f;

        #pragma unroll
        for (int kk = 0; kk < 64; kk += 4) {
            float4 a[4], b[4];
            #pragma unroll
            for (int i = 0; i < 4; i++)
                a[i] = *(const float4*)&Qs[(ty * 4 + i) * AT_STRIDE + kk];
            #pragma unroll
            for (int j = 0; j < 4; j++)
                b[j] = *(const float4*)&Ks[(tx * 4 + j) * AT_STRIDE + kk];
            #pragma unroll
            for (int i = 0; i < 4; i++)
                #pragma unroll
                for (int j = 0; j < 4; j++)
                    s[i][j] += a[i].x * b[j].x + a[i].y * b[j].y
                             + a[i].z * b[j].z + a[i].w * b[j].w;
        }

        // Scale + causal mask (diagonal block only)
        const bool diag = (kb == qb);
        #pragma unroll
        for (int i = 0; i < 4; i++)
            #pragma unroll
            for (int j = 0; j < 4; j++) {
                float v = s[i][j] * scale;
                if (diag && (k0 + tx * 4 + j > q0 + ty * 4 + i)) v = -1e30f;
                s[i][j] = v;
            }

        // Online softmax: row max / rescale / exp / row sum
        float mnew[4], csc[4];
        #pragma unroll
        for (int i = 0; i < 4; i++) {
            float lm = fmaxf(fmaxf(s[i][0], s[i][1]), fmaxf(s[i][2], s[i][3]));
            #pragma unroll
            for (int off = 8; off; off >>= 1)
                lm = fmaxf(lm, __shfl_xor_sync(0xffffffffu, lm, off));
            mnew[i] = fmaxf(mrow[i], lm);
            csc[i]  = __expf(mrow[i] - mnew[i]);
            mrow[i] = mnew[i];
        }
        #pragma unroll
        for (int i = 0; i < 4; i++) {
            float rs = 0.f;
            #pragma unroll
            for (int j = 0; j < 4; j++) {
                float p = __expf(s[i][j] - mnew[i]);
                s[i][j] = p; rs += p;
            }
            #pragma unroll
            for (int off = 8; off; off >>= 1)
                rs += __shfl_xor_sync(0xffffffffu, rs, off);
            lrow[i] = lrow[i] * csc[i] + rs;
            #pragma unroll
            for (int j = 0; j < 4; j++) o[i][j] *= csc[i];
        }

        // P -> smem
        #pragma unroll
        for (int i = 0; i < 4; i++)
            *(float4*)&Ps[(ty * 4 + i) * AT_STRIDE + tx * 4] =
                make_float4(s[i][0], s[i][1], s[i][2], s[i][3]);
        __syncthreads();

        // O += P @ V
        #pragma unroll 8
        for (int kk = 0; kk < 64; kk++) {
            float4 vv = *(const float4*)&Vs[kk * AT_STRIDE + tx * 4];
            float p0 = Ps[(ty * 4 + 0) * AT_STRIDE + kk];
            float p1 = Ps[(ty * 4 + 1) * AT_STRIDE + kk];
            float p2 = Ps[(ty * 4 + 2) * AT_STRIDE + kk];
            float p3 = Ps[(ty * 4 + 3) * AT_STRIDE + kk];
            o[0][0] = fmaf(p0, vv.x, o[0][0]); o[0][1] = fmaf(p0, vv.y, o[0][1]);
            o[0][2] = fmaf(p0, vv.z, o[0][2]); o[0][3] = fmaf(p0, vv.w, o[0][3]);
            o[1][0] = fmaf(p1, vv.x, o[1][0]); o[1][1] = fmaf(p1, vv.y, o[1][1]);
            o[1][2] = fmaf(p1, vv.z, o[1][2]); o[1][3] = fmaf(p1, vv.w, o[1][3]);
            o[2][0] = fmaf(p2, vv.x, o[2][0]); o[2][1] = fmaf(p2, vv.y, o[2][1]);
            o[2][2] = fmaf(p2, vv.z, o[2][2]); o[2][3] = fmaf(p2, vv.w, o[2][3]);
            o[3][0] = fmaf(p3, vv.x, o[3][0]); o[3][1] = fmaf(p3, vv.y, o[3][1]);
            o[3][2] = fmaf(p3, vv.z, o[3][2]); o[3][3] = fmaf(p3, vv.w, o[3][3]);
        }
        __syncthreads();
    }

    // Normalize and store into [B,T,C] with heads re-interleaved
    const int b = bh / H_;
    const int h = bh % H_;
    #pragma unroll
    for (int i = 0; i < 4; i++) {
        float inv = 1.f / lrow[i];
        int t = q0 + ty * 4 + i;
        float4 r = make_float4(o[i][0] * inv, o[i][1] * inv,
                               o[i][2] * inv, o[i][3] * inv);
        *(float4*)&ctx[((size_t)b * T_ + t) * C_ + h * HD_ + tx * 4] = r;
    }
}

// ---------------------------------------------------------------------------
// kernel_launch: x, Wq, Wk, Wv, Wo  ->  out [B,T,C] fp32
// ---------------------------------------------------------------------------
extern "C" void kernel_launch(void* const* d_in, const int* in_sizes, int n_in,
                              void* d_out, int out_size)
{
    const float* x  = (const float*)d_in[0];
    const float* Wq = (const float*)d_in[1];
    const float* Wk = (const float*)d_in[2];
    const float* Wv = (const float*)d_in[3];
    const float* Wo = (const float*)d_in[4];
    float* out = (float*)d_out;

    float *q, *k, *v, *ctx;
    cudaGetSymbolAddress((void**)&q,   g_Q);
    cudaGetSymbolAddress((void**)&k,   g_K);
    cudaGetSymbolAddress((void**)&v,   g_V);
    cudaGetSymbolAddress((void**)&ctx, g_CTX);

    cudaFuncSetAttribute(flash_attn_kernel,
                         cudaFuncAttributeMaxDynamicSharedMemorySize, AT_SMEM_BYTES);

    dim3 gg(C_ / 128, M_ / 128);   // (8, 64)

    // QKV projections into head layout
    gemm128_nt<<<gg, 256>>>(x, Wq, q, M_, C_, C_, 1);
    gemm128_nt<<<gg, 256>>>(x, Wk, k, M_, C_, C_, 1);
    gemm128_nt<<<gg, 256>>>(x, Wv, v, M_, C_, C_, 1);

    // Causal flash attention
    flash_attn_kernel<<<dim3(T_ / 64, B_ * H_), 256, AT_SMEM_BYTES>>>(q, k, v, ctx);

    // Output projection
    gemm128_nt<<<gg, 256>>>(ctx, Wo, out, M_, C_, C_, 0);
}

// round 3
// speedup vs baseline: 1.4618x; 1.4618x over previous
#include <cuda_runtime.h>
#include <cuda_bf16.h>
#include <cstdint>
#include <math.h>

// Problem constants
#define B_  4
#define T_  2048
#define C_  1024
#define H_  16
#define HD_ 64
#define M_  (B_ * T_)   // 8192

// ---------------------------------------------------------------------------
// Scratch (__device__ globals, allocation-free rule)
// ---------------------------------------------------------------------------
__device__ __nv_bfloat16 g_Xhi[(size_t)M_ * C_];
__device__ __nv_bfloat16 g_Xlo[(size_t)M_ * C_];
__device__ __nv_bfloat16 g_Whi[4][(size_t)C_ * C_];
__device__ __nv_bfloat16 g_Wlo[4][(size_t)C_ * C_];
__device__ float g_Q[(size_t)B_ * H_ * T_ * HD_];
__device__ float g_K[(size_t)B_ * H_ * T_ * HD_];
__device__ float g_V[(size_t)B_ * H_ * T_ * HD_];
__device__ __nv_bfloat16 g_CTXhi[(size_t)M_ * C_];
__device__ __nv_bfloat16 g_CTXlo[(size_t)M_ * C_];

// ---------------------------------------------------------------------------
// Helpers: ldmatrix + mma.sync (HMMA path, legal on base sm_103 target)
// ---------------------------------------------------------------------------
__device__ __forceinline__ uint32_t smem_u32(const void* p) {
    uint32_t a;
    asm("{ .reg .u64 t; cvta.to.shared.u64 t, %1; cvt.u32.u64 %0, t; }"
        : "=r"(a) : "l"(p));
    return a;
}
__device__ __forceinline__ void ldsm_x4(uint32_t* r, uint32_t addr) {
    asm volatile("ldmatrix.sync.aligned.m8n8.x4.shared.b16 {%0,%1,%2,%3}, [%4];"
        : "=r"(r[0]), "=r"(r[1]), "=r"(r[2]), "=r"(r[3]) : "r"(addr));
}
__device__ __forceinline__ void ldsm_x2(uint32_t* r, uint32_t addr) {
    asm volatile("ldmatrix.sync.aligned.m8n8.x2.shared.b16 {%0,%1}, [%2];"
        : "=r"(r[0]), "=r"(r[1]) : "r"(addr));
}
__device__ __forceinline__ void mma_bf16(float* d, const uint32_t* a,
                                         const uint32_t* b) {
    asm volatile(
        "mma.sync.aligned.m16n8k16.row.col.f32.bf16.bf16.f32 "
        "{%0,%1,%2,%3}, {%4,%5,%6,%7}, {%8,%9}, {%0,%1,%2,%3};"
        : "+f"(d[0]), "+f"(d[1]), "+f"(d[2]), "+f"(d[3])
        : "r"(a[0]), "r"(a[1]), "r"(a[2]), "r"(a[3]), "r"(b[0]), "r"(b[1]));
}

// ---------------------------------------------------------------------------
// Split-precision conversion: fp32 -> bf16 hi + bf16 lo
// ---------------------------------------------------------------------------
__global__ void split_bf16(const float* __restrict__ src,
                           __nv_bfloat16* __restrict__ hi,
                           __nv_bfloat16* __restrict__ lo, int n4)
{
    int i = blockIdx.x * blockDim.x + threadIdx.x;
    if (i >= n4) return;
    float4 v = ((const float4*)src)[i];
    float vv[4] = {v.x, v.y, v.z, v.w};
    __nv_bfloat16 h[4], l[4];
    #pragma unroll
    for (int j = 0; j < 4; j++) {
        h[j] = __float2bfloat16(vv[j]);
        l[j] = __float2bfloat16(vv[j] - __bfloat162float(h[j]));
    }
    ((__nv_bfloat162*)hi)[2 * i + 0] = __nv_bfloat162(h[0], h[1]);
    ((__nv_bfloat162*)hi)[2 * i + 1] = __nv_bfloat162(h[2], h[3]);
    ((__nv_bfloat162*)lo)[2 * i + 0] = __nv_bfloat162(l[0], l[1]);
    ((__nv_bfloat162*)lo)[2 * i + 1] = __nv_bfloat162(l[2], l[3]);
}

// ---------------------------------------------------------------------------
// HMMA GEMM: out[m,n] = sum_k A[m,k]*B[n,k], split-bf16 (3 products).
// CTA 128x128, BK=32, 256 threads (8 warps, 2M x 4N), double-buffered smem,
// gmem->reg->smem software pipeline. 80B smem row stride (conflict-free
// ldmatrix phases). mode 0: row-major out; mode 1: [B,H,T,HD] head layout.
// ---------------------------------------------------------------------------
#define BM 128
#define BN 128
#define BK 32
#define TROW 40                        // smem row stride in bf16 (80 bytes)
#define TILE_B (128 * TROW * 2)        // 10240 bytes
#define STAGE_B (4 * TILE_B)           // Ahi, Alo, Bhi, Blo
#define GSMEM (2 * STAGE_B)            // 81920 bytes

__global__ void __launch_bounds__(256, 1) gemm_hmma(
    const __nv_bfloat16* __restrict__ Ahi, const __nv_bfloat16* __restrict__ Alo,
    const __nv_bfloat16* __restrict__ Bhi, const __nv_bfloat16* __restrict__ Blo,
    float* __restrict__ out, int Mtot, int Ntot, int Ktot, int mode)
{
    extern __shared__ char sm[];
    const uint32_t smb = smem_u32(sm);
    const int tid = threadIdx.x;
    const int wid = tid >> 5;
    const int lane = tid & 31;
    const int bm = blockIdx.y * BM;
    const int bn = blockIdx.x * BN;
    const int wm = (wid & 1) * 64;     // warp M offset
    const int wn = (wid >> 1) * 32;    // warp N offset

    const __nv_bfloat16* gsrc[4] = {Ahi, Alo, Bhi, Blo};

    // gmem load mapping: per tile, 512 uint4; thread does 2 (i = tid + u*256)
    const int ldrow0 = tid >> 2;             // rows 0..63 (u=0), +64 (u=1)
    const int ldcg   = (tid & 3) * 8;        // bf16 col offset (8 per uint4)
    const uint32_t st_off0 = (uint32_t)ldrow0 * 80 + (uint32_t)(tid & 3) * 16;

    // ldmatrix lane addressing (byte offsets within a tile)
    const uint32_t aoff = (uint32_t)(wm + (lane & 15)) * 80
                        + (uint32_t)((lane >> 4) * 8) * 2;
    const uint32_t boff = (uint32_t)(wn + (lane & 7)) * 80
                        + (uint32_t)(((lane >> 3) & 1) * 8) * 2;

    float acc[4][4][4];
    #pragma unroll
    for (int mi = 0; mi < 4; mi++)
        #pragma unroll
        for (int ni = 0; ni < 4; ni++)
            #pragma unroll
            for (int r = 0; r < 4; r++) acc[mi][ni][r] = 0.f;

    const int nchunk = Ktot / BK;      // 32
    uint4 ld[8];

    // ---- load chunk `ch` from gmem into regs
    auto load_regs = [&](int ch) {
        #pragma unroll
        for (int t2 = 0; t2 < 4; t2++) {
            const __nv_bfloat16* G = gsrc[t2];
            const int rbase = (t2 < 2) ? bm : bn;
            #pragma unroll
            for (int u = 0; u < 2; u++) {
                int row = ldrow0 + u * 64;
                ld[t2 * 2 + u] = *(const uint4*)&G[(size_t)(rbase + row) * Ktot
                                                   + ch * BK + ldcg];
            }
        }
    };
    // ---- store regs into stage buffer `buf`
    auto store_smem = [&](int buf) {
        char* stage = sm + buf * STAGE_B;
        #pragma unroll
        for (int t2 = 0; t2 < 4; t2++) {
            char* tb = stage + t2 * TILE_B;
            #pragma unroll
            for (int u = 0; u < 2; u++)
                *(uint4*)(tb + st_off0 + u * 64 * 80) = ld[t2 * 2 + u];
        }
    };

    load_regs(0);
    store_smem(0);

    for (int ch = 0; ch < nchunk; ch++) {
        __syncthreads();
        const int buf = ch & 1;
        if (ch + 1 < nchunk) load_regs(ch + 1);

        const uint32_t sA_hi = smb + buf * STAGE_B + 0 * TILE_B;
        const uint32_t sA_lo = smb + buf * STAGE_B + 1 * TILE_B;
        const uint32_t sB_hi = smb + buf * STAGE_B + 2 * TILE_B;
        const uint32_t sB_lo = smb + buf * STAGE_B + 3 * TILE_B;

        #pragma unroll
        for (int ks = 0; ks < 2; ks++) {
            const uint32_t kb = ks * 32;   // 16 bf16 = 32 bytes
            uint32_t ah[4][4], al[4][4], bh[4][2], bl[4][2];
            #pragma unroll
            for (int mi = 0; mi < 4; mi++) {
                ldsm_x4(ah[mi], sA_hi + aoff + (uint32_t)mi * 16 * 80 + kb);
                ldsm_x4(al[mi], sA_lo + aoff + (uint32_t)mi * 16 * 80 + kb);
            }
            #pragma unroll
            for (int ni = 0; ni < 4; ni++) {
                ldsm_x2(bh[ni], sB_hi + boff + (uint32_t)ni * 8 * 80 + kb);
                ldsm_x2(bl[ni], sB_lo + boff + (uint32_t)ni * 8 * 80 + kb);
            }
            #pragma unroll
            for (int mi = 0; mi < 4; mi++)
                #pragma unroll
                for (int ni = 0; ni < 4; ni++) {
                    mma_bf16(acc[mi][ni], ah[mi], bh[ni]);
                    mma_bf16(acc[mi][ni], ah[mi], bl[ni]);
                    mma_bf16(acc[mi][ni], al[mi], bh[ni]);
                }
        }
        if (ch + 1 < nchunk) store_smem(buf ^ 1);
    }

    // Epilogue: thread holds d0,d1 @ (m + lane/4, n + 2*(lane%4)), d2,d3 @ m+8
    const int mrow0 = bm + wm + (lane >> 2);
    const int ncol0 = bn + wn + 2 * (lane & 3);
    #pragma unroll
    for (int mi = 0; mi < 4; mi++) {
        #pragma unroll
        for (int ni = 0; ni < 4; ni++) {
            int n = ncol0 + ni * 8;
            #pragma unroll
            for (int half = 0; half < 2; half++) {
                int m = mrow0 + mi * 16 + half * 8;
                float2 r2 = make_float2(acc[mi][ni][half * 2],
                                        acc[mi][ni][half * 2 + 1]);
                if (mode == 0) {
                    *(float2*)&out[(size_t)m * Ntot + n] = r2;
                } else {
                    int b = m >> 11;
                    int t = m & (T_ - 1);
                    int hh = n >> 6;
                    int d = n & (HD_ - 1);
                    *(float2*)&out[(((size_t)b * H_ + hh) * T_ + t) * HD_ + d] = r2;
                }
            }
        }
    }
}

// ---------------------------------------------------------------------------
// Flash attention, fp32, causal, BQ=BK=64, HD=64, 256 threads (16x16, 4x4)
// Q,K,V: [B,H,T,HD]. Output ctx: bf16 hi/lo [B,T,C] (heads re-interleaved).
// ---------------------------------------------------------------------------
#define AT_STRIDE 68
#define AT_SMEM_FLOATS (4 * 64 * AT_STRIDE)
#define AT_SMEM_BYTES  (AT_SMEM_FLOATS * 4)

__global__ void __launch_bounds__(256) flash_attn_kernel(
    const float* __restrict__ Q, const float* __restrict__ K,
    const float* __restrict__ V,
    __nv_bfloat16* __restrict__ ctx_hi, __nv_bfloat16* __restrict__ ctx_lo)
{
    extern __shared__ float smf[];
    float* Qs = smf;
    float* Ks = Qs + 64 * AT_STRIDE;
    float* Vs = Ks + 64 * AT_STRIDE;
    float* Ps = Vs + 64 * AT_STRIDE;

    const int qb = blockIdx.x;
    const int bh = blockIdx.y;
    const int q0 = qb * 64;
    const size_t base = (size_t)bh * T_ * HD_;

    const int tid = threadIdx.x;
    const int ty = tid >> 4;
    const int tx = tid & 15;

    #pragma unroll
    for (int u = 0; u < 4; u++) {
        int i = tid + u * 256;
        int row = i >> 4;
        int c = (i & 15) * 4;
        *(float4*)&Qs[row * AT_STRIDE + c] =
            *(const float4*)&Q[base + (size_t)(q0 + row) * HD_ + c];
    }

    float o[4][4];
    float mrow[4], lrow[4];
    #pragma unroll
    for (int i = 0; i < 4; i++) {
        mrow[i] = -1e30f; lrow[i] = 0.f;
        #pragma unroll
        for (int j = 0; j < 4; j++) o[i][j] = 0.f;
    }

    const float scale = 0.125f;
    const int nkv = qb + 1;

    for (int kb = 0; kb < nkv; kb++) {
        const int k0 = kb * 64;
        #pragma unroll
        for (int u = 0; u < 4; u++) {
            int i = tid + u * 256;
            int row = i >> 4;
            int c = (i & 15) * 4;
            *(float4*)&Ks[row * AT_STRIDE + c] =
                *(const float4*)&K[base + (size_t)(k0 + row) * HD_ + c];
            *(float4*)&Vs[row * AT_STRIDE + c] =
                *(const float4*)&V[base + (size_t)(k0 + row) * HD_ + c];
        }
        __syncthreads();

        float s[4][4];
        #pragma unroll
        for (int i = 0; i < 4; i++)
            #pragma unroll
            for (int j = 0; j < 4; j++) s[i][j] = 0.f;

        #pragma unroll
        for (int kk = 0; kk < 64; kk += 4) {
            float4 a[4], b[4];
            #pragma unroll
            for (int i = 0; i < 4; i++)
                a[i] = *(const float4*)&Qs[(ty * 4 + i) * AT_STRIDE + kk];
            #pragma unroll
            for (int j = 0; j < 4; j++)
                b[j] = *(const float4*)&Ks[(tx * 4 + j) * AT_STRIDE + kk];
            #pragma unroll
            for (int i = 0; i < 4; i++)
                #pragma unroll
                for (int j = 0; j < 4; j++)
                    s[i][j] += a[i].x * b[j].x + a[i].y * b[j].y
                             + a[i].z * b[j].z + a[i].w * b[j].w;
        }

        const bool diag = (kb == qb);
        #pragma unroll
        for (int i = 0; i < 4; i++)
            #pragma unroll
            for (int j = 0; j < 4; j++) {
                float v = s[i][j] * scale;
                if (diag && (k0 + tx * 4 + j > q0 + ty * 4 + i)) v = -1e30f;
                s[i][j] = v;
            }

        float mnew[4], csc[4];
        #pragma unroll
        for (int i = 0; i < 4; i++) {
            float lm = fmaxf(fmaxf(s[i][0], s[i][1]), fmaxf(s[i][2], s[i][3]));
            #pragma unroll
            for (int off = 8; off; off >>= 1)
                lm = fmaxf(lm, __shfl_xor_sync(0xffffffffu, lm, off));
            mnew[i] = fmaxf(mrow[i], lm);
            csc[i]  = __expf(mrow[i] - mnew[i]);
            mrow[i] = mnew[i];
        }
        #pragma unroll
        for (int i = 0; i < 4; i++) {
            float rs = 0.f;
            #pragma unroll
            for (int j = 0; j < 4; j++) {
                float p = __expf(s[i][j] - mnew[i]);
                s[i][j] = p; rs += p;
            }
            #pragma unroll
            for (int off = 8; off; off >>= 1)
                rs += __shfl_xor_sync(0xffffffffu, rs, off);
            lrow[i] = lrow[i] * csc[i] + rs;
            #pragma unroll
            for (int j = 0; j < 4; j++) o[i][j] *= csc[i];
        }

        #pragma unroll
        for (int i = 0; i < 4; i++)
            *(float4*)&Ps[(ty * 4 + i) * AT_STRIDE + tx * 4] =
                make_float4(s[i][0], s[i][1], s[i][2], s[i][3]);
        __syncthreads();

        #pragma unroll 8
        for (int kk = 0; kk < 64; kk++) {
            float4 vv = *(const float4*)&Vs[kk * AT_STRIDE + tx * 4];
            float p0 = Ps[(ty * 4 + 0) * AT_STRIDE + kk];
            float p1 = Ps[(ty * 4 + 1) * AT_STRIDE + kk];
            float p2 = Ps[(ty * 4 + 2) * AT_STRIDE + kk];
            float p3 = Ps[(ty * 4 + 3) * AT_STRIDE + kk];
            o[0][0] = fmaf(p0, vv.x, o[0][0]); o[0][1] = fmaf(p0, vv.y, o[0][1]);
            o[0][2] = fmaf(p0, vv.z, o[0][2]); o[0][3] = fmaf(p0, vv.w, o[0][3]);
            o[1][0] = fmaf(p1, vv.x, o[1][0]); o[1][1] = fmaf(p1, vv.y, o[1][1]);
            o[1][2] = fmaf(p1, vv.z, o[1][2]); o[1][3] = fmaf(p1, vv.w, o[1][3]);
            o[2][0] = fmaf(p2, vv.x, o[2][0]); o[2][1] = fmaf(p2, vv.y, o[2][1]);
            o[2][2] = fmaf(p2, vv.z, o[2][2]); o[2][3] = fmaf(p2, vv.w, o[2][3]);
            o[3][0] = fmaf(p3, vv.x, o[3][0]); o[3][1] = fmaf(p3, vv.y, o[3][1]);
            o[3][2] = fmaf(p3, vv.z, o[3][2]); o[3][3] = fmaf(p3, vv.w, o[3][3]);
        }
        __syncthreads();
    }

    const int b = bh / H_;
    const int hh = bh % H_;
    #pragma unroll
    for (int i = 0; i < 4; i++) {
        float inv = 1.f / lrow[i];
        int t = q0 + ty * 4 + i;
        float vv[4];
        #pragma unroll
        for (int j = 0; j < 4; j++) vv[j] = o[i][j] * inv;
        __nv_bfloat16 h4[4], l4[4];
        #pragma unroll
        for (int j = 0; j < 4; j++) {
            h4[j] = __float2bfloat16(vv[j]);
            l4[j] = __float2bfloat16(vv[j] - __bfloat162float(h4[j]));
        }
        size_t off = ((size_t)b * T_ + t) * C_ + hh * HD_ + tx * 4;
        *(__nv_bfloat162*)&ctx_hi[off]     = __nv_bfloat162(h4[0], h4[1]);
        *(__nv_bfloat162*)&ctx_hi[off + 2] = __nv_bfloat162(h4[2], h4[3]);
        *(__nv_bfloat162*)&ctx_lo[off]     = __nv_bfloat162(l4[0], l4[1]);
        *(__nv_bfloat162*)&ctx_lo[off + 2] = __nv_bfloat162(l4[2], l4[3]);
    }
}

// ---------------------------------------------------------------------------
// kernel_launch
// ---------------------------------------------------------------------------
extern "C" void kernel_launch(void* const* d_in, const int* in_sizes, int n_in,
                              void* d_out, int out_size)
{
    const float* x = (const float*)d_in[0];
    const float* W[4] = {(const float*)d_in[1], (const float*)d_in[2],
                         (const float*)d_in[3], (const float*)d_in[4]};
    float* out = (float*)d_out;

    __nv_bfloat16 *xhi, *xlo, *whi, *wlo, *chi, *clo;
    float *q, *k, *v;
    cudaGetSymbolAddress((void**)&xhi, g_Xhi);
    cudaGetSymbolAddress((void**)&xlo, g_Xlo);
    cudaGetSymbolAddress((void**)&whi, g_Whi);
    cudaGetSymbolAddress((void**)&wlo, g_Wlo);
    cudaGetSymbolAddress((void**)&q,   g_Q);
    cudaGetSymbolAddress((void**)&k,   g_K);
    cudaGetSymbolAddress((void**)&v,   g_V);
    cudaGetSymbolAddress((void**)&chi, g_CTXhi);
    cudaGetSymbolAddress((void**)&clo, g_CTXlo);

    cudaFuncSetAttribute(gemm_hmma,
                         cudaFuncAttributeMaxDynamicSharedMemorySize, GSMEM);
    cudaFuncSetAttribute(flash_attn_kernel,
                         cudaFuncAttributeMaxDynamicSharedMemorySize, AT_SMEM_BYTES);

    // Split conversions
    {
        int n4 = M_ * C_ / 4;
        split_bf16<<<n4 / 256, 256>>>(x, xhi, xlo, n4);
        int w4 = C_ * C_ / 4;
        for (int i = 0; i < 4; i++)
            split_bf16<<<w4 / 256, 256>>>(W[i],
                whi + (size_t)i * C_ * C_, wlo + (size_t)i * C_ * C_, w4);
    }

    dim3 gg(C_ / BN, M_ / BM);   // (8, 64)
    float* qkv[3] = {q, k, v};
    for (int i = 0; i < 3; i++)
        gemm_hmma<<<gg, 256, GSMEM>>>(xhi, xlo,
            whi + (size_t)i * C_ * C_, wlo + (size_t)i * C_ * C_,
            qkv[i], M_, C_, C_, 1);

    flash_attn_kernel<<<dim3(T_ / 64, B_ * H_), 256, AT_SMEM_BYTES>>>(
        q, k, v, chi, clo);

    gemm_hmma<<<gg, 256, GSMEM>>>(chi, clo,
        whi + (size_t)3 * C_ * C_, wlo + (size_t)3 * C_ * C_,
        out, M_, C_, C_, 0);
}

// round 4
// speedup vs baseline: 3.4664x; 2.3714x over previous
#include <cuda_runtime.h>
#include <cuda_bf16.h>
#include <cstdint>
#include <math.h>

// Problem constants
#define B_  4
#define T_  2048
#define C_  1024
#define H_  16
#define HD_ 64
#define M_  (B_ * T_)   // 8192

// ---------------------------------------------------------------------------
// Scratch (__device__ globals, allocation-free rule)
// ---------------------------------------------------------------------------
__device__ __nv_bfloat16 g_Xhi[(size_t)M_ * C_];
__device__ __nv_bfloat16 g_Xlo[(size_t)M_ * C_];
__device__ __nv_bfloat16 g_Whi[4][(size_t)C_ * C_];
__device__ __nv_bfloat16 g_Wlo[4][(size_t)C_ * C_];
__device__ __nv_bfloat16 g_Qhi[(size_t)M_ * C_];   // [B,H,T,HD], pre-scaled 1/8
__device__ __nv_bfloat16 g_Qlo[(size_t)M_ * C_];
__device__ __nv_bfloat16 g_Khi[(size_t)M_ * C_];
__device__ __nv_bfloat16 g_Klo[(size_t)M_ * C_];
__device__ __nv_bfloat16 g_Vhi[(size_t)M_ * C_];
__device__ __nv_bfloat16 g_Vlo[(size_t)M_ * C_];
__device__ __nv_bfloat16 g_CTXhi[(size_t)M_ * C_];
__device__ __nv_bfloat16 g_CTXlo[(size_t)M_ * C_];

// ---------------------------------------------------------------------------
// PTX helpers
// ---------------------------------------------------------------------------
__device__ __forceinline__ uint32_t smem_u32(const void* p) {
    uint32_t a;
    asm("{ .reg .u64 t; cvta.to.shared.u64 t, %1; cvt.u32.u64 %0, t; }"
        : "=r"(a) : "l"(p));
    return a;
}
__device__ __forceinline__ void ldsm_x4(uint32_t* r, uint32_t addr) {
    asm volatile("ldmatrix.sync.aligned.m8n8.x4.shared.b16 {%0,%1,%2,%3}, [%4];"
        : "=r"(r[0]), "=r"(r[1]), "=r"(r[2]), "=r"(r[3]) : "r"(addr));
}
__device__ __forceinline__ void ldsm_x4_t(uint32_t* r, uint32_t addr) {
    asm volatile("ldmatrix.sync.aligned.m8n8.x4.trans.shared.b16 {%0,%1,%2,%3}, [%4];"
        : "=r"(r[0]), "=r"(r[1]), "=r"(r[2]), "=r"(r[3]) : "r"(addr));
}
__device__ __forceinline__ void ldsm_x2(uint32_t* r, uint32_t addr) {
    asm volatile("ldmatrix.sync.aligned.m8n8.x2.shared.b16 {%0,%1}, [%2];"
        : "=r"(r[0]), "=r"(r[1]) : "r"(addr));
}
__device__ __forceinline__ void mma_bf16(float* d, const uint32_t* a,
                                         const uint32_t* b) {
    asm volatile(
        "mma.sync.aligned.m16n8k16.row.col.f32.bf16.bf16.f32 "
        "{%0,%1,%2,%3}, {%4,%5,%6,%7}, {%8,%9}, {%0,%1,%2,%3};"
        : "+f"(d[0]), "+f"(d[1]), "+f"(d[2]), "+f"(d[3])
        : "r"(a[0]), "r"(a[1]), "r"(a[2]), "r"(a[3]), "r"(b[0]), "r"(b[1]));
}
__device__ __forceinline__ void cp16(uint32_t dst, const void* src) {
    asm volatile("cp.async.cg.shared.global [%0], [%1], 16;"
                 :: "r"(dst), "l"(src));
}
#define CP_COMMIT() asm volatile("cp.async.commit_group;" ::: "memory")
#define CP_WAIT(n)  asm volatile("cp.async.wait_group %0;" :: "n"(n) : "memory")

// split a float2 into bf16 hi pair + bf16 lo (residual) pair
__device__ __forceinline__ void split2(float x, float y,
                                       uint32_t& hi, uint32_t& lo) {
    __nv_bfloat162 h = __float22bfloat162_rn(make_float2(x, y));
    float2 hf = __bfloat1622float2(h);
    __nv_bfloat162 l = __float22bfloat162_rn(make_float2(x - hf.x, y - hf.y));
    hi = *(uint32_t*)&h;
    lo = *(uint32_t*)&l;
}

// ---------------------------------------------------------------------------
// Split-precision conversion: fp32 -> bf16 hi + bf16 lo
// ---------------------------------------------------------------------------
__global__ void split_bf16(const float* __restrict__ src,
                           __nv_bfloat16* __restrict__ hi,
                           __nv_bfloat16* __restrict__ lo, int n4)
{
    int i = blockIdx.x * blockDim.x + threadIdx.x;
    if (i >= n4) return;
    float4 v = ((const float4*)src)[i];
    uint32_t h0, l0, h1, l1;
    split2(v.x, v.y, h0, l0);
    split2(v.z, v.w, h1, l1);
    ((uint32_t*)hi)[2 * i + 0] = h0;
    ((uint32_t*)hi)[2 * i + 1] = h1;
    ((uint32_t*)lo)[2 * i + 0] = l0;
    ((uint32_t*)lo)[2 * i + 1] = l1;
}

// ---------------------------------------------------------------------------
// HMMA GEMM (as R3) with new epilogue:
// mode 0: fp32 row-major out. mode 1: bf16 hi/lo, [B,H,T,HD] layout, *scale.
// ---------------------------------------------------------------------------
#define BM 128
#define BN 128
#define BK 32
#define TROW 40                        // smem row stride in bf16 (80 bytes)
#define TILE_B (128 * TROW * 2)        // 10240 bytes
#define STAGE_B (4 * TILE_B)
#define GSMEM (2 * STAGE_B)            // 81920 bytes

__global__ void __launch_bounds__(256, 1) gemm_hmma(
    const __nv_bfloat16* __restrict__ Ahi, const __nv_bfloat16* __restrict__ Alo,
    const __nv_bfloat16* __restrict__ Bhi, const __nv_bfloat16* __restrict__ Blo,
    float* __restrict__ out,
    __nv_bfloat16* __restrict__ ohi, __nv_bfloat16* __restrict__ olo,
    int Mtot, int Ntot, int Ktot, int mode, float scale)
{
    extern __shared__ char sm[];
    const uint32_t smb = smem_u32(sm);
    const int tid = threadIdx.x;
    const int wid = tid >> 5;
    const int lane = tid & 31;
    const int bm = blockIdx.y * BM;
    const int bn = blockIdx.x * BN;
    const int wm = (wid & 1) * 64;
    const int wn = (wid >> 1) * 32;

    const __nv_bfloat16* gsrc[4] = {Ahi, Alo, Bhi, Blo};

    const int ldrow0 = tid >> 2;
    const int ldcg   = (tid & 3) * 8;
    const uint32_t st_off0 = (uint32_t)ldrow0 * 80 + (uint32_t)(tid & 3) * 16;

    const uint32_t aoff = (uint32_t)(wm + (lane & 15)) * 80
                        + (uint32_t)((lane >> 4) * 8) * 2;
    const uint32_t boff = (uint32_t)(wn + (lane & 7)) * 80
                        + (uint32_t)(((lane >> 3) & 1) * 8) * 2;

    float acc[4][4][4];
    #pragma unroll
    for (int mi = 0; mi < 4; mi++)
        #pragma unroll
        for (int ni = 0; ni < 4; ni++)
            #pragma unroll
            for (int r = 0; r < 4; r++) acc[mi][ni][r] = 0.f;

    const int nchunk = Ktot / BK;
    uint4 ld[8];

    auto load_regs = [&](int ch) {
        #pragma unroll
        for (int t2 = 0; t2 < 4; t2++) {
            const __nv_bfloat16* G = gsrc[t2];
            const int rbase = (t2 < 2) ? bm : bn;
            #pragma unroll
            for (int u = 0; u < 2; u++) {
                int row = ldrow0 + u * 64;
                ld[t2 * 2 + u] = *(const uint4*)&G[(size_t)(rbase + row) * Ktot
                                                   + ch * BK + ldcg];
            }
        }
    };
    auto store_smem = [&](int buf) {
        char* stage = sm + buf * STAGE_B;
        #pragma unroll
        for (int t2 = 0; t2 < 4; t2++) {
            char* tb = stage + t2 * TILE_B;
            #pragma unroll
            for (int u = 0; u < 2; u++)
                *(uint4*)(tb + st_off0 + u * 64 * 80) = ld[t2 * 2 + u];
        }
    };

    load_regs(0);
    store_smem(0);

    for (int ch = 0; ch < nchunk; ch++) {
        __syncthreads();
        const int buf = ch & 1;
        if (ch + 1 < nchunk) load_regs(ch + 1);

        const uint32_t sA_hi = smb + buf * STAGE_B + 0 * TILE_B;
        const uint32_t sA_lo = smb + buf * STAGE_B + 1 * TILE_B;
        const uint32_t sB_hi = smb + buf * STAGE_B + 2 * TILE_B;
        const uint32_t sB_lo = smb + buf * STAGE_B + 3 * TILE_B;

        #pragma unroll
        for (int ks = 0; ks < 2; ks++) {
            const uint32_t kb = ks * 32;
            uint32_t ah[4][4], al[4][4], bh2[4][2], bl2[4][2];
            #pragma unroll
            for (int mi = 0; mi < 4; mi++) {
                ldsm_x4(ah[mi], sA_hi + aoff + (uint32_t)mi * 16 * 80 + kb);
                ldsm_x4(al[mi], sA_lo + aoff + (uint32_t)mi * 16 * 80 + kb);
            }
            #pragma unroll
            for (int ni = 0; ni < 4; ni++) {
                ldsm_x2(bh2[ni], sB_hi + boff + (uint32_t)ni * 8 * 80 + kb);
                ldsm_x2(bl2[ni], sB_lo + boff + (uint32_t)ni * 8 * 80 + kb);
            }
            #pragma unroll
            for (int mi = 0; mi < 4; mi++)
                #pragma unroll
                for (int ni = 0; ni < 4; ni++) {
                    mma_bf16(acc[mi][ni], ah[mi], bh2[ni]);
                    mma_bf16(acc[mi][ni], ah[mi], bl2[ni]);
                    mma_bf16(acc[mi][ni], al[mi], bh2[ni]);
                }
        }
        if (ch + 1 < nchunk) store_smem(buf ^ 1);
    }

    const int mrow0 = bm + wm + (lane >> 2);
    const int ncol0 = bn + wn + 2 * (lane & 3);
    #pragma unroll
    for (int mi = 0; mi < 4; mi++) {
        #pragma unroll
        for (int ni = 0; ni < 4; ni++) {
            int n = ncol0 + ni * 8;
            #pragma unroll
            for (int half = 0; half < 2; half++) {
                int m = mrow0 + mi * 16 + half * 8;
                float vx = acc[mi][ni][half * 2];
                float vy = acc[mi][ni][half * 2 + 1];
                if (mode == 0) {
                    *(float2*)&out[(size_t)m * Ntot + n] = make_float2(vx, vy);
                } else {
                    int b = m >> 11;
                    int t = m & (T_ - 1);
                    int hh = n >> 6;
                    int d = n & (HD_ - 1);
                    size_t off = (((size_t)b * H_ + hh) * T_ + t) * HD_ + d;
                    uint32_t h2, l2;
                    split2(vx * scale, vy * scale, h2, l2);
                    *(uint32_t*)&ohi[off] = h2;
                    *(uint32_t*)&olo[off] = l2;
                }
            }
        }
    }
}

// ---------------------------------------------------------------------------
// HMMA flash attention: causal, BQ=128, kv-tile 64, HD=64, 256 threads.
// Q pre-scaled by 1/8. Split-bf16 for QK^T and PV (3 products each).
// Q,K,V hi/lo: [B,H,T,HD] bf16. Output ctx hi/lo: [B,T,C] bf16.
// ---------------------------------------------------------------------------
#define FQ_HI 0
#define FQ_LO 16384
#define FSTG(s) (32768 + (s) * 32768)
#define F_KHI 0
#define F_KLO 8192
#define F_VHI 16384
#define F_VLO 24576
#define FSMEM 98304

__global__ void __launch_bounds__(256, 1) flash_hmma(
    const __nv_bfloat16* __restrict__ Qhi, const __nv_bfloat16* __restrict__ Qlo,
    const __nv_bfloat16* __restrict__ Khi, const __nv_bfloat16* __restrict__ Klo,
    const __nv_bfloat16* __restrict__ Vhi, const __nv_bfloat16* __restrict__ Vlo,
    __nv_bfloat16* __restrict__ ctx_hi, __nv_bfloat16* __restrict__ ctx_lo)
{
    extern __shared__ char sm[];
    const uint32_t smb = smem_u32(sm);
    const int tid = threadIdx.x;
    const int wid = tid >> 5;
    const int lane = tid & 31;
    const int qb = (int)gridDim.x - 1 - (int)blockIdx.x;   // heavy tiles first
    const int bh = blockIdx.y;
    const size_t base = (size_t)bh * T_ * HD_;
    const int q0 = qb * 128;
    const int nkv = 2 * qb + 2;

    // ---- Q tiles (hi+lo) via cp.async: 128 rows x 8 x 16B chunks each
    #pragma unroll
    for (int u = 0; u < 4; u++) {
        int c = tid + u * 256;            // 0..1023
        int row = c >> 3;
        int c16 = c & 7;
        uint32_t d = (uint32_t)row * 128 + (((uint32_t)c16 * 16) ^ ((row & 7) << 4));
        size_t g = base + (size_t)(q0 + row) * HD_ + c16 * 8;
        cp16(smb + FQ_HI + d, &Qhi[g]);
        cp16(smb + FQ_LO + d, &Qlo[g]);
    }
    CP_COMMIT();

    // ---- K/V stage loader
    auto load_kv = [&](int kt, int s) {
        uint32_t dst = smb + FSTG(s);
        const int k0 = kt * 64;
        #pragma unroll
        for (int u = 0; u < 2; u++) {
            int c = tid + u * 256;        // 0..511
            int row = c >> 3;
            int c16 = c & 7;
            uint32_t d = (uint32_t)row * 128
                       + (((uint32_t)c16 * 16) ^ ((row & 7) << 4));
            size_t g = base + (size_t)(k0 + row) * HD_ + c16 * 8;
            cp16(dst + F_KHI + d, &Khi[g]);
            cp16(dst + F_KLO + d, &Klo[g]);
            cp16(dst + F_VHI + d, &Vhi[g]);
            cp16(dst + F_VLO + d, &Vlo[g]);
        }
        CP_COMMIT();
    };
    load_kv(0, 0);
    load_kv(1, 1);

    // ---- build Q fragments (held in registers for the whole kernel)
    CP_WAIT(2);               // Q group retired (stages may still be pending)
    __syncthreads();
    uint32_t qh[4][4], ql[4][4];
    {
        const int arow = wid * 16 + (lane & 7) + ((lane >> 3) & 1) * 8;
        const uint32_t asw = (uint32_t)(arow & 7) << 4;
        #pragma unroll
        for (int ks = 0; ks < 4; ks++) {
            uint32_t colb = (uint32_t)ks * 32 + (uint32_t)(lane >> 4) * 16;
            uint32_t ad = (uint32_t)arow * 128 + (colb ^ asw);
            ldsm_x4(qh[ks], smb + FQ_HI + ad);
            ldsm_x4(ql[ks], smb + FQ_LO + ad);
        }
    }

    float oacc[8][4];
    #pragma unroll
    for (int nt = 0; nt < 8; nt++)
        #pragma unroll
        for (int r = 0; r < 4; r++) oacc[nt][r] = 0.f;
    float mrow[2] = {-1e30f, -1e30f};
    float lrow[2] = {0.f, 0.f};

    // per-lane fragment addresses (swizzle applied per row)
    const int krow = (lane & 7) + (lane >> 4) * 8;           // + nt2*16
    const uint32_t kcol = (uint32_t)((lane >> 3) & 1) * 16;  // + ks*32
    const int vrow = (lane & 7) + ((lane >> 3) & 1) * 8;     // + ks*16
    const uint32_t vcol = (uint32_t)(lane >> 4) * 16;        // + nt2*32

    for (int kb = 0; kb < nkv; kb++) {
        const uint32_t stg = smb + FSTG(kb & 1);
        CP_WAIT(1);
        __syncthreads();

        // ---------- S = Q K^T (split bf16, 3 products) ----------
        float sc[8][4];
        #pragma unroll
        for (int nt = 0; nt < 8; nt++)
            #pragma unroll
            for (int r = 0; r < 4; r++) sc[nt][r] = 0.f;

        #pragma unroll
        for (int ks = 0; ks < 4; ks++) {
            uint32_t kh[4][4], kl[4][4];
            #pragma unroll
            for (int nt2 = 0; nt2 < 4; nt2++) {
                int row = nt2 * 16 + krow;
                uint32_t colb = (uint32_t)ks * 32 + kcol;
                uint32_t ad = (uint32_t)row * 128 + (colb ^ ((row & 7) << 4));
                ldsm_x4(kh[nt2], stg + F_KHI + ad);
                ldsm_x4(kl[nt2], stg + F_KLO + ad);
            }
            #pragma unroll
            for (int nt = 0; nt < 8; nt++) {
                const uint32_t* bh2 = &kh[nt >> 1][(nt & 1) * 2];
                const uint32_t* bl2 = &kl[nt >> 1][(nt & 1) * 2];
                mma_bf16(sc[nt], qh[ks], bh2);
                mma_bf16(sc[nt], qh[ks], bl2);
                mma_bf16(sc[nt], ql[ks], bh2);
            }
        }

        // ---------- causal mask (last two tiles only) ----------
        if (kb >= nkv - 2) {
            int grow0 = q0 + wid * 16 + (lane >> 2);
            int gcol0 = kb * 64 + 2 * (lane & 3);
            #pragma unroll
            for (int nt = 0; nt < 8; nt++)
                #pragma unroll
                for (int e = 0; e < 4; e++) {
                    int col = gcol0 + nt * 8 + (e & 1);
                    int row = grow0 + (e >> 1) * 8;
                    if (col > row) sc[nt][e] = -1e30f;
                }
        }

        // ---------- online softmax ----------
        float mx0 = -1e30f, mx1 = -1e30f;
        #pragma unroll
        for (int nt = 0; nt < 8; nt++) {
            mx0 = fmaxf(mx0, fmaxf(sc[nt][0], sc[nt][1]));
            mx1 = fmaxf(mx1, fmaxf(sc[nt][2], sc[nt][3]));
        }
        mx0 = fmaxf(mx0, __shfl_xor_sync(0xffffffffu, mx0, 1));
        mx0 = fmaxf(mx0, __shfl_xor_sync(0xffffffffu, mx0, 2));
        mx1 = fmaxf(mx1, __shfl_xor_sync(0xffffffffu, mx1, 1));
        mx1 = fmaxf(mx1, __shfl_xor_sync(0xffffffffu, mx1, 2));
        float mn0 = fmaxf(mrow[0], mx0);
        float mn1 = fmaxf(mrow[1], mx1);
        float cs0 = __expf(mrow[0] - mn0);
        float cs1 = __expf(mrow[1] - mn1);
        mrow[0] = mn0; mrow[1] = mn1;

        float sum0 = 0.f, sum1 = 0.f;
        #pragma unroll
        for (int nt = 0; nt < 8; nt++) {
            sc[nt][0] = __expf(sc[nt][0] - mn0); sum0 += sc[nt][0];
            sc[nt][1] = __expf(sc[nt][1] - mn0); sum0 += sc[nt][1];
            sc[nt][2] = __expf(sc[nt][2] - mn1); sum1 += sc[nt][2];
            sc[nt][3] = __expf(sc[nt][3] - mn1); sum1 += sc[nt][3];
        }
        sum0 += __shfl_xor_sync(0xffffffffu, sum0, 1);
        sum0 += __shfl_xor_sync(0xffffffffu, sum0, 2);
        sum1 += __shfl_xor_sync(0xffffffffu, sum1, 1);
        sum1 += __shfl_xor_sync(0xffffffffu, sum1, 2);
        lrow[0] = lrow[0] * cs0 + sum0;
        lrow[1] = lrow[1] * cs1 + sum1;
        #pragma unroll
        for (int nt = 0; nt < 8; nt++) {
            oacc[nt][0] *= cs0; oacc[nt][1] *= cs0;
            oacc[nt][2] *= cs1; oacc[nt][3] *= cs1;
        }

        // ---------- O += P V (split bf16, 3 products; P from registers) ----
        #pragma unroll
        for (int ks = 0; ks < 4; ks++) {
            uint32_t ah[4], al[4];
            split2(sc[2 * ks][0],     sc[2 * ks][1],     ah[0], al[0]);
            split2(sc[2 * ks][2],     sc[2 * ks][3],     ah[1], al[1]);
            split2(sc[2 * ks + 1][0], sc[2 * ks + 1][1], ah[2], al[2]);
            split2(sc[2 * ks + 1][2], sc[2 * ks + 1][3], ah[3], al[3]);
            #pragma unroll
            for (int nt2 = 0; nt2 < 4; nt2++) {
                int row = ks * 16 + vrow;
                uint32_t colb = (uint32_t)nt2 * 32 + vcol;
                uint32_t ad = (uint32_t)row * 128 + (colb ^ ((row & 7) << 4));
                uint32_t vh[4], vl[4];
                ldsm_x4_t(vh, stg + F_VHI + ad);
                ldsm_x4_t(vl, stg + F_VLO + ad);
                mma_bf16(oacc[2 * nt2],     ah, &vh[0]);
                mma_bf16(oacc[2 * nt2],     ah, &vl[0]);
                mma_bf16(oacc[2 * nt2],     al, &vh[0]);
                mma_bf16(oacc[2 * nt2 + 1], ah, &vh[2]);
                mma_bf16(oacc[2 * nt2 + 1], ah, &vl[2]);
                mma_bf16(oacc[2 * nt2 + 1], al, &vh[2]);
            }
        }

        __syncthreads();
        if (kb + 2 < nkv) load_kv(kb + 2, kb & 1);
    }

    // ---------- normalize + store ctx as bf16 hi/lo ----------
    float inv0 = 1.f / lrow[0];
    float inv1 = 1.f / lrow[1];
    const int b = bh >> 4;
    const int hh = bh & 15;
    #pragma unroll
    for (int h = 0; h < 2; h++) {
        float inv = h ? inv1 : inv0;
        int t = q0 + wid * 16 + (lane >> 2) + h * 8;
        #pragma unroll
        for (int nt = 0; nt < 8; nt++) {
            int col = hh * 64 + nt * 8 + 2 * (lane & 3);
            size_t off = ((size_t)b * T_ + t) * C_ + col;
            uint32_t h2, l2;
            split2(oacc[nt][2 * h] * inv, oacc[nt][2 * h + 1] * inv, h2, l2);
            *(uint32_t*)&ctx_hi[off] = h2;
            *(uint32_t*)&ctx_lo[off] = l2;
        }
    }
}

// ---------------------------------------------------------------------------
// kernel_launch
// ---------------------------------------------------------------------------
extern "C" void kernel_launch(void* const* d_in, const int* in_sizes, int n_in,
                              void* d_out, int out_size)
{
    const float* x = (const float*)d_in[0];
    const float* W[4] = {(const float*)d_in[1], (const float*)d_in[2],
                         (const float*)d_in[3], (const float*)d_in[4]};
    float* out = (float*)d_out;

    __nv_bfloat16 *xhi, *xlo, *whi, *wlo;
    __nv_bfloat16 *qhi, *qlo, *khi, *klo, *vhi, *vlo, *chi, *clo;
    cudaGetSymbolAddress((void**)&xhi, g_Xhi);
    cudaGetSymbolAddress((void**)&xlo, g_Xlo);
    cudaGetSymbolAddress((void**)&whi, g_Whi);
    cudaGetSymbolAddress((void**)&wlo, g_Wlo);
    cudaGetSymbolAddress((void**)&qhi, g_Qhi);
    cudaGetSymbolAddress((void**)&qlo, g_Qlo);
    cudaGetSymbolAddress((void**)&khi, g_Khi);
    cudaGetSymbolAddress((void**)&klo, g_Klo);
    cudaGetSymbolAddress((void**)&vhi, g_Vhi);
    cudaGetSymbolAddress((void**)&vlo, g_Vlo);
    cudaGetSymbolAddress((void**)&chi, g_CTXhi);
    cudaGetSymbolAddress((void**)&clo, g_CTXlo);

    cudaFuncSetAttribute(gemm_hmma,
                         cudaFuncAttributeMaxDynamicSharedMemorySize, GSMEM);
    cudaFuncSetAttribute(flash_hmma,
                         cudaFuncAttributeMaxDynamicSharedMemorySize, FSMEM);

    // Split conversions
    {
        int n4 = M_ * C_ / 4;
        split_bf16<<<n4 / 256, 256>>>(x, xhi, xlo, n4);
        int w4 = C_ * C_ / 4;
        for (int i = 0; i < 4; i++)
            split_bf16<<<w4 / 256, 256>>>(W[i],
                whi + (size_t)i * C_ * C_, wlo + (size_t)i * C_ * C_, w4);
    }

    dim3 gg(C_ / BN, M_ / BM);   // (8, 64)
    // QKV projections -> bf16 hi/lo head layout (Q pre-scaled by 1/8)
    gemm_hmma<<<gg, 256, GSMEM>>>(xhi, xlo,
        whi + 0 * (size_t)C_ * C_, wlo + 0 * (size_t)C_ * C_,
        nullptr, qhi, qlo, M_, C_, C_, 1, 0.125f);
    gemm_hmma<<<gg, 256, GSMEM>>>(xhi, xlo,
        whi + 1 * (size_t)C_ * C_, wlo + 1 * (size_t)C_ * C_,
        nullptr, khi, klo, M_, C_, C_, 1, 1.0f);
    gemm_hmma<<<gg, 256, GSMEM>>>(xhi, xlo,
        whi + 2 * (size_t)C_ * C_, wlo + 2 * (size_t)C_ * C_,
        nullptr, vhi, vlo, M_, C_, C_, 1, 1.0f);

    // Causal flash attention (HMMA)
    flash_hmma<<<dim3(T_ / 128, B_ * H_), 256, FSMEM>>>(
        qhi, qlo, khi, klo, vhi, vlo, chi, clo);

    // Output projection (fp32 out)
    gemm_hmma<<<gg, 256, GSMEM>>>(chi, clo,
        whi + 3 * (size_t)C_ * C_, wlo + 3 * (size_t)C_ * C_,
        out, nullptr, nullptr, M_, C_, C_, 0, 1.0f);
}

// round 5
// speedup vs baseline: 4.7658x; 1.3749x over previous
#include <cuda_runtime.h>
#include <cuda_fp16.h>
#include <cstdint>
#include <math.h>

// Problem constants
#define B_  4
#define T_  2048
#define C_  1024
#define H_  16
#define HD_ 64
#define M_  (B_ * T_)   // 8192

// ---------------------------------------------------------------------------
// Scratch (__device__ globals, allocation-free rule)
// ---------------------------------------------------------------------------
__device__ __half g_Xh[(size_t)M_ * C_];
__device__ __half g_Xl[(size_t)M_ * C_];
__device__ __half g_Wh[4][(size_t)C_ * C_];
__device__ __half g_Qh[(size_t)M_ * C_];   // [B,H,T,HD], pre-scaled 1/8
__device__ __half g_Ql[(size_t)M_ * C_];
__device__ __half g_Kh[(size_t)M_ * C_];   // [B,H,T,HD]
__device__ __half g_Vh[(size_t)M_ * C_];
__device__ __half g_CTXh[(size_t)M_ * C_]; // [B,T,C]
__device__ __half g_CTXl[(size_t)M_ * C_];

// ---------------------------------------------------------------------------
// PTX helpers
// ---------------------------------------------------------------------------
__device__ __forceinline__ uint32_t smem_u32(const void* p) {
    uint32_t a;
    asm("{ .reg .u64 t; cvta.to.shared.u64 t, %1; cvt.u32.u64 %0, t; }"
        : "=r"(a) : "l"(p));
    return a;
}
__device__ __forceinline__ void ldsm_x4(uint32_t* r, uint32_t addr) {
    asm volatile("ldmatrix.sync.aligned.m8n8.x4.shared.b16 {%0,%1,%2,%3}, [%4];"
        : "=r"(r[0]), "=r"(r[1]), "=r"(r[2]), "=r"(r[3]) : "r"(addr));
}
__device__ __forceinline__ void ldsm_x4_t(uint32_t* r, uint32_t addr) {
    asm volatile("ldmatrix.sync.aligned.m8n8.x4.trans.shared.b16 {%0,%1,%2,%3}, [%4];"
        : "=r"(r[0]), "=r"(r[1]), "=r"(r[2]), "=r"(r[3]) : "r"(addr));
}
__device__ __forceinline__ void ldsm_x2(uint32_t* r, uint32_t addr) {
    asm volatile("ldmatrix.sync.aligned.m8n8.x2.shared.b16 {%0,%1}, [%2];"
        : "=r"(r[0]), "=r"(r[1]) : "r"(addr));
}
__device__ __forceinline__ void mma_f16(float* d, const uint32_t* a,
                                        const uint32_t* b) {
    asm volatile(
        "mma.sync.aligned.m16n8k16.row.col.f32.f16.f16.f32 "
        "{%0,%1,%2,%3}, {%4,%5,%6,%7}, {%8,%9}, {%0,%1,%2,%3};"
        : "+f"(d[0]), "+f"(d[1]), "+f"(d[2]), "+f"(d[3])
        : "r"(a[0]), "r"(a[1]), "r"(a[2]), "r"(a[3]), "r"(b[0]), "r"(b[1]));
}
__device__ __forceinline__ void cp16(uint32_t dst, const void* src) {
    asm volatile("cp.async.cg.shared.global [%0], [%1], 16;"
                 :: "r"(dst), "l"(src));
}
#define CP_COMMIT() asm volatile("cp.async.commit_group;" ::: "memory")
#define CP_WAIT(n)  asm volatile("cp.async.wait_group %0;" :: "n"(n) : "memory")

// split a float2 into fp16 hi pair + fp16 lo (residual) pair
__device__ __forceinline__ void split2h(float x, float y,
                                        uint32_t& hi, uint32_t& lo) {
    __half2 h = __floats2half2_rn(x, y);
    float2 hf = __half22float2(h);
    __half2 l = __floats2half2_rn(x - hf.x, y - hf.y);
    hi = *(uint32_t*)&h;
    lo = *(uint32_t*)&l;
}

// ---------------------------------------------------------------------------
// Conversions
// ---------------------------------------------------------------------------
__global__ void split_f16(const float* __restrict__ src,
                          __half* __restrict__ hi, __half* __restrict__ lo,
                          int n4)
{
    int i = blockIdx.x * blockDim.x + threadIdx.x;
    if (i >= n4) return;
    float4 v = ((const float4*)src)[i];
    uint32_t h0, l0, h1, l1;
    split2h(v.x, v.y, h0, l0);
    split2h(v.z, v.w, h1, l1);
    ((uint32_t*)hi)[2 * i + 0] = h0;
    ((uint32_t*)hi)[2 * i + 1] = h1;
    ((uint32_t*)lo)[2 * i + 0] = l0;
    ((uint32_t*)lo)[2 * i + 1] = l1;
}
__global__ void conv_f16(const float* __restrict__ src,
                         __half* __restrict__ dst, int n4)
{
    int i = blockIdx.x * blockDim.x + threadIdx.x;
    if (i >= n4) return;
    float4 v = ((const float4*)src)[i];
    __half2 a = __floats2half2_rn(v.x, v.y);
    __half2 b = __floats2half2_rn(v.z, v.w);
    ((uint32_t*)dst)[2 * i + 0] = *(uint32_t*)&a;
    ((uint32_t*)dst)[2 * i + 1] = *(uint32_t*)&b;
}

// ---------------------------------------------------------------------------
// HMMA GEMM: out[m,n] = sum_k A[m,k]*B[n,k], fp16 asymmetric split:
// A = Ah + Al (both fp16), B = Bh (fp16). 2 MMA products.
// CTA 128x128, BK=32, 256 threads (8 warps 64x32), 3-stage cp.async pipeline.
// mode 0: fp32 row-major out.
// mode 1: fp16 hi/lo [B,H,T,HD] head layout (*scale).
// mode 2: fp16 hi only [B,H,T,HD] head layout (*scale).
// ---------------------------------------------------------------------------
#define BM 128
#define BN 128
#define BK 32
#define TILE_B (128 * 80)        // 10240 bytes (row stride 80B)
#define STAGE_B (3 * TILE_B)     // Ah, Al, B
#define NSTAGE 3
#define GSMEM (NSTAGE * STAGE_B) // 92160

__global__ void __launch_bounds__(256) gemm_hmma(
    const __half* __restrict__ Ah, const __half* __restrict__ Al,
    const __half* __restrict__ Bh,
    float* __restrict__ out,
    __half* __restrict__ ohi, __half* __restrict__ olo,
    int Mtot, int Ntot, int Ktot, int mode, float scale)
{
    extern __shared__ char sm[];
    const uint32_t smb = smem_u32(sm);
    const int tid = threadIdx.x;
    const int wid = tid >> 5;
    const int lane = tid & 31;
    const int bm = blockIdx.y * BM;
    const int bn = blockIdx.x * BN;
    const int wm = (wid & 1) * 64;
    const int wn = (wid >> 1) * 32;

    const int ldrow = tid >> 2;              // 0..63 (+64 for u=1)
    const int ldc4  = tid & 3;               // 16B unit within 64B row chunk
    const uint32_t st_base = (uint32_t)ldc4 * 16;

    // ldmatrix lane addressing (byte offsets within a tile, 80B row stride)
    const uint32_t aoff = (uint32_t)(wm + (lane & 15)) * 80
                        + (uint32_t)((lane >> 4) * 8) * 2;
    const uint32_t boff = (uint32_t)(wn + (lane & 7)) * 80
                        + (uint32_t)(((lane >> 3) & 1) * 8) * 2;

    auto load_stage = [&](int ch, int s) {
        uint32_t dst = smb + (uint32_t)s * STAGE_B;
        #pragma unroll
        for (int u = 0; u < 2; u++) {
            int row = ldrow + u * 64;
            uint32_t so = (uint32_t)row * 80 + st_base;
            size_t gA = (size_t)(bm + row) * Ktot + ch * BK + ldc4 * 8;
            size_t gB = (size_t)(bn + row) * Ktot + ch * BK + ldc4 * 8;
            cp16(dst + 0 * TILE_B + so, &Ah[gA]);
            cp16(dst + 1 * TILE_B + so, &Al[gA]);
            cp16(dst + 2 * TILE_B + so, &Bh[gB]);
        }
    };

    float acc[4][4][4];
    #pragma unroll
    for (int mi = 0; mi < 4; mi++)
        #pragma unroll
        for (int ni = 0; ni < 4; ni++)
            #pragma unroll
            for (int r = 0; r < 4; r++) acc[mi][ni][r] = 0.f;

    const int nchunk = Ktot / BK;            // 32

    load_stage(0, 0); CP_COMMIT();
    load_stage(1, 1); CP_COMMIT();

    int sbuf = 0;
    for (int ch = 0; ch < nchunk; ch++) {
        CP_WAIT(1);
        __syncthreads();
        if (ch + 2 < nchunk) {
            int s = sbuf + 2; if (s >= NSTAGE) s -= NSTAGE;
            load_stage(ch + 2, s);
            CP_COMMIT();
        }

        const uint32_t sA_hi = smb + (uint32_t)sbuf * STAGE_B + 0 * TILE_B;
        const uint32_t sA_lo = smb + (uint32_t)sbuf * STAGE_B + 1 * TILE_B;
        const uint32_t sB    = smb + (uint32_t)sbuf * STAGE_B + 2 * TILE_B;

        #pragma unroll
        for (int ks = 0; ks < 2; ks++) {
            const uint32_t kb = ks * 32;     // 16 fp16 = 32 bytes
            uint32_t ah[4][4], al[4][4], bb[4][2];
            #pragma unroll
            for (int mi = 0; mi < 4; mi++) {
                ldsm_x4(ah[mi], sA_hi + aoff + (uint32_t)mi * 16 * 80 + kb);
                ldsm_x4(al[mi], sA_lo + aoff + (uint32_t)mi * 16 * 80 + kb);
            }
            #pragma unroll
            for (int ni = 0; ni < 4; ni++)
                ldsm_x2(bb[ni], sB + boff + (uint32_t)ni * 8 * 80 + kb);
            #pragma unroll
            for (int mi = 0; mi < 4; mi++)
                #pragma unroll
                for (int ni = 0; ni < 4; ni++) {
                    mma_f16(acc[mi][ni], ah[mi], bb[ni]);
                    mma_f16(acc[mi][ni], al[mi], bb[ni]);
                }
        }
        if (++sbuf == NSTAGE) sbuf = 0;
    }

    // Epilogue
    const int mrow0 = bm + wm + (lane >> 2);
    const int ncol0 = bn + wn + 2 * (lane & 3);
    #pragma unroll
    for (int mi = 0; mi < 4; mi++) {
        #pragma unroll
        for (int ni = 0; ni < 4; ni++) {
            int n = ncol0 + ni * 8;
            #pragma unroll
            for (int half = 0; half < 2; half++) {
                int m = mrow0 + mi * 16 + half * 8;
                float vx = acc[mi][ni][half * 2];
                float vy = acc[mi][ni][half * 2 + 1];
                if (mode == 0) {
                    *(float2*)&out[(size_t)m * Ntot + n] = make_float2(vx, vy);
                } else {
                    int b = m >> 11;
                    int t = m & (T_ - 1);
                    int hh = n >> 6;
                    int d = n & (HD_ - 1);
                    size_t off = (((size_t)b * H_ + hh) * T_ + t) * HD_ + d;
                    if (mode == 1) {
                        uint32_t h2, l2;
                        split2h(vx * scale, vy * scale, h2, l2);
                        *(uint32_t*)&ohi[off] = h2;
                        *(uint32_t*)&olo[off] = l2;
                    } else {
                        __half2 h = __floats2half2_rn(vx * scale, vy * scale);
                        *(uint32_t*)&ohi[off] = *(uint32_t*)&h;
                    }
                }
            }
        }
    }
}

// ---------------------------------------------------------------------------
// HMMA flash attention: causal, BQ=128, kv-tile 64, HD=64, 256 threads.
// Q pre-scaled by 1/8, split fp16 hi/lo. K,V single fp16. P split in-register.
// S = Qh*K + Ql*K ; O += Ph*V + Pl*V  (2 products each).
// Output ctx: fp16 hi/lo [B,T,C].
// ---------------------------------------------------------------------------
#define FQ_HI 0
#define FQ_LO 16384
#define FSTG(s) (32768 + (s) * 16384)
#define F_K 0
#define F_V 8192
#define FSMEM 65536

__global__ void __launch_bounds__(256, 1) flash_hmma(
    const __half* __restrict__ Qhi, const __half* __restrict__ Qlo,
    const __half* __restrict__ Kh, const __half* __restrict__ Vh,
    __half* __restrict__ ctx_hi, __half* __restrict__ ctx_lo)
{
    extern __shared__ char sm[];
    const uint32_t smb = smem_u32(sm);
    const int tid = threadIdx.x;
    const int wid = tid >> 5;
    const int lane = tid & 31;
    const int qb = (int)gridDim.x - 1 - (int)blockIdx.x;   // heavy tiles first
    const int bh = blockIdx.y;
    const size_t base = (size_t)bh * T_ * HD_;
    const int q0 = qb * 128;
    const int nkv = 2 * qb + 2;

    // ---- Q tiles (hi+lo): 128 rows x 8 x 16B chunks each
    #pragma unroll
    for (int u = 0; u < 4; u++) {
        int c = tid + u * 256;            // 0..1023
        int row = c >> 3;
        int c16 = c & 7;
        uint32_t d = (uint32_t)row * 128 + (((uint32_t)c16 * 16) ^ ((row & 7) << 4));
        size_t g = base + (size_t)(q0 + row) * HD_ + c16 * 8;
        cp16(smb + FQ_HI + d, &Qhi[g]);
        cp16(smb + FQ_LO + d, &Qlo[g]);
    }
    CP_COMMIT();

    // ---- K/V stage loader (single precision fp16)
    auto load_kv = [&](int kt, int s) {
        uint32_t dst = smb + FSTG(s);
        const int k0 = kt * 64;
        #pragma unroll
        for (int u = 0; u < 2; u++) {
            int c = tid + u * 256;        // 0..511
            int row = c >> 3;
            int c16 = c & 7;
            uint32_t d = (uint32_t)row * 128
                       + (((uint32_t)c16 * 16) ^ ((row & 7) << 4));
            size_t g = base + (size_t)(k0 + row) * HD_ + c16 * 8;
            cp16(dst + F_K + d, &Kh[g]);
            cp16(dst + F_V + d, &Vh[g]);
        }
        CP_COMMIT();
    };
    load_kv(0, 0);
    load_kv(1, 1);

    // ---- build Q fragments (held in registers for the whole kernel)
    CP_WAIT(2);
    __syncthreads();
    uint32_t qh[4][4], ql[4][4];
    {
        const int arow = wid * 16 + (lane & 7) + ((lane >> 3) & 1) * 8;
        const uint32_t asw = (uint32_t)(arow & 7) << 4;
        #pragma unroll
        for (int ks = 0; ks < 4; ks++) {
            uint32_t colb = (uint32_t)ks * 32 + (uint32_t)(lane >> 4) * 16;
            uint32_t ad = (uint32_t)arow * 128 + (colb ^ asw);
            ldsm_x4(qh[ks], smb + FQ_HI + ad);
            ldsm_x4(ql[ks], smb + FQ_LO + ad);
        }
    }

    float oacc[8][4];
    #pragma unroll
    for (int nt = 0; nt < 8; nt++)
        #pragma unroll
        for (int r = 0; r < 4; r++) oacc[nt][r] = 0.f;
    float mrow[2] = {-1e30f, -1e30f};
    float lrow[2] = {0.f, 0.f};

    const int krow = (lane & 7) + (lane >> 4) * 8;           // + nt2*16
    const uint32_t kcol = (uint32_t)((lane >> 3) & 1) * 16;  // + ks*32
    const int vrow = (lane & 7) + ((lane >> 3) & 1) * 8;     // + ks*16
    const uint32_t vcol = (uint32_t)(lane >> 4) * 16;        // + nt2*32

    for (int kb = 0; kb < nkv; kb++) {
        const uint32_t stg = smb + FSTG(kb & 1);
        CP_WAIT(1);
        __syncthreads();

        // ---------- S = Q K^T (2 products) ----------
        float sc[8][4];
        #pragma unroll
        for (int nt = 0; nt < 8; nt++)
            #pragma unroll
            for (int r = 0; r < 4; r++) sc[nt][r] = 0.f;

        #pragma unroll
        for (int ks = 0; ks < 4; ks++) {
            uint32_t kf[4][4];
            #pragma unroll
            for (int nt2 = 0; nt2 < 4; nt2++) {
                int row = nt2 * 16 + krow;
                uint32_t colb = (uint32_t)ks * 32 + kcol;
                uint32_t ad = (uint32_t)row * 128 + (colb ^ ((row & 7) << 4));
                ldsm_x4(kf[nt2], stg + F_K + ad);
            }
            #pragma unroll
            for (int nt = 0; nt < 8; nt++) {
                const uint32_t* bb = &kf[nt >> 1][(nt & 1) * 2];
                mma_f16(sc[nt], qh[ks], bb);
                mma_f16(sc[nt], ql[ks], bb);
            }
        }

        // ---------- causal mask (last two tiles only) ----------
        if (kb >= nkv - 2) {
            int grow0 = q0 + wid * 16 + (lane >> 2);
            int gcol0 = kb * 64 + 2 * (lane & 3);
            #pragma unroll
            for (int nt = 0; nt < 8; nt++)
                #pragma unroll
                for (int e = 0; e < 4; e++) {
                    int col = gcol0 + nt * 8 + (e & 1);
                    int row = grow0 + (e >> 1) * 8;
                    if (col > row) sc[nt][e] = -1e30f;
                }
        }

        // ---------- online softmax ----------
        float mx0 = -1e30f, mx1 = -1e30f;
        #pragma unroll
        for (int nt = 0; nt < 8; nt++) {
            mx0 = fmaxf(mx0, fmaxf(sc[nt][0], sc[nt][1]));
            mx1 = fmaxf(mx1, fmaxf(sc[nt][2], sc[nt][3]));
        }
        mx0 = fmaxf(mx0, __shfl_xor_sync(0xffffffffu, mx0, 1));
        mx0 = fmaxf(mx0, __shfl_xor_sync(0xffffffffu, mx0, 2));
        mx1 = fmaxf(mx1, __shfl_xor_sync(0xffffffffu, mx1, 1));
        mx1 = fmaxf(mx1, __shfl_xor_sync(0xffffffffu, mx1, 2));
        float mn0 = fmaxf(mrow[0], mx0);
        float mn1 = fmaxf(mrow[1], mx1);
        float cs0 = __expf(mrow[0] - mn0);
        float cs1 = __expf(mrow[1] - mn1);
        mrow[0] = mn0; mrow[1] = mn1;

        float sum0 = 0.f, sum1 = 0.f;
        #pragma unroll
        for (int nt = 0; nt < 8; nt++) {
            sc[nt][0] = __expf(sc[nt][0] - mn0); sum0 += sc[nt][0];
            sc[nt][1] = __expf(sc[nt][1] - mn0); sum0 += sc[nt][1];
            sc[nt][2] = __expf(sc[nt][2] - mn1); sum1 += sc[nt][2];
            sc[nt][3] = __expf(sc[nt][3] - mn1); sum1 += sc[nt][3];
        }
        sum0 += __shfl_xor_sync(0xffffffffu, sum0, 1);
        sum0 += __shfl_xor_sync(0xffffffffu, sum0, 2);
        sum1 += __shfl_xor_sync(0xffffffffu, sum1, 1);
        sum1 += __shfl_xor_sync(0xffffffffu, sum1, 2);
        lrow[0] = lrow[0] * cs0 + sum0;
        lrow[1] = lrow[1] * cs1 + sum1;
        #pragma unroll
        for (int nt = 0; nt < 8; nt++) {
            oacc[nt][0] *= cs0; oacc[nt][1] *= cs0;
            oacc[nt][2] *= cs1; oacc[nt][3] *= cs1;
        }

        // ---------- O += P V (2 products; P split in registers) ----------
        #pragma unroll
        for (int ks = 0; ks < 4; ks++) {
            uint32_t ph[4], pl[4];
            split2h(sc[2 * ks][0],     sc[2 * ks][1],     ph[0], pl[0]);
            split2h(sc[2 * ks][2],     sc[2 * ks][3],     ph[1], pl[1]);
            split2h(sc[2 * ks + 1][0], sc[2 * ks + 1][1], ph[2], pl[2]);
            split2h(sc[2 * ks + 1][2], sc[2 * ks + 1][3], ph[3], pl[3]);
            #pragma unroll
            for (int nt2 = 0; nt2 < 4; nt2++) {
                int row = ks * 16 + vrow;
                uint32_t colb = (uint32_t)nt2 * 32 + vcol;
                uint32_t ad = (uint32_t)row * 128 + (colb ^ ((row & 7) << 4));
                uint32_t vf[4];
                ldsm_x4_t(vf, stg + F_V + ad);
                mma_f16(oacc[2 * nt2],     ph, &vf[0]);
                mma_f16(oacc[2 * nt2],     pl, &vf[0]);
                mma_f16(oacc[2 * nt2 + 1], ph, &vf[2]);
                mma_f16(oacc[2 * nt2 + 1], pl, &vf[2]);
            }
        }

        __syncthreads();
        if (kb + 2 < nkv) load_kv(kb + 2, kb & 1);
    }

    // ---------- normalize + store ctx as fp16 hi/lo ----------
    float inv0 = 1.f / lrow[0];
    float inv1 = 1.f / lrow[1];
    const int b = bh >> 4;
    const int hh = bh & 15;
    #pragma unroll
    for (int h = 0; h < 2; h++) {
        float inv = h ? inv1 : inv0;
        int t = q0 + wid * 16 + (lane >> 2) + h * 8;
        #pragma unroll
        for (int nt = 0; nt < 8; nt++) {
            int col = hh * 64 + nt * 8 + 2 * (lane & 3);
            size_t off = ((size_t)b * T_ + t) * C_ + col;
            uint32_t h2, l2;
            split2h(oacc[nt][2 * h] * inv, oacc[nt][2 * h + 1] * inv, h2, l2);
            *(uint32_t*)&ctx_hi[off] = h2;
            *(uint32_t*)&ctx_lo[off] = l2;
        }
    }
}

// ---------------------------------------------------------------------------
// kernel_launch
// ---------------------------------------------------------------------------
extern "C" void kernel_launch(void* const* d_in, const int* in_sizes, int n_in,
                              void* d_out, int out_size)
{
    const float* x = (const float*)d_in[0];
    const float* W[4] = {(const float*)d_in[1], (const float*)d_in[2],
                         (const float*)d_in[3], (const float*)d_in[4]};
    float* out = (float*)d_out;

    __half *xh, *xl, *wh, *qh, *ql, *kh, *vh, *ch, *cl;
    cudaGetSymbolAddress((void**)&xh, g_Xh);
    cudaGetSymbolAddress((void**)&xl, g_Xl);
    cudaGetSymbolAddress((void**)&wh, g_Wh);
    cudaGetSymbolAddress((void**)&qh, g_Qh);
    cudaGetSymbolAddress((void**)&ql, g_Ql);
    cudaGetSymbolAddress((void**)&kh, g_Kh);
    cudaGetSymbolAddress((void**)&vh, g_Vh);
    cudaGetSymbolAddress((void**)&ch, g_CTXh);
    cudaGetSymbolAddress((void**)&cl, g_CTXl);

    cudaFuncSetAttribute(gemm_hmma,
                         cudaFuncAttributeMaxDynamicSharedMemorySize, GSMEM);
    cudaFuncSetAttribute(flash_hmma,
                         cudaFuncAttributeMaxDynamicSharedMemorySize, FSMEM);

    // Conversions
    {
        int n4 = M_ * C_ / 4;
        split_f16<<<n4 / 256, 256>>>(x, xh, xl, n4);
        int w4 = C_ * C_ / 4;
        for (int i = 0; i < 4; i++)
            conv_f16<<<w4 / 256, 256>>>(W[i], wh + (size_t)i * C_ * C_, w4);
    }

    dim3 gg(C_ / BN, M_ / BM);   // (8, 64)
    // QKV projections (Q split hi/lo + pre-scaled 1/8; K,V single fp16)
    gemm_hmma<<<gg, 256, GSMEM>>>(xh, xl, wh + 0 * (size_t)C_ * C_,
        nullptr, qh, ql, M_, C_, C_, 1, 0.125f);
    gemm_hmma<<<gg, 256, GSMEM>>>(xh, xl, wh + 1 * (size_t)C_ * C_,
        nullptr, kh, nullptr, M_, C_, C_, 2, 1.0f);
    gemm_hmma<<<gg, 256, GSMEM>>>(xh, xl, wh + 2 * (size_t)C_ * C_,
        nullptr, vh, nullptr, M_, C_, C_, 2, 1.0f);

    // Causal flash attention (HMMA, fp16 2-product)
    flash_hmma<<<dim3(T_ / 128, B_ * H_), 256, FSMEM>>>(
        qh, ql, kh, vh, ch, cl);

    // Output projection (fp32 out)
    gemm_hmma<<<gg, 256, GSMEM>>>(ch, cl, wh + 3 * (size_t)C_ * C_,
        out, nullptr, nullptr, M_, C_, C_, 0, 1.0f);
}

// round 6
// speedup vs baseline: 5.5677x; 1.1683x over previous
#include <cuda_runtime.h>
#include <cuda_fp16.h>
#include <cstdint>
#include <math.h>

// Problem constants
#define B_  4
#define T_  2048
#define C_  1024
#define H_  16
#define HD_ 64
#define M_  (B_ * T_)   // 8192

// ---------------------------------------------------------------------------
// Scratch (__device__ globals, allocation-free rule)
// ---------------------------------------------------------------------------
__device__ __half g_Xh[(size_t)M_ * C_];
__device__ __half g_Xl[(size_t)M_ * C_];
__device__ __half g_Wh[4][(size_t)C_ * C_];
__device__ __half g_Qh[(size_t)M_ * C_];   // [B,H,T,HD], pre-scaled 1/8
__device__ __half g_Ql[(size_t)M_ * C_];
__device__ __half g_Kh[(size_t)M_ * C_];   // [B,H,T,HD]
__device__ __half g_Vh[(size_t)M_ * C_];
__device__ __half g_CTXh[(size_t)M_ * C_]; // [B,T,C]
__device__ __half g_CTXl[(size_t)M_ * C_];

// ---------------------------------------------------------------------------
// PTX helpers
// ---------------------------------------------------------------------------
__device__ __forceinline__ uint32_t smem_u32(const void* p) {
    uint32_t a;
    asm("{ .reg .u64 t; cvta.to.shared.u64 t, %1; cvt.u32.u64 %0, t; }"
        : "=r"(a) : "l"(p));
    return a;
}
__device__ __forceinline__ void ldsm_x4(uint32_t* r, uint32_t addr) {
    asm volatile("ldmatrix.sync.aligned.m8n8.x4.shared.b16 {%0,%1,%2,%3}, [%4];"
        : "=r"(r[0]), "=r"(r[1]), "=r"(r[2]), "=r"(r[3]) : "r"(addr));
}
__device__ __forceinline__ void ldsm_x4_t(uint32_t* r, uint32_t addr) {
    asm volatile("ldmatrix.sync.aligned.m8n8.x4.trans.shared.b16 {%0,%1,%2,%3}, [%4];"
        : "=r"(r[0]), "=r"(r[1]), "=r"(r[2]), "=r"(r[3]) : "r"(addr));
}
__device__ __forceinline__ void mma_f16(float* d, const uint32_t* a,
                                        const uint32_t* b) {
    asm volatile(
        "mma.sync.aligned.m16n8k16.row.col.f32.f16.f16.f32 "
        "{%0,%1,%2,%3}, {%4,%5,%6,%7}, {%8,%9}, {%0,%1,%2,%3};"
        : "+f"(d[0]), "+f"(d[1]), "+f"(d[2]), "+f"(d[3])
        : "r"(a[0]), "r"(a[1]), "r"(a[2]), "r"(a[3]), "r"(b[0]), "r"(b[1]));
}
__device__ __forceinline__ void cp16(uint32_t dst, const void* src) {
    asm volatile("cp.async.cg.shared.global [%0], [%1], 16;"
                 :: "r"(dst), "l"(src));
}
#define CP_COMMIT() asm volatile("cp.async.commit_group;" ::: "memory")
#define CP_WAIT(n)  asm volatile("cp.async.wait_group %0;" :: "n"(n) : "memory")

// split a float2 into fp16 hi pair + fp16 lo (residual) pair
__device__ __forceinline__ void split2h(float x, float y,
                                        uint32_t& hi, uint32_t& lo) {
    __half2 h = __floats2half2_rn(x, y);
    float2 hf = __half22float2(h);
    __half2 l = __floats2half2_rn(x - hf.x, y - hf.y);
    hi = *(uint32_t*)&h;
    lo = *(uint32_t*)&l;
}

// ---------------------------------------------------------------------------
// Conversions
// ---------------------------------------------------------------------------
__global__ void split_f16(const float* __restrict__ src,
                          __half* __restrict__ hi, __half* __restrict__ lo,
                          int n4)
{
    int i = blockIdx.x * blockDim.x + threadIdx.x;
    if (i >= n4) return;
    float4 v = ((const float4*)src)[i];
    uint32_t h0, l0, h1, l1;
    split2h(v.x, v.y, h0, l0);
    split2h(v.z, v.w, h1, l1);
    ((uint32_t*)hi)[2 * i + 0] = h0;
    ((uint32_t*)hi)[2 * i + 1] = h1;
    ((uint32_t*)lo)[2 * i + 0] = l0;
    ((uint32_t*)lo)[2 * i + 1] = l1;
}
__global__ void conv_f16(const float* __restrict__ src,
                         __half* __restrict__ dst, int n4)
{
    int i = blockIdx.x * blockDim.x + threadIdx.x;
    if (i >= n4) return;
    float4 v = ((const float4*)src)[i];
    __half2 a = __floats2half2_rn(v.x, v.y);
    __half2 b = __floats2half2_rn(v.z, v.w);
    ((uint32_t*)dst)[2 * i + 0] = *(uint32_t*)&a;
    ((uint32_t*)dst)[2 * i + 1] = *(uint32_t*)&b;
}

// ---------------------------------------------------------------------------
// HMMA GEMM: out[m,n] = sum_k A[m,k]*W[n,k], fp16 asymmetric split
// (A = Ah + Al, W rounded). CTA 128x128, BK=64, 256 threads (8 warps 64x32),
// 3-stage cp.async pipeline, 128B rows + XOR swizzle.
// MODE 0: fp32 row-major out (Wo projection), grid (8, 64).
// MODE 1: merged QKV, grid (24, 64): wi = blockIdx.x>>3 picks W and dest.
//         wi==0 -> Q split hi/lo * 0.125 ; wi==1 -> K ; wi==2 -> V.
// ---------------------------------------------------------------------------
#define BM 128
#define BN 128
#define BK 64
#define GT_B 16384               // 128 rows x 128 bytes
#define GSTAGE (3 * GT_B)        // Ah, Al, W
#define GSMEM (3 * GSTAGE)       // 147456

template<int MODE>
__global__ void __launch_bounds__(256) gemm_f16(
    const __half* __restrict__ Ah, const __half* __restrict__ Al,
    const __half* __restrict__ Wbase,
    float* __restrict__ out,
    __half* __restrict__ qh, __half* __restrict__ ql,
    __half* __restrict__ kh, __half* __restrict__ vh)
{
    extern __shared__ char smc[];
    const uint32_t smb = smem_u32(smc);
    const int tid = threadIdx.x;
    const int wid = tid >> 5;
    const int lane = tid & 31;
    const int bm = blockIdx.y * BM;

    int wi, bn;
    if (MODE == 1) { wi = blockIdx.x >> 3; bn = (blockIdx.x & 7) * BN; }
    else           { wi = 0;               bn = blockIdx.x * BN; }
    const __half* Bh = Wbase + (size_t)wi * C_ * C_;

    const int wm = (wid & 1) * 64;
    const int wn = (wid >> 1) * 32;

    // gmem->smem mapping: 1024 16B chunks per tile; 4 per thread
    const int ldrow = tid >> 3;             // base row (0..31), +32*u
    const int ldc16 = tid & 7;              // 16B chunk in row
    const uint32_t st_off = (uint32_t)ldrow * 128
                          + (((uint32_t)ldc16 * 16) ^ ((ldrow & 7) << 4));

    auto load_stage = [&](int ch, int s) {
        uint32_t dst = smb + (uint32_t)s * GSTAGE;
        #pragma unroll
        for (int u = 0; u < 4; u++) {
            int row = ldrow + u * 32;
            uint32_t so = st_off + (uint32_t)u * 32 * 128;
            size_t gA = (size_t)(bm + row) * C_ + ch * BK + ldc16 * 8;
            size_t gB = (size_t)(bn + row) * C_ + ch * BK + ldc16 * 8;
            cp16(dst + 0 * GT_B + so, &Ah[gA]);
            cp16(dst + 1 * GT_B + so, &Al[gA]);
            cp16(dst + 2 * GT_B + so, &Bh[gB]);
        }
    };

    // fragment lane addressing (base + per-ks XOR)
    uint32_t a_base[4], a_swz[4];
    #pragma unroll
    for (int mi = 0; mi < 4; mi++) {
        int r = wm + mi * 16 + (lane & 15);
        a_base[mi] = (uint32_t)r * 128;
        a_swz[mi] = (uint32_t)(r & 7) << 4;
    }
    const uint32_t a_lp = (uint32_t)(lane >> 4) * 16;
    uint32_t b_base[4], b_swz[4];
    #pragma unroll
    for (int ni = 0; ni < 4; ni++) {
        int r = wn + ni * 8 + (lane & 7);
        b_base[ni] = (uint32_t)r * 128;
        b_swz[ni] = (uint32_t)(r & 7) << 4;
    }
    const uint32_t b_lp = (uint32_t)(lane >> 3) * 16;

    float acc[4][4][4];
    #pragma unroll
    for (int mi = 0; mi < 4; mi++)
        #pragma unroll
        for (int ni = 0; ni < 4; ni++)
            #pragma unroll
            for (int r = 0; r < 4; r++) acc[mi][ni][r] = 0.f;

    const int nchunk = C_ / BK;             // 16
    load_stage(0, 0); CP_COMMIT();
    load_stage(1, 1); CP_COMMIT();

    int sbuf = 0;
    for (int ch = 0; ch < nchunk; ch++) {
        CP_WAIT(1);
        __syncthreads();
        if (ch + 2 < nchunk) {
            int s = sbuf + 2; if (s >= 3) s -= 3;
            load_stage(ch + 2, s);
            CP_COMMIT();
        }
        const uint32_t sA_hi = smb + (uint32_t)sbuf * GSTAGE + 0 * GT_B;
        const uint32_t sA_lo = smb + (uint32_t)sbuf * GSTAGE + 1 * GT_B;
        const uint32_t sB    = smb + (uint32_t)sbuf * GSTAGE + 2 * GT_B;

        #pragma unroll
        for (int kp = 0; kp < 2; kp++) {
            // B fragments for two k-steps at once (x4 = n8 x k32)
            uint32_t bf[4][4];
            #pragma unroll
            for (int ni = 0; ni < 4; ni++)
                ldsm_x4(bf[ni], sB + b_base[ni]
                        + ((((uint32_t)kp * 64) | b_lp) ^ b_swz[ni]));
            #pragma unroll
            for (int sub = 0; sub < 2; sub++) {
                const uint32_t kc = (uint32_t)(kp * 2 + sub) * 32;
                uint32_t ahf[4][4], alf[4][4];
                #pragma unroll
                for (int mi = 0; mi < 4; mi++) {
                    uint32_t ax = (kc | a_lp) ^ a_swz[mi];
                    ldsm_x4(ahf[mi], sA_hi + a_base[mi] + ax);
                    ldsm_x4(alf[mi], sA_lo + a_base[mi] + ax);
                }
                #pragma unroll
                for (int mi = 0; mi < 4; mi++)
                    #pragma unroll
                    for (int ni = 0; ni < 4; ni++) {
                        mma_f16(acc[mi][ni], ahf[mi], &bf[ni][sub * 2]);
                        mma_f16(acc[mi][ni], alf[mi], &bf[ni][sub * 2]);
                    }
            }
        }
        if (++sbuf == 3) sbuf = 0;
    }

    // Epilogue
    const int mrow0 = bm + wm + (lane >> 2);
    const int ncol0 = wn + 2 * (lane & 3);
    #pragma unroll
    for (int mi = 0; mi < 4; mi++) {
        #pragma unroll
        for (int ni = 0; ni < 4; ni++) {
            int nl = ncol0 + ni * 8;               // 0..127 within tile
            #pragma unroll
            for (int half = 0; half < 2; half++) {
                int m = mrow0 + mi * 16 + half * 8;
                float vx = acc[mi][ni][half * 2];
                float vy = acc[mi][ni][half * 2 + 1];
                if (MODE == 0) {
                    int n = bn + nl;
                    *(float2*)&out[(size_t)m * C_ + n] = make_float2(vx, vy);
                } else {
                    int n = bn + nl;
                    int b = m >> 11;
                    int t = m & (T_ - 1);
                    int hh = n >> 6;
                    int d = n & (HD_ - 1);
                    size_t off = (((size_t)b * H_ + hh) * T_ + t) * HD_ + d;
                    if (wi == 0) {
                        uint32_t h2, l2;
                        split2h(vx * 0.125f, vy * 0.125f, h2, l2);
                        *(uint32_t*)&qh[off] = h2;
                        *(uint32_t*)&ql[off] = l2;
                    } else {
                        __half2 h = __floats2half2_rn(vx, vy);
                        *(uint32_t*)&((wi == 1) ? kh : vh)[off] = *(uint32_t*)&h;
                    }
                }
            }
        }
    }
}

// ---------------------------------------------------------------------------
// HMMA flash attention: causal, BQ=128, kv-tile 64, HD=64, 256 threads.
// Q pre-scaled by 1/8, split fp16 hi/lo. K,V single fp16. P split in-register.
// ---------------------------------------------------------------------------
#define FQ_HI 0
#define FQ_LO 16384
#define FSTG(s) (32768 + (s) * 16384)
#define F_K 0
#define F_V 8192
#define FSMEM 65536

__global__ void __launch_bounds__(256, 1) flash_hmma(
    const __half* __restrict__ Qhi, const __half* __restrict__ Qlo,
    const __half* __restrict__ Kh, const __half* __restrict__ Vh,
    __half* __restrict__ ctx_hi, __half* __restrict__ ctx_lo)
{
    extern __shared__ char sm[];
    const uint32_t smb = smem_u32(sm);
    const int tid = threadIdx.x;
    const int wid = tid >> 5;
    const int lane = tid & 31;
    const int qb = (int)gridDim.x - 1 - (int)blockIdx.x;   // heavy tiles first
    const int bh = blockIdx.y;
    const size_t base = (size_t)bh * T_ * HD_;
    const int q0 = qb * 128;
    const int nkv = 2 * qb + 2;

    #pragma unroll
    for (int u = 0; u < 4; u++) {
        int c = tid + u * 256;
        int row = c >> 3;
        int c16 = c & 7;
        uint32_t d = (uint32_t)row * 128 + (((uint32_t)c16 * 16) ^ ((row & 7) << 4));
        size_t g = base + (size_t)(q0 + row) * HD_ + c16 * 8;
        cp16(smb + FQ_HI + d, &Qhi[g]);
        cp16(smb + FQ_LO + d, &Qlo[g]);
    }
    CP_COMMIT();

    auto load_kv = [&](int kt, int s) {
        uint32_t dst = smb + FSTG(s);
        const int k0 = kt * 64;
        #pragma unroll
        for (int u = 0; u < 2; u++) {
            int c = tid + u * 256;
            int row = c >> 3;
            int c16 = c & 7;
            uint32_t d = (uint32_t)row * 128
                       + (((uint32_t)c16 * 16) ^ ((row & 7) << 4));
            size_t g = base + (size_t)(k0 + row) * HD_ + c16 * 8;
            cp16(dst + F_K + d, &Kh[g]);
            cp16(dst + F_V + d, &Vh[g]);
        }
        CP_COMMIT();
    };
    load_kv(0, 0);
    load_kv(1, 1);

    CP_WAIT(2);
    __syncthreads();
    uint32_t qh[4][4], ql[4][4];
    {
        const int arow = wid * 16 + (lane & 7) + ((lane >> 3) & 1) * 8;
        const uint32_t asw = (uint32_t)(arow & 7) << 4;
        #pragma unroll
        for (int ks = 0; ks < 4; ks++) {
            uint32_t colb = (uint32_t)ks * 32 + (uint32_t)(lane >> 4) * 16;
            uint32_t ad = (uint32_t)arow * 128 + (colb ^ asw);
            ldsm_x4(qh[ks], smb + FQ_HI + ad);
            ldsm_x4(ql[ks], smb + FQ_LO + ad);
        }
    }

    float oacc[8][4];
    #pragma unroll
    for (int nt = 0; nt < 8; nt++)
        #pragma unroll
        for (int r = 0; r < 4; r++) oacc[nt][r] = 0.f;
    float mrow[2] = {-1e30f, -1e30f};
    float lrow[2] = {0.f, 0.f};

    const int krow = (lane & 7) + (lane >> 4) * 8;
    const uint32_t kcol = (uint32_t)((lane >> 3) & 1) * 16;
    const int vrow = (lane & 7) + ((lane >> 3) & 1) * 8;
    const uint32_t vcol = (uint32_t)(lane >> 4) * 16;

    for (int kb = 0; kb < nkv; kb++) {
        const uint32_t stg = smb + FSTG(kb & 1);
        CP_WAIT(1);
        __syncthreads();

        float sc[8][4];
        #pragma unroll
        for (int nt = 0; nt < 8; nt++)
            #pragma unroll
            for (int r = 0; r < 4; r++) sc[nt][r] = 0.f;

        #pragma unroll
        for (int ks = 0; ks < 4; ks++) {
            uint32_t kf[4][4];
            #pragma unroll
            for (int nt2 = 0; nt2 < 4; nt2++) {
                int row = nt2 * 16 + krow;
                uint32_t colb = (uint32_t)ks * 32 + kcol;
                uint32_t ad = (uint32_t)row * 128 + (colb ^ ((row & 7) << 4));
                ldsm_x4(kf[nt2], stg + F_K + ad);
            }
            #pragma unroll
            for (int nt = 0; nt < 8; nt++) {
                const uint32_t* bb = &kf[nt >> 1][(nt & 1) * 2];
                mma_f16(sc[nt], qh[ks], bb);
                mma_f16(sc[nt], ql[ks], bb);
            }
        }

        if (kb >= nkv - 2) {
            int grow0 = q0 + wid * 16 + (lane >> 2);
            int gcol0 = kb * 64 + 2 * (lane & 3);
            #pragma unroll
            for (int nt = 0; nt < 8; nt++)
                #pragma unroll
                for (int e = 0; e < 4; e++) {
                    int col = gcol0 + nt * 8 + (e & 1);
                    int row = grow0 + (e >> 1) * 8;
                    if (col > row) sc[nt][e] = -1e30f;
                }
        }

        float mx0 = -1e30f, mx1 = -1e30f;
        #pragma unroll
        for (int nt = 0; nt < 8; nt++) {
            mx0 = fmaxf(mx0, fmaxf(sc[nt][0], sc[nt][1]));
            mx1 = fmaxf(mx1, fmaxf(sc[nt][2], sc[nt][3]));
        }
        mx0 = fmaxf(mx0, __shfl_xor_sync(0xffffffffu, mx0, 1));
        mx0 = fmaxf(mx0, __shfl_xor_sync(0xffffffffu, mx0, 2));
        mx1 = fmaxf(mx1, __shfl_xor_sync(0xffffffffu, mx1, 1));
        mx1 = fmaxf(mx1, __shfl_xor_sync(0xffffffffu, mx1, 2));
        float mn0 = fmaxf(mrow[0], mx0);
        float mn1 = fmaxf(mrow[1], mx1);
        float cs0 = __expf(mrow[0] - mn0);
        float cs1 = __expf(mrow[1] - mn1);
        mrow[0] = mn0; mrow[1] = mn1;

        float sum0 = 0.f, sum1 = 0.f;
        #pragma unroll
        for (int nt = 0; nt < 8; nt++) {
            sc[nt][0] = __expf(sc[nt][0] - mn0); sum0 += sc[nt][0];
            sc[nt][1] = __expf(sc[nt][1] - mn0); sum0 += sc[nt][1];
            sc[nt][2] = __expf(sc[nt][2] - mn1); sum1 += sc[nt][2];
            sc[nt][3] = __expf(sc[nt][3] - mn1); sum1 += sc[nt][3];
        }
        sum0 += __shfl_xor_sync(0xffffffffu, sum0, 1);
        sum0 += __shfl_xor_sync(0xffffffffu, sum0, 2);
        sum1 += __shfl_xor_sync(0xffffffffu, sum1, 1);
        sum1 += __shfl_xor_sync(0xffffffffu, sum1, 2);
        lrow[0] = lrow[0] * cs0 + sum0;
        lrow[1] = lrow[1] * cs1 + sum1;
        #pragma unroll
        for (int nt = 0; nt < 8; nt++) {
            oacc[nt][0] *= cs0; oacc[nt][1] *= cs0;
            oacc[nt][2] *= cs1; oacc[nt][3] *= cs1;
        }

        #pragma unroll
        for (int ks = 0; ks < 4; ks++) {
            uint32_t ph[4], pl[4];
            split2h(sc[2 * ks][0],     sc[2 * ks][1],     ph[0], pl[0]);
            split2h(sc[2 * ks][2],     sc[2 * ks][3],     ph[1], pl[1]);
            split2h(sc[2 * ks + 1][0], sc[2 * ks + 1][1], ph[2], pl[2]);
            split2h(sc[2 * ks + 1][2], sc[2 * ks + 1][3], ph[3], pl[3]);
            #pragma unroll
            for (int nt2 = 0; nt2 < 4; nt2++) {
                int row = ks * 16 + vrow;
                uint32_t colb = (uint32_t)nt2 * 32 + vcol;
                uint32_t ad = (uint32_t)row * 128 + (colb ^ ((row & 7) << 4));
                uint32_t vf[4];
                ldsm_x4_t(vf, stg + F_V + ad);
                mma_f16(oacc[2 * nt2],     ph, &vf[0]);
                mma_f16(oacc[2 * nt2],     pl, &vf[0]);
                mma_f16(oacc[2 * nt2 + 1], ph, &vf[2]);
                mma_f16(oacc[2 * nt2 + 1], pl, &vf[2]);
            }
        }

        __syncthreads();
        if (kb + 2 < nkv) load_kv(kb + 2, kb & 1);
    }

    float inv0 = 1.f / lrow[0];
    float inv1 = 1.f / lrow[1];
    const int b = bh >> 4;
    const int hh = bh & 15;
    #pragma unroll
    for (int h = 0; h < 2; h++) {
        float inv = h ? inv1 : inv0;
        int t = q0 + wid * 16 + (lane >> 2) + h * 8;
        #pragma unroll
        for (int nt = 0; nt < 8; nt++) {
            int col = hh * 64 + nt * 8 + 2 * (lane & 3);
            size_t off = ((size_t)b * T_ + t) * C_ + col;
            uint32_t h2, l2;
            split2h(oacc[nt][2 * h] * inv, oacc[nt][2 * h + 1] * inv, h2, l2);
            *(uint32_t*)&ctx_hi[off] = h2;
            *(uint32_t*)&ctx_lo[off] = l2;
        }
    }
}

// ---------------------------------------------------------------------------
// kernel_launch
// ---------------------------------------------------------------------------
extern "C" void kernel_launch(void* const* d_in, const int* in_sizes, int n_in,
                              void* d_out, int out_size)
{
    const float* x  = (const float*)d_in[0];
    const float* Wq = (const float*)d_in[1];
    const float* Wk = (const float*)d_in[2];
    const float* Wv = (const float*)d_in[3];
    const float* Wo = (const float*)d_in[4];
    float* out = (float*)d_out;

    __half *xh, *xl, *wh, *qh, *ql, *kh, *vh, *ch, *cl;
    cudaGetSymbolAddress((void**)&xh, g_Xh);
    cudaGetSymbolAddress((void**)&xl, g_Xl);
    cudaGetSymbolAddress((void**)&wh, g_Wh);
    cudaGetSymbolAddress((void**)&qh, g_Qh);
    cudaGetSymbolAddress((void**)&ql, g_Ql);
    cudaGetSymbolAddress((void**)&kh, g_Kh);
    cudaGetSymbolAddress((void**)&vh, g_Vh);
    cudaGetSymbolAddress((void**)&ch, g_CTXh);
    cudaGetSymbolAddress((void**)&cl, g_CTXl);

    cudaFuncSetAttribute(gemm_f16<0>,
                         cudaFuncAttributeMaxDynamicSharedMemorySize, GSMEM);
    cudaFuncSetAttribute(gemm_f16<1>,
                         cudaFuncAttributeMaxDynamicSharedMemorySize, GSMEM);
    cudaFuncSetAttribute(flash_hmma,
                         cudaFuncAttributeMaxDynamicSharedMemorySize, FSMEM);

    // Conversions: x -> split hi/lo ; W[qkvo] -> fp16 (one launch each)
    {
        int n4 = M_ * C_ / 4;
        split_f16<<<n4 / 256, 256>>>(x, xh, xl, n4);
        int w4 = C_ * C_ / 4;
        conv_f16<<<w4 / 256, 256>>>(Wq, wh + 0 * (size_t)C_ * C_, w4);
        conv_f16<<<w4 / 256, 256>>>(Wk, wh + 1 * (size_t)C_ * C_, w4);
        conv_f16<<<w4 / 256, 256>>>(Wv, wh + 2 * (size_t)C_ * C_, w4);
        conv_f16<<<w4 / 256, 256>>>(Wo, wh + 3 * (size_t)C_ * C_, w4);
    }

    // Merged QKV projection (grid 24 x 64)
    gemm_f16<1><<<dim3(24, M_ / BM), 256, GSMEM>>>(
        xh, xl, wh, nullptr, qh, ql, kh, vh);

    // Causal flash attention
    flash_hmma<<<dim3(T_ / 128, B_ * H_), 256, FSMEM>>>(
        qh, ql, kh, vh, ch, cl);

    // Output projection (fp32 out)
    gemm_f16<0><<<dim3(8, M_ / BM), 256, GSMEM>>>(
        ch, cl, wh + 3 * (size_t)C_ * C_, out, nullptr, nullptr, nullptr, nullptr);
}

// round 7
// speedup vs baseline: 6.7710x; 1.2161x over previous
#include <cuda_runtime.h>
#include <cuda_fp16.h>
#include <cstdint>
#include <math.h>

// Problem constants
#define B_  4
#define T_  2048
#define C_  1024
#define H_  16
#define HD_ 64
#define M_  (B_ * T_)   // 8192

// ---------------------------------------------------------------------------
// Scratch (__device__ globals, allocation-free rule)
// ---------------------------------------------------------------------------
__device__ __half g_Xh[(size_t)M_ * C_];
__device__ __half g_Xl[(size_t)M_ * C_];
__device__ __half g_Wh[4][(size_t)C_ * C_];
__device__ __half g_Qh[(size_t)M_ * C_];   // [B,H,T,HD], pre-scaled 1/8
__device__ __half g_Ql[(size_t)M_ * C_];
__device__ __half g_Kh[(size_t)M_ * C_];   // [B,H,T,HD]
__device__ __half g_Vh[(size_t)M_ * C_];
__device__ __half g_CTXh[(size_t)M_ * C_]; // [B,T,C]

// ---------------------------------------------------------------------------
// PTX helpers
// ---------------------------------------------------------------------------
__device__ __forceinline__ uint32_t smem_u32(const void* p) {
    uint32_t a;
    asm("{ .reg .u64 t; cvta.to.shared.u64 t, %1; cvt.u32.u64 %0, t; }"
        : "=r"(a) : "l"(p));
    return a;
}
__device__ __forceinline__ void ldsm_x4(uint32_t* r, uint32_t addr) {
    asm volatile("ldmatrix.sync.aligned.m8n8.x4.shared.b16 {%0,%1,%2,%3}, [%4];"
        : "=r"(r[0]), "=r"(r[1]), "=r"(r[2]), "=r"(r[3]) : "r"(addr));
}
__device__ __forceinline__ void ldsm_x4_t(uint32_t* r, uint32_t addr) {
    asm volatile("ldmatrix.sync.aligned.m8n8.x4.trans.shared.b16 {%0,%1,%2,%3}, [%4];"
        : "=r"(r[0]), "=r"(r[1]), "=r"(r[2]), "=r"(r[3]) : "r"(addr));
}
__device__ __forceinline__ void mma_f16(float* d, const uint32_t* a,
                                        const uint32_t* b) {
    asm volatile(
        "mma.sync.aligned.m16n8k16.row.col.f32.f16.f16.f32 "
        "{%0,%1,%2,%3}, {%4,%5,%6,%7}, {%8,%9}, {%0,%1,%2,%3};"
        : "+f"(d[0]), "+f"(d[1]), "+f"(d[2]), "+f"(d[3])
        : "r"(a[0]), "r"(a[1]), "r"(a[2]), "r"(a[3]), "r"(b[0]), "r"(b[1]));
}
__device__ __forceinline__ void cp16(uint32_t dst, const void* src) {
    asm volatile("cp.async.cg.shared.global [%0], [%1], 16;"
                 :: "r"(dst), "l"(src));
}
#define CP_COMMIT() asm volatile("cp.async.commit_group;" ::: "memory")
#define CP_WAIT(n)  asm volatile("cp.async.wait_group %0;" :: "n"(n) : "memory")

// split a float2 into fp16 hi pair + fp16 lo (residual) pair
__device__ __forceinline__ void split2h(float x, float y,
                                        uint32_t& hi, uint32_t& lo) {
    __half2 h = __floats2half2_rn(x, y);
    float2 hf = __half22float2(h);
    __half2 l = __floats2half2_rn(x - hf.x, y - hf.y);
    hi = *(uint32_t*)&h;
    lo = *(uint32_t*)&l;
}

// ---------------------------------------------------------------------------
// Conversions: x -> fp16 hi/lo split ; all 4 W -> fp16 (one launch)
// ---------------------------------------------------------------------------
__global__ void split_f16(const float* __restrict__ src,
                          __half* __restrict__ hi, __half* __restrict__ lo,
                          int n4)
{
    int i = blockIdx.x * blockDim.x + threadIdx.x;
    if (i >= n4) return;
    float4 v = ((const float4*)src)[i];
    uint32_t h0, l0, h1, l1;
    split2h(v.x, v.y, h0, l0);
    split2h(v.z, v.w, h1, l1);
    ((uint32_t*)hi)[2 * i + 0] = h0;
    ((uint32_t*)hi)[2 * i + 1] = h1;
    ((uint32_t*)lo)[2 * i + 0] = l0;
    ((uint32_t*)lo)[2 * i + 1] = l1;
}
#define W4_ (C_ * C_ / 4)   // 262144 float4 chunks per weight
__global__ void conv_w4(const float* __restrict__ Wq, const float* __restrict__ Wk,
                        const float* __restrict__ Wv, const float* __restrict__ Wo,
                        __half* __restrict__ dst)
{
    int i = blockIdx.x * blockDim.x + threadIdx.x;   // 0 .. 4*W4_-1
    int wi = i >> 18;                                // /W4_
    int j  = i & (W4_ - 1);
    const float* src = (wi == 0) ? Wq : (wi == 1) ? Wk : (wi == 2) ? Wv : Wo;
    float4 v = ((const float4*)src)[j];
    __half2 a = __floats2half2_rn(v.x, v.y);
    __half2 b = __floats2half2_rn(v.z, v.w);
    ((uint32_t*)dst)[2 * i + 0] = *(uint32_t*)&a;
    ((uint32_t*)dst)[2 * i + 1] = *(uint32_t*)&b;
}

// ---------------------------------------------------------------------------
// HMMA GEMM: out[m,n] = sum_k A[m,k]*W[n,k].
// SPLIT=true:  A = Ah + Al (2 MMA products).  SPLIT=false: A = Ah (1 product).
// CTA 128x128, BK=64, 256 threads (8 warps 64x32), 3-stage cp.async pipeline,
// 128B rows + XOR swizzle.
// MODE 0: fp32 row-major out (Wo projection), grid (8, 64).
// MODE 1: merged QKV, grid (24, 64): wi = blockIdx.x>>3 picks W and dest.
//         wi==0 -> Q split hi/lo * 0.125 ; wi==1 -> K ; wi==2 -> V.
// ---------------------------------------------------------------------------
#define BM 128
#define BN 128
#define BK 64
#define GT_B 16384               // 128 rows x 128 bytes

template<int MODE, bool SPLIT>
__global__ void __launch_bounds__(256, SPLIT ? 1 : 2) gemm_f16(
    const __half* __restrict__ Ah, const __half* __restrict__ Al,
    const __half* __restrict__ Wbase,
    float* __restrict__ out,
    __half* __restrict__ qh, __half* __restrict__ ql,
    __half* __restrict__ kh, __half* __restrict__ vh)
{
    constexpr int NTILE = SPLIT ? 3 : 2;         // Ah, [Al], W
    constexpr uint32_t GSTAGE = NTILE * GT_B;
    constexpr int WSLOT = SPLIT ? 2 : 1;         // W tile index within stage

    extern __shared__ char smc[];
    const uint32_t smb = smem_u32(smc);
    const int tid = threadIdx.x;
    const int wid = tid >> 5;
    const int lane = tid & 31;
    const int bm = blockIdx.y * BM;

    int wi, bn;
    if (MODE == 1) { wi = blockIdx.x >> 3; bn = (blockIdx.x & 7) * BN; }
    else           { wi = 0;               bn = blockIdx.x * BN; }
    const __half* Bh = Wbase + (size_t)wi * C_ * C_;

    const int wm = (wid & 1) * 64;
    const int wn = (wid >> 1) * 32;

    // gmem->smem mapping: 1024 16B chunks per tile; 4 per thread
    const int ldrow = tid >> 3;
    const int ldc16 = tid & 7;
    const uint32_t st_off = (uint32_t)ldrow * 128
                          + (((uint32_t)ldc16 * 16) ^ ((ldrow & 7) << 4));

    auto load_stage = [&](int ch, int s) {
        uint32_t dst = smb + (uint32_t)s * GSTAGE;
        #pragma unroll
        for (int u = 0; u < 4; u++) {
            int row = ldrow + u * 32;
            uint32_t so = st_off + (uint32_t)u * 32 * 128;
            size_t gA = (size_t)(bm + row) * C_ + ch * BK + ldc16 * 8;
            size_t gB = (size_t)(bn + row) * C_ + ch * BK + ldc16 * 8;
            cp16(dst + 0 * GT_B + so, &Ah[gA]);
            if (SPLIT) cp16(dst + 1 * GT_B + so, &Al[gA]);
            cp16(dst + WSLOT * GT_B + so, &Bh[gB]);
        }
    };

    // fragment lane addressing (base + per-ks XOR)
    uint32_t a_base[4], a_swz[4];
    #pragma unroll
    for (int mi = 0; mi < 4; mi++) {
        int r = wm + mi * 16 + (lane & 15);
        a_base[mi] = (uint32_t)r * 128;
        a_swz[mi] = (uint32_t)(r & 7) << 4;
    }
    const uint32_t a_lp = (uint32_t)(lane >> 4) * 16;
    uint32_t b_base[4], b_swz[4];
    #pragma unroll
    for (int ni = 0; ni < 4; ni++) {
        int r = wn + ni * 8 + (lane & 7);
        b_base[ni] = (uint32_t)r * 128;
        b_swz[ni] = (uint32_t)(r & 7) << 4;
    }
    const uint32_t b_lp = (uint32_t)(lane >> 3) * 16;

    float acc[4][4][4];
    #pragma unroll
    for (int mi = 0; mi < 4; mi++)
        #pragma unroll
        for (int ni = 0; ni < 4; ni++)
            #pragma unroll
            for (int r = 0; r < 4; r++) acc[mi][ni][r] = 0.f;

    const int nchunk = C_ / BK;             // 16
    load_stage(0, 0); CP_COMMIT();
    load_stage(1, 1); CP_COMMIT();

    int sbuf = 0;
    for (int ch = 0; ch < nchunk; ch++) {
        CP_WAIT(1);
        __syncthreads();
        if (ch + 2 < nchunk) {
            int s = sbuf + 2; if (s >= 3) s -= 3;
            load_stage(ch + 2, s);
            CP_COMMIT();
        }
        const uint32_t sA_hi = smb + (uint32_t)sbuf * GSTAGE + 0 * GT_B;
        const uint32_t sA_lo = smb + (uint32_t)sbuf * GSTAGE + 1 * GT_B;
        const uint32_t sB    = smb + (uint32_t)sbuf * GSTAGE + WSLOT * GT_B;

        #pragma unroll
        for (int kp = 0; kp < 2; kp++) {
            uint32_t bf[4][4];
            #pragma unroll
            for (int ni = 0; ni < 4; ni++)
                ldsm_x4(bf[ni], sB + b_base[ni]
                        + ((((uint32_t)kp * 64) | b_lp) ^ b_swz[ni]));
            #pragma unroll
            for (int sub = 0; sub < 2; sub++) {
                const uint32_t kc = (uint32_t)(kp * 2 + sub) * 32;
                uint32_t ahf[4][4], alf[4][4];
                #pragma unroll
                for (int mi = 0; mi < 4; mi++) {
                    uint32_t ax = (kc | a_lp) ^ a_swz[mi];
                    ldsm_x4(ahf[mi], sA_hi + a_base[mi] + ax);
                    if (SPLIT) ldsm_x4(alf[mi], sA_lo + a_base[mi] + ax);
                }
                #pragma unroll
                for (int mi = 0; mi < 4; mi++)
                    #pragma unroll
                    for (int ni = 0; ni < 4; ni++) {
                        mma_f16(acc[mi][ni], ahf[mi], &bf[ni][sub * 2]);
                        if (SPLIT)
                            mma_f16(acc[mi][ni], alf[mi], &bf[ni][sub * 2]);
                    }
            }
        }
        if (++sbuf == 3) sbuf = 0;
    }

    // Epilogue
    const int mrow0 = bm + wm + (lane >> 2);
    const int ncol0 = wn + 2 * (lane & 3);
    #pragma unroll
    for (int mi = 0; mi < 4; mi++) {
        #pragma unroll
        for (int ni = 0; ni < 4; ni++) {
            int nl = ncol0 + ni * 8;
            #pragma unroll
            for (int half = 0; half < 2; half++) {
                int m = mrow0 + mi * 16 + half * 8;
                float vx = acc[mi][ni][half * 2];
                float vy = acc[mi][ni][half * 2 + 1];
                if (MODE == 0) {
                    int n = bn + nl;
                    *(float2*)&out[(size_t)m * C_ + n] = make_float2(vx, vy);
                } else {
                    int n = bn + nl;
                    int b = m >> 11;
                    int t = m & (T_ - 1);
                    int hh = n >> 6;
                    int d = n & (HD_ - 1);
                    size_t off = (((size_t)b * H_ + hh) * T_ + t) * HD_ + d;
                    if (wi == 0) {
                        uint32_t h2, l2;
                        split2h(vx * 0.125f, vy * 0.125f, h2, l2);
                        *(uint32_t*)&qh[off] = h2;
                        *(uint32_t*)&ql[off] = l2;
                    } else {
                        __half2 h = __floats2half2_rn(vx, vy);
                        *(uint32_t*)&((wi == 1) ? kh : vh)[off] = *(uint32_t*)&h;
                    }
                }
            }
        }
    }
}

// ---------------------------------------------------------------------------
// HMMA flash attention: causal, BQ=128, kv-tile 64, HD=64, 256 threads.
// Q pre-scaled by 1/8, split fp16 hi/lo (2-product S). K,V single fp16.
// PV single product (P rounded to fp16). Output ctx: fp16 [B,T,C].
// ---------------------------------------------------------------------------
#define FQ_HI 0
#define FQ_LO 16384
#define FSTG(s) (32768 + (s) * 16384)
#define F_K 0
#define F_V 8192
#define FSMEM 65536

__global__ void __launch_bounds__(256, 1) flash_hmma(
    const __half* __restrict__ Qhi, const __half* __restrict__ Qlo,
    const __half* __restrict__ Kh, const __half* __restrict__ Vh,
    __half* __restrict__ ctx_hi)
{
    extern __shared__ char sm[];
    const uint32_t smb = smem_u32(sm);
    const int tid = threadIdx.x;
    const int wid = tid >> 5;
    const int lane = tid & 31;
    const int qb = (int)gridDim.x - 1 - (int)blockIdx.x;   // heavy tiles first
    const int bh = blockIdx.y;
    const size_t base = (size_t)bh * T_ * HD_;
    const int q0 = qb * 128;
    const int nkv = 2 * qb + 2;

    #pragma unroll
    for (int u = 0; u < 4; u++) {
        int c = tid + u * 256;
        int row = c >> 3;
        int c16 = c & 7;
        uint32_t d = (uint32_t)row * 128 + (((uint32_t)c16 * 16) ^ ((row & 7) << 4));
        size_t g = base + (size_t)(q0 + row) * HD_ + c16 * 8;
        cp16(smb + FQ_HI + d, &Qhi[g]);
        cp16(smb + FQ_LO + d, &Qlo[g]);
    }
    CP_COMMIT();

    auto load_kv = [&](int kt, int s) {
        uint32_t dst = smb + FSTG(s);
        const int k0 = kt * 64;
        #pragma unroll
        for (int u = 0; u < 2; u++) {
            int c = tid + u * 256;
            int row = c >> 3;
            int c16 = c & 7;
            uint32_t d = (uint32_t)row * 128
                       + (((uint32_t)c16 * 16) ^ ((row & 7) << 4));
            size_t g = base + (size_t)(k0 + row) * HD_ + c16 * 8;
            cp16(dst + F_K + d, &Kh[g]);
            cp16(dst + F_V + d, &Vh[g]);
        }
        CP_COMMIT();
    };
    load_kv(0, 0);
    load_kv(1, 1);

    CP_WAIT(2);
    __syncthreads();
    uint32_t qh[4][4], ql[4][4];
    {
        const int arow = wid * 16 + (lane & 7) + ((lane >> 3) & 1) * 8;
        const uint32_t asw = (uint32_t)(arow & 7) << 4;
        #pragma unroll
        for (int ks = 0; ks < 4; ks++) {
            uint32_t colb = (uint32_t)ks * 32 + (uint32_t)(lane >> 4) * 16;
            uint32_t ad = (uint32_t)arow * 128 + (colb ^ asw);
            ldsm_x4(qh[ks], smb + FQ_HI + ad);
            ldsm_x4(ql[ks], smb + FQ_LO + ad);
        }
    }

    float oacc[8][4];
    #pragma unroll
    for (int nt = 0; nt < 8; nt++)
        #pragma unroll
        for (int r = 0; r < 4; r++) oacc[nt][r] = 0.f;
    float mrow[2] = {-1e30f, -1e30f};
    float lrow[2] = {0.f, 0.f};

    const int krow = (lane & 7) + (lane >> 4) * 8;
    const uint32_t kcol = (uint32_t)((lane >> 3) & 1) * 16;
    const int vrow = (lane & 7) + ((lane >> 3) & 1) * 8;
    const uint32_t vcol = (uint32_t)(lane >> 4) * 16;

    for (int kb = 0; kb < nkv; kb++) {
        const uint32_t stg = smb + FSTG(kb & 1);
        CP_WAIT(1);
        __syncthreads();

        float sc[8][4];
        #pragma unroll
        for (int nt = 0; nt < 8; nt++)
            #pragma unroll
            for (int r = 0; r < 4; r++) sc[nt][r] = 0.f;

        #pragma unroll
        for (int ks = 0; ks < 4; ks++) {
            uint32_t kf[4][4];
            #pragma unroll
            for (int nt2 = 0; nt2 < 4; nt2++) {
                int row = nt2 * 16 + krow;
                uint32_t colb = (uint32_t)ks * 32 + kcol;
                uint32_t ad = (uint32_t)row * 128 + (colb ^ ((row & 7) << 4));
                ldsm_x4(kf[nt2], stg + F_K + ad);
            }
            #pragma unroll
            for (int nt = 0; nt < 8; nt++) {
                const uint32_t* bb = &kf[nt >> 1][(nt & 1) * 2];
                mma_f16(sc[nt], qh[ks], bb);
                mma_f16(sc[nt], ql[ks], bb);
            }
        }

        if (kb >= nkv - 2) {
            int grow0 = q0 + wid * 16 + (lane >> 2);
            int gcol0 = kb * 64 + 2 * (lane & 3);
            #pragma unroll
            for (int nt = 0; nt < 8; nt++)
                #pragma unroll
                for (int e = 0; e < 4; e++) {
                    int col = gcol0 + nt * 8 + (e & 1);
                    int row = grow0 + (e >> 1) * 8;
                    if (col > row) sc[nt][e] = -1e30f;
                }
        }

        float mx0 = -1e30f, mx1 = -1e30f;
        #pragma unroll
        for (int nt = 0; nt < 8; nt++) {
            mx0 = fmaxf(mx0, fmaxf(sc[nt][0], sc[nt][1]));
            mx1 = fmaxf(mx1, fmaxf(sc[nt][2], sc[nt][3]));
        }
        mx0 = fmaxf(mx0, __shfl_xor_sync(0xffffffffu, mx0, 1));
        mx0 = fmaxf(mx0, __shfl_xor_sync(0xffffffffu, mx0, 2));
        mx1 = fmaxf(mx1, __shfl_xor_sync(0xffffffffu, mx1, 1));
        mx1 = fmaxf(mx1, __shfl_xor_sync(0xffffffffu, mx1, 2));
        float mn0 = fmaxf(mrow[0], mx0);
        float mn1 = fmaxf(mrow[1], mx1);
        float cs0 = __expf(mrow[0] - mn0);
        float cs1 = __expf(mrow[1] - mn1);
        mrow[0] = mn0; mrow[1] = mn1;

        float sum0 = 0.f, sum1 = 0.f;
        #pragma unroll
        for (int nt = 0; nt < 8; nt++) {
            sc[nt][0] = __expf(sc[nt][0] - mn0); sum0 += sc[nt][0];
            sc[nt][1] = __expf(sc[nt][1] - mn0); sum0 += sc[nt][1];
            sc[nt][2] = __expf(sc[nt][2] - mn1); sum1 += sc[nt][2];
            sc[nt][3] = __expf(sc[nt][3] - mn1); sum1 += sc[nt][3];
        }
        sum0 += __shfl_xor_sync(0xffffffffu, sum0, 1);
        sum0 += __shfl_xor_sync(0xffffffffu, sum0, 2);
        sum1 += __shfl_xor_sync(0xffffffffu, sum1, 1);
        sum1 += __shfl_xor_sync(0xffffffffu, sum1, 2);
        lrow[0] = lrow[0] * cs0 + sum0;
        lrow[1] = lrow[1] * cs1 + sum1;
        #pragma unroll
        for (int nt = 0; nt < 8; nt++) {
            oacc[nt][0] *= cs0; oacc[nt][1] *= cs0;
            oacc[nt][2] *= cs1; oacc[nt][3] *= cs1;
        }

        // ---------- O += P V (single product; P rounded to fp16) ----------
        #pragma unroll
        for (int ks = 0; ks < 4; ks++) {
            uint32_t ph[4];
            {
                __half2 t0 = __floats2half2_rn(sc[2 * ks][0],     sc[2 * ks][1]);
                __half2 t1 = __floats2half2_rn(sc[2 * ks][2],     sc[2 * ks][3]);
                __half2 t2 = __floats2half2_rn(sc[2 * ks + 1][0], sc[2 * ks + 1][1]);
                __half2 t3 = __floats2half2_rn(sc[2 * ks + 1][2], sc[2 * ks + 1][3]);
                ph[0] = *(uint32_t*)&t0; ph[1] = *(uint32_t*)&t1;
                ph[2] = *(uint32_t*)&t2; ph[3] = *(uint32_t*)&t3;
            }
            #pragma unroll
            for (int nt2 = 0; nt2 < 4; nt2++) {
                int row = ks * 16 + vrow;
                uint32_t colb = (uint32_t)nt2 * 32 + vcol;
                uint32_t ad = (uint32_t)row * 128 + (colb ^ ((row & 7) << 4));
                uint32_t vf[4];
                ldsm_x4_t(vf, stg + F_V + ad);
                mma_f16(oacc[2 * nt2],     ph, &vf[0]);
                mma_f16(oacc[2 * nt2 + 1], ph, &vf[2]);
            }
        }

        __syncthreads();
        if (kb + 2 < nkv) load_kv(kb + 2, kb & 1);
    }

    // ---------- normalize + store ctx as fp16 ----------
    float inv0 = 1.f / lrow[0];
    float inv1 = 1.f / lrow[1];
    const int b = bh >> 4;
    const int hh = bh & 15;
    #pragma unroll
    for (int h = 0; h < 2; h++) {
        float inv = h ? inv1 : inv0;
        int t = q0 + wid * 16 + (lane >> 2) + h * 8;
        #pragma unroll
        for (int nt = 0; nt < 8; nt++) {
            int col = hh * 64 + nt * 8 + 2 * (lane & 3);
            size_t off = ((size_t)b * T_ + t) * C_ + col;
            __half2 hv = __floats2half2_rn(oacc[nt][2 * h] * inv,
                                           oacc[nt][2 * h + 1] * inv);
            *(uint32_t*)&ctx_hi[off] = *(uint32_t*)&hv;
        }
    }
}

// ---------------------------------------------------------------------------
// kernel_launch
// ---------------------------------------------------------------------------
extern "C" void kernel_launch(void* const* d_in, const int* in_sizes, int n_in,
                              void* d_out, int out_size)
{
    const float* x  = (const float*)d_in[0];
    const float* Wq = (const float*)d_in[1];
    const float* Wk = (const float*)d_in[2];
    const float* Wv = (const float*)d_in[3];
    const float* Wo = (const float*)d_in[4];
    float* out = (float*)d_out;

    __half *xh, *xl, *wh, *qh, *ql, *kh, *vh, *ch;
    cudaGetSymbolAddress((void**)&xh, g_Xh);
    cudaGetSymbolAddress((void**)&xl, g_Xl);
    cudaGetSymbolAddress((void**)&wh, g_Wh);
    cudaGetSymbolAddress((void**)&qh, g_Qh);
    cudaGetSymbolAddress((void**)&ql, g_Ql);
    cudaGetSymbolAddress((void**)&kh, g_Kh);
    cudaGetSymbolAddress((void**)&vh, g_Vh);
    cudaGetSymbolAddress((void**)&ch, g_CTXh);

    cudaFuncSetAttribute(gemm_f16<1, true>,
                         cudaFuncAttributeMaxDynamicSharedMemorySize,
                         3 * 3 * GT_B);
    cudaFuncSetAttribute(gemm_f16<0, false>,
                         cudaFuncAttributeMaxDynamicSharedMemorySize,
                         3 * 2 * GT_B);
    cudaFuncSetAttribute(flash_hmma,
                         cudaFuncAttributeMaxDynamicSharedMemorySize, FSMEM);

    // Conversions: 2 launches total
    {
        int n4 = M_ * C_ / 4;
        split_f16<<<n4 / 256, 256>>>(x, xh, xl, n4);
        conv_w4<<<4 * W4_ / 256, 256>>>(Wq, Wk, Wv, Wo, wh);
    }

    // Merged QKV projection (grid 24 x 64), split-A 2-product
    gemm_f16<1, true><<<dim3(24, M_ / BM), 256, 3 * 3 * GT_B>>>(
        xh, xl, wh, nullptr, qh, ql, kh, vh);

    // Causal flash attention
    flash_hmma<<<dim3(T_ / 128, B_ * H_), 256, FSMEM>>>(
        qh, ql, kh, vh, ch);

    // Output projection (fp32 out), single-product, 2 CTAs/SM
    gemm_f16<0, false><<<dim3(8, M_ / BM), 256, 3 * 2 * GT_B>>>(
        ch, nullptr, wh + 3 * (size_t)C_ * C_, out,
        nullptr, nullptr, nullptr, nullptr);
}

// round 8
// speedup vs baseline: 6.7993x; 1.0042x over previous
#include <cuda_runtime.h>
#include <cuda_fp16.h>
#include <cstdint>
#include <math.h>

// Problem constants
#define B_  4
#define T_  2048
#define C_  1024
#define H_  16
#define HD_ 64
#define M_  (B_ * T_)   // 8192

// ---------------------------------------------------------------------------
// Scratch (__device__ globals, allocation-free rule)
// ---------------------------------------------------------------------------
__device__ __half g_Xh[(size_t)M_ * C_];
__device__ __half g_Xl[(size_t)M_ * C_];
__device__ __half g_Wh[4][(size_t)C_ * C_];
__device__ __half g_Qh[(size_t)M_ * C_];   // [B,H,T,HD], pre-scaled 1/8
__device__ __half g_Ql[(size_t)M_ * C_];
__device__ __half g_Kh[(size_t)M_ * C_];   // [B,H,T,HD]
__device__ __half g_Vh[(size_t)M_ * C_];
__device__ __half g_CTXh[(size_t)M_ * C_]; // [B,T,C]

// ---------------------------------------------------------------------------
// PTX helpers
// ---------------------------------------------------------------------------
__device__ __forceinline__ uint32_t smem_u32(const void* p) {
    uint32_t a;
    asm("{ .reg .u64 t; cvta.to.shared.u64 t, %1; cvt.u32.u64 %0, t; }"
        : "=r"(a) : "l"(p));
    return a;
}
__device__ __forceinline__ void ldsm_x4(uint32_t* r, uint32_t addr) {
    asm volatile("ldmatrix.sync.aligned.m8n8.x4.shared.b16 {%0,%1,%2,%3}, [%4];"
        : "=r"(r[0]), "=r"(r[1]), "=r"(r[2]), "=r"(r[3]) : "r"(addr));
}
__device__ __forceinline__ void ldsm_x4_t(uint32_t* r, uint32_t addr) {
    asm volatile("ldmatrix.sync.aligned.m8n8.x4.trans.shared.b16 {%0,%1,%2,%3}, [%4];"
        : "=r"(r[0]), "=r"(r[1]), "=r"(r[2]), "=r"(r[3]) : "r"(addr));
}
__device__ __forceinline__ void mma_f16(float* d, const uint32_t* a,
                                        const uint32_t* b) {
    asm volatile(
        "mma.sync.aligned.m16n8k16.row.col.f32.f16.f16.f32 "
        "{%0,%1,%2,%3}, {%4,%5,%6,%7}, {%8,%9}, {%0,%1,%2,%3};"
        : "+f"(d[0]), "+f"(d[1]), "+f"(d[2]), "+f"(d[3])
        : "r"(a[0]), "r"(a[1]), "r"(a[2]), "r"(a[3]), "r"(b[0]), "r"(b[1]));
}
__device__ __forceinline__ void cp16(uint32_t dst, const void* src) {
    asm volatile("cp.async.cg.shared.global [%0], [%1], 16;"
                 :: "r"(dst), "l"(src));
}
#define CP_COMMIT() asm volatile("cp.async.commit_group;" ::: "memory")
#define CP_WAIT(n)  asm volatile("cp.async.wait_group %0;" :: "n"(n) : "memory")

// split a float2 into fp16 hi pair + fp16 lo (residual) pair
__device__ __forceinline__ void split2h(float x, float y,
                                        uint32_t& hi, uint32_t& lo) {
    __half2 h = __floats2half2_rn(x, y);
    float2 hf = __half22float2(h);
    __half2 l = __floats2half2_rn(x - hf.x, y - hf.y);
    hi = *(uint32_t*)&h;
    lo = *(uint32_t*)&l;
}

// ---------------------------------------------------------------------------
// Conversions: x -> fp16 hi/lo split ; all 4 W -> fp16 (one launch)
// ---------------------------------------------------------------------------
__global__ void split_f16(const float* __restrict__ src,
                          __half* __restrict__ hi, __half* __restrict__ lo,
                          int n4)
{
    int i = blockIdx.x * blockDim.x + threadIdx.x;
    if (i >= n4) return;
    float4 v = ((const float4*)src)[i];
    uint32_t h0, l0, h1, l1;
    split2h(v.x, v.y, h0, l0);
    split2h(v.z, v.w, h1, l1);
    ((uint32_t*)hi)[2 * i + 0] = h0;
    ((uint32_t*)hi)[2 * i + 1] = h1;
    ((uint32_t*)lo)[2 * i + 0] = l0;
    ((uint32_t*)lo)[2 * i + 1] = l1;
}
#define W4_ (C_ * C_ / 4)   // 262144 float4 chunks per weight
__global__ void conv_w4(const float* __restrict__ Wq, const float* __restrict__ Wk,
                        const float* __restrict__ Wv, const float* __restrict__ Wo,
                        __half* __restrict__ dst)
{
    int i = blockIdx.x * blockDim.x + threadIdx.x;   // 0 .. 4*W4_-1
    int wi = i >> 18;                                // /W4_
    int j  = i & (W4_ - 1);
    const float* src = (wi == 0) ? Wq : (wi == 1) ? Wk : (wi == 2) ? Wv : Wo;
    float4 v = ((const float4*)src)[j];
    __half2 a = __floats2half2_rn(v.x, v.y);
    __half2 b = __floats2half2_rn(v.z, v.w);
    ((uint32_t*)dst)[2 * i + 0] = *(uint32_t*)&a;
    ((uint32_t*)dst)[2 * i + 1] = *(uint32_t*)&b;
}

// ---------------------------------------------------------------------------
// HMMA GEMM: out[m,n] = sum_k A[m,k]*W[n,k].
// SPLIT=true:  A = Ah + Al (2 MMA products).  SPLIT=false: A = Ah (1 product).
// CTA 128x128, BK=64, 256 threads (8 warps 64x32), 3-stage cp.async pipeline,
// 128B rows + XOR swizzle.
// MODE 0: fp32 row-major out (Wo projection), grid (8, 64).
// MODE 1: merged QKV, grid (24, 64): wi = blockIdx.x>>3 picks W and dest.
// ---------------------------------------------------------------------------
#define BM 128
#define BN 128
#define BK 64
#define GT_B 16384               // 128 rows x 128 bytes

template<int MODE, bool SPLIT>
__global__ void __launch_bounds__(256, SPLIT ? 1 : 2) gemm_f16(
    const __half* __restrict__ Ah, const __half* __restrict__ Al,
    const __half* __restrict__ Wbase,
    float* __restrict__ out,
    __half* __restrict__ qh, __half* __restrict__ ql,
    __half* __restrict__ kh, __half* __restrict__ vh)
{
    constexpr int NTILE = SPLIT ? 3 : 2;         // Ah, [Al], W
    constexpr uint32_t GSTAGE = NTILE * GT_B;
    constexpr int WSLOT = SPLIT ? 2 : 1;

    extern __shared__ char smc[];
    const uint32_t smb = smem_u32(smc);
    const int tid = threadIdx.x;
    const int wid = tid >> 5;
    const int lane = tid & 31;
    const int bm = blockIdx.y * BM;

    int wi, bn;
    if (MODE == 1) { wi = blockIdx.x >> 3; bn = (blockIdx.x & 7) * BN; }
    else           { wi = 0;               bn = blockIdx.x * BN; }
    const __half* Bh = Wbase + (size_t)wi * C_ * C_;

    const int wm = (wid & 1) * 64;
    const int wn = (wid >> 1) * 32;

    const int ldrow = tid >> 3;
    const int ldc16 = tid & 7;
    const uint32_t st_off = (uint32_t)ldrow * 128
                          + (((uint32_t)ldc16 * 16) ^ ((ldrow & 7) << 4));

    auto load_stage = [&](int ch, int s) {
        uint32_t dst = smb + (uint32_t)s * GSTAGE;
        #pragma unroll
        for (int u = 0; u < 4; u++) {
            int row = ldrow + u * 32;
            uint32_t so = st_off + (uint32_t)u * 32 * 128;
            size_t gA = (size_t)(bm + row) * C_ + ch * BK + ldc16 * 8;
            size_t gB = (size_t)(bn + row) * C_ + ch * BK + ldc16 * 8;
            cp16(dst + 0 * GT_B + so, &Ah[gA]);
            if (SPLIT) cp16(dst + 1 * GT_B + so, &Al[gA]);
            cp16(dst + WSLOT * GT_B + so, &Bh[gB]);
        }
    };

    uint32_t a_base[4], a_swz[4];
    #pragma unroll
    for (int mi = 0; mi < 4; mi++) {
        int r = wm + mi * 16 + (lane & 15);
        a_base[mi] = (uint32_t)r * 128;
        a_swz[mi] = (uint32_t)(r & 7) << 4;
    }
    const uint32_t a_lp = (uint32_t)(lane >> 4) * 16;
    uint32_t b_base[4], b_swz[4];
    #pragma unroll
    for (int ni = 0; ni < 4; ni++) {
        int r = wn + ni * 8 + (lane & 7);
        b_base[ni] = (uint32_t)r * 128;
        b_swz[ni] = (uint32_t)(r & 7) << 4;
    }
    const uint32_t b_lp = (uint32_t)(lane >> 3) * 16;

    float acc[4][4][4];
    #pragma unroll
    for (int mi = 0; mi < 4; mi++)
        #pragma unroll
        for (int ni = 0; ni < 4; ni++)
            #pragma unroll
            for (int r = 0; r < 4; r++) acc[mi][ni][r] = 0.f;

    const int nchunk = C_ / BK;             // 16
    load_stage(0, 0); CP_COMMIT();
    load_stage(1, 1); CP_COMMIT();

    int sbuf = 0;
    for (int ch = 0; ch < nchunk; ch++) {
        CP_WAIT(1);
        __syncthreads();
        if (ch + 2 < nchunk) {
            int s = sbuf + 2; if (s >= 3) s -= 3;
            load_stage(ch + 2, s);
            CP_COMMIT();
        }
        const uint32_t sA_hi = smb + (uint32_t)sbuf * GSTAGE + 0 * GT_B;
        const uint32_t sA_lo = smb + (uint32_t)sbuf * GSTAGE + 1 * GT_B;
        const uint32_t sB    = smb + (uint32_t)sbuf * GSTAGE + WSLOT * GT_B;

        #pragma unroll
        for (int kp = 0; kp < 2; kp++) {
            uint32_t bf[4][4];
            #pragma unroll
            for (int ni = 0; ni < 4; ni++)
                ldsm_x4(bf[ni], sB + b_base[ni]
                        + ((((uint32_t)kp * 64) | b_lp) ^ b_swz[ni]));
            #pragma unroll
            for (int sub = 0; sub < 2; sub++) {
                const uint32_t kc = (uint32_t)(kp * 2 + sub) * 32;
                uint32_t ahf[4][4], alf[4][4];
                #pragma unroll
                for (int mi = 0; mi < 4; mi++) {
                    uint32_t ax = (kc | a_lp) ^ a_swz[mi];
                    ldsm_x4(ahf[mi], sA_hi + a_base[mi] + ax);
                    if (SPLIT) ldsm_x4(alf[mi], sA_lo + a_base[mi] + ax);
                }
                #pragma unroll
                for (int mi = 0; mi < 4; mi++)
                    #pragma unroll
                    for (int ni = 0; ni < 4; ni++) {
                        mma_f16(acc[mi][ni], ahf[mi], &bf[ni][sub * 2]);
                        if (SPLIT)
                            mma_f16(acc[mi][ni], alf[mi], &bf[ni][sub * 2]);
                    }
            }
        }
        if (++sbuf == 3) sbuf = 0;
    }

    // Epilogue
    const int mrow0 = bm + wm + (lane >> 2);
    const int ncol0 = wn + 2 * (lane & 3);
    #pragma unroll
    for (int mi = 0; mi < 4; mi++) {
        #pragma unroll
        for (int ni = 0; ni < 4; ni++) {
            int nl = ncol0 + ni * 8;
            #pragma unroll
            for (int half = 0; half < 2; half++) {
                int m = mrow0 + mi * 16 + half * 8;
                float vx = acc[mi][ni][half * 2];
                float vy = acc[mi][ni][half * 2 + 1];
                if (MODE == 0) {
                    int n = bn + nl;
                    *(float2*)&out[(size_t)m * C_ + n] = make_float2(vx, vy);
                } else {
                    int n = bn + nl;
                    int b = m >> 11;
                    int t = m & (T_ - 1);
                    int hh = n >> 6;
                    int d = n & (HD_ - 1);
                    size_t off = (((size_t)b * H_ + hh) * T_ + t) * HD_ + d;
                    if (wi == 0) {
                        uint32_t h2, l2;
                        split2h(vx * 0.125f, vy * 0.125f, h2, l2);
                        *(uint32_t*)&qh[off] = h2;
                        *(uint32_t*)&ql[off] = l2;
                    } else {
                        __half2 h = __floats2half2_rn(vx, vy);
                        *(uint32_t*)&((wi == 1) ? kh : vh)[off] = *(uint32_t*)&h;
                    }
                }
            }
        }
    }
}

// ---------------------------------------------------------------------------
// HMMA flash attention: causal, BQ=128, kv-tile 64, HD=64, 256 threads,
// 2 CTAs/SM (Q fragments reloaded from smem per tile; 3-stage KV ring).
// Q pre-scaled by 1/8, split fp16 hi/lo (2-product S). K,V single fp16.
// PV single product (P rounded to fp16). Output ctx: fp16 [B,T,C].
// ---------------------------------------------------------------------------
#define FQ_HI 0
#define FQ_LO 16384
#define FSTG(s) (32768 + (s) * 16384)
#define F_K 0
#define F_V 8192
#define FSMEM (32768 + 3 * 16384)   // 81920

__global__ void __launch_bounds__(256, 2) flash_hmma(
    const __half* __restrict__ Qhi, const __half* __restrict__ Qlo,
    const __half* __restrict__ Kh, const __half* __restrict__ Vh,
    __half* __restrict__ ctx_hi)
{
    extern __shared__ char sm[];
    const uint32_t smb = smem_u32(sm);
    const int tid = threadIdx.x;
    const int wid = tid >> 5;
    const int lane = tid & 31;
    const int qb = (int)gridDim.x - 1 - (int)blockIdx.x;   // heavy tiles first
    const int bh = blockIdx.y;
    const size_t base = (size_t)bh * T_ * HD_;
    const int q0 = qb * 128;
    const int nkv = 2 * qb + 2;

    // ---- Q tiles (hi+lo) group
    #pragma unroll
    for (int u = 0; u < 4; u++) {
        int c = tid + u * 256;
        int row = c >> 3;
        int c16 = c & 7;
        uint32_t d = (uint32_t)row * 128 + (((uint32_t)c16 * 16) ^ ((row & 7) << 4));
        size_t g = base + (size_t)(q0 + row) * HD_ + c16 * 8;
        cp16(smb + FQ_HI + d, &Qhi[g]);
        cp16(smb + FQ_LO + d, &Qlo[g]);
    }
    CP_COMMIT();

    // ---- K/V stage loader: always commits (keeps group counting uniform)
    auto load_kv = [&](int kt) {
        if (kt < nkv) {
            uint32_t dst = smb + FSTG(kt % 3);
            const int k0 = kt * 64;
            #pragma unroll
            for (int u = 0; u < 2; u++) {
                int c = tid + u * 256;
                int row = c >> 3;
                int c16 = c & 7;
                uint32_t d = (uint32_t)row * 128
                           + (((uint32_t)c16 * 16) ^ ((row & 7) << 4));
                size_t g = base + (size_t)(k0 + row) * HD_ + c16 * 8;
                cp16(dst + F_K + d, &Kh[g]);
                cp16(dst + F_V + d, &Vh[g]);
            }
        }
        CP_COMMIT();
    };
    load_kv(0);
    load_kv(1);
    load_kv(2);

    float oacc[8][4];
    #pragma unroll
    for (int nt = 0; nt < 8; nt++)
        #pragma unroll
        for (int r = 0; r < 4; r++) oacc[nt][r] = 0.f;
    float mrow[2] = {-1e30f, -1e30f};
    float lrow[2] = {0.f, 0.f};

    // Q fragment lane addressing (reloaded per tile)
    const int arow = wid * 16 + (lane & 7) + ((lane >> 3) & 1) * 8;
    const uint32_t a_base = (uint32_t)arow * 128;
    const uint32_t a_swz = (uint32_t)(arow & 7) << 4;
    const uint32_t a_lp = (uint32_t)(lane >> 4) * 16;

    const int krow = (lane & 7) + (lane >> 4) * 8;
    const uint32_t kcol = (uint32_t)((lane >> 3) & 1) * 16;
    const int vrow = (lane & 7) + ((lane >> 3) & 1) * 8;
    const uint32_t vcol = (uint32_t)(lane >> 4) * 16;

    for (int kb = 0; kb < nkv; kb++) {
        const uint32_t stg = smb + FSTG(kb % 3);
        CP_WAIT(2);
        __syncthreads();

        // ---------- S = Q K^T (2 products; Q frags from smem) ----------
        float sc[8][4];
        #pragma unroll
        for (int nt = 0; nt < 8; nt++)
            #pragma unroll
            for (int r = 0; r < 4; r++) sc[nt][r] = 0.f;

        #pragma unroll
        for (int ks = 0; ks < 4; ks++) {
            uint32_t qhf[4], qlf[4];
            {
                uint32_t ax = (((uint32_t)ks * 32) | a_lp) ^ a_swz;
                ldsm_x4(qhf, smb + FQ_HI + a_base + ax);
                ldsm_x4(qlf, smb + FQ_LO + a_base + ax);
            }
            uint32_t kf[4][4];
            #pragma unroll
            for (int nt2 = 0; nt2 < 4; nt2++) {
                int row = nt2 * 16 + krow;
                uint32_t colb = (uint32_t)ks * 32 + kcol;
                uint32_t ad = (uint32_t)row * 128 + (colb ^ ((row & 7) << 4));
                ldsm_x4(kf[nt2], stg + F_K + ad);
            }
            #pragma unroll
            for (int nt = 0; nt < 8; nt++) {
                const uint32_t* bb = &kf[nt >> 1][(nt & 1) * 2];
                mma_f16(sc[nt], qhf, bb);
                mma_f16(sc[nt], qlf, bb);
            }
        }

        // ---------- causal mask (last two tiles only) ----------
        if (kb >= nkv - 2) {
            int grow0 = q0 + wid * 16 + (lane >> 2);
            int gcol0 = kb * 64 + 2 * (lane & 3);
            #pragma unroll
            for (int nt = 0; nt < 8; nt++)
                #pragma unroll
                for (int e = 0; e < 4; e++) {
                    int col = gcol0 + nt * 8 + (e & 1);
                    int row = grow0 + (e >> 1) * 8;
                    if (col > row) sc[nt][e] = -1e30f;
                }
        }

        // ---------- online softmax ----------
        float mx0 = -1e30f, mx1 = -1e30f;
        #pragma unroll
        for (int nt = 0; nt < 8; nt++) {
            mx0 = fmaxf(mx0, fmaxf(sc[nt][0], sc[nt][1]));
            mx1 = fmaxf(mx1, fmaxf(sc[nt][2], sc[nt][3]));
        }
        mx0 = fmaxf(mx0, __shfl_xor_sync(0xffffffffu, mx0, 1));
        mx0 = fmaxf(mx0, __shfl_xor_sync(0xffffffffu, mx0, 2));
        mx1 = fmaxf(mx1, __shfl_xor_sync(0xffffffffu, mx1, 1));
        mx1 = fmaxf(mx1, __shfl_xor_sync(0xffffffffu, mx1, 2));
        float mn0 = fmaxf(mrow[0], mx0);
        float mn1 = fmaxf(mrow[1], mx1);
        float cs0 = __expf(mrow[0] - mn0);
        float cs1 = __expf(mrow[1] - mn1);
        mrow[0] = mn0; mrow[1] = mn1;

        float sum0 = 0.f, sum1 = 0.f;
        #pragma unroll
        for (int nt = 0; nt < 8; nt++) {
            sc[nt][0] = __expf(sc[nt][0] - mn0); sum0 += sc[nt][0];
            sc[nt][1] = __expf(sc[nt][1] - mn0); sum0 += sc[nt][1];
            sc[nt][2] = __expf(sc[nt][2] - mn1); sum1 += sc[nt][2];
            sc[nt][3] = __expf(sc[nt][3] - mn1); sum1 += sc[nt][3];
        }
        sum0 += __shfl_xor_sync(0xffffffffu, sum0, 1);
        sum0 += __shfl_xor_sync(0xffffffffu, sum0, 2);
        sum1 += __shfl_xor_sync(0xffffffffu, sum1, 1);
        sum1 += __shfl_xor_sync(0xffffffffu, sum1, 2);
        lrow[0] = lrow[0] * cs0 + sum0;
        lrow[1] = lrow[1] * cs1 + sum1;
        #pragma unroll
        for (int nt = 0; nt < 8; nt++) {
            oacc[nt][0] *= cs0; oacc[nt][1] *= cs0;
            oacc[nt][2] *= cs1; oacc[nt][3] *= cs1;
        }

        // ---------- O += P V (single product; P rounded to fp16) ----------
        #pragma unroll
        for (int ks = 0; ks < 4; ks++) {
            uint32_t ph[4];
            {
                __half2 t0 = __floats2half2_rn(sc[2 * ks][0],     sc[2 * ks][1]);
                __half2 t1 = __floats2half2_rn(sc[2 * ks][2],     sc[2 * ks][3]);
                __half2 t2 = __floats2half2_rn(sc[2 * ks + 1][0], sc[2 * ks + 1][1]);
                __half2 t3 = __floats2half2_rn(sc[2 * ks + 1][2], sc[2 * ks + 1][3]);
                ph[0] = *(uint32_t*)&t0; ph[1] = *(uint32_t*)&t1;
                ph[2] = *(uint32_t*)&t2; ph[3] = *(uint32_t*)&t3;
            }
            #pragma unroll
            for (int nt2 = 0; nt2 < 4; nt2++) {
                int row = ks * 16 + vrow;
                uint32_t colb = (uint32_t)nt2 * 32 + vcol;
                uint32_t ad = (uint32_t)row * 128 + (colb ^ ((row & 7) << 4));
                uint32_t vf[4];
                ldsm_x4_t(vf, stg + F_V + ad);
                mma_f16(oacc[2 * nt2],     ph, &vf[0]);
                mma_f16(oacc[2 * nt2 + 1], ph, &vf[2]);
            }
        }

        __syncthreads();
        load_kv(kb + 3);
    }

    // ---------- normalize + store ctx as fp16 ----------
    float inv0 = 1.f / lrow[0];
    float inv1 = 1.f / lrow[1];
    const int b = bh >> 4;
    const int hh = bh & 15;
    #pragma unroll
    for (int h = 0; h < 2; h++) {
        float inv = h ? inv1 : inv0;
        int t = q0 + wid * 16 + (lane >> 2) + h * 8;
        #pragma unroll
        for (int nt = 0; nt < 8; nt++) {
            int col = hh * 64 + nt * 8 + 2 * (lane & 3);
            size_t off = ((size_t)b * T_ + t) * C_ + col;
            __half2 hv = __floats2half2_rn(oacc[nt][2 * h] * inv,
                                           oacc[nt][2 * h + 1] * inv);
            *(uint32_t*)&ctx_hi[off] = *(uint32_t*)&hv;
        }
    }
}

// ---------------------------------------------------------------------------
// kernel_launch
// ---------------------------------------------------------------------------
extern "C" void kernel_launch(void* const* d_in, const int* in_sizes, int n_in,
                              void* d_out, int out_size)
{
    const float* x  = (const float*)d_in[0];
    const float* Wq = (const float*)d_in[1];
    const float* Wk = (const float*)d_in[2];
    const float* Wv = (const float*)d_in[3];
    const float* Wo = (const float*)d_in[4];
    float* out = (float*)d_out;

    __half *xh, *xl, *wh, *qh, *ql, *kh, *vh, *ch;
    cudaGetSymbolAddress((void**)&xh, g_Xh);
    cudaGetSymbolAddress((void**)&xl, g_Xl);
    cudaGetSymbolAddress((void**)&wh, g_Wh);
    cudaGetSymbolAddress((void**)&qh, g_Qh);
    cudaGetSymbolAddress((void**)&ql, g_Ql);
    cudaGetSymbolAddress((void**)&kh, g_Kh);
    cudaGetSymbolAddress((void**)&vh, g_Vh);
    cudaGetSymbolAddress((void**)&ch, g_CTXh);

    cudaFuncSetAttribute(gemm_f16<1, true>,
                         cudaFuncAttributeMaxDynamicSharedMemorySize,
                         3 * 3 * GT_B);
    cudaFuncSetAttribute(gemm_f16<0, false>,
                         cudaFuncAttributeMaxDynamicSharedMemorySize,
                         3 * 2 * GT_B);
    cudaFuncSetAttribute(flash_hmma,
                         cudaFuncAttributeMaxDynamicSharedMemorySize, FSMEM);

    // Conversions: 2 launches total
    {
        int n4 = M_ * C_ / 4;
        split_f16<<<n4 / 256, 256>>>(x, xh, xl, n4);
        conv_w4<<<4 * W4_ / 256, 256>>>(Wq, Wk, Wv, Wo, wh);
    }

    // Merged QKV projection (grid 24 x 64), split-A 2-product
    gemm_f16<1, true><<<dim3(24, M_ / BM), 256, 3 * 3 * GT_B>>>(
        xh, xl, wh, nullptr, qh, ql, kh, vh);

    // Causal flash attention (2 CTAs/SM)
    flash_hmma<<<dim3(T_ / 128, B_ * H_), 256, FSMEM>>>(
        qh, ql, kh, vh, ch);

    // Output projection (fp32 out), single-product, 2 CTAs/SM
    gemm_f16<0, false><<<dim3(8, M_ / BM), 256, 3 * 2 * GT_B>>>(
        ch, nullptr, wh + 3 * (size_t)C_ * C_, out,
        nullptr, nullptr, nullptr, nullptr);
}

// round 9
// speedup vs baseline: 7.9431x; 1.1682x over previous
#include <cuda_runtime.h>
#include <cuda_fp16.h>
#include <cstdint>
#include <math.h>

// Problem constants
#define B_  4
#define T_  2048
#define C_  1024
#define H_  16
#define HD_ 64
#define M_  (B_ * T_)   // 8192

// ---------------------------------------------------------------------------
// Scratch (__device__ globals, allocation-free rule)
// ---------------------------------------------------------------------------
__device__ __half g_Xh[(size_t)M_ * C_];
__device__ __half g_Xl[(size_t)M_ * C_];
__device__ __half g_Wh[4][(size_t)C_ * C_];
__device__ __half g_Qh[(size_t)M_ * C_];   // [B,H,T,HD], pre-scaled 1/8
__device__ __half g_Ql[(size_t)M_ * C_];
__device__ __half g_Kh[(size_t)M_ * C_];   // [B,H,T,HD]
__device__ __half g_Vh[(size_t)M_ * C_];
__device__ __half g_CTXh[(size_t)M_ * C_]; // [B,T,C]

// ---------------------------------------------------------------------------
// PTX helpers
// ---------------------------------------------------------------------------
__device__ __forceinline__ uint32_t smem_u32(const void* p) {
    uint32_t a;
    asm("{ .reg .u64 t; cvta.to.shared.u64 t, %1; cvt.u32.u64 %0, t; }"
        : "=r"(a) : "l"(p));
    return a;
}
__device__ __forceinline__ void ldsm_x4(uint32_t* r, uint32_t addr) {
    asm volatile("ldmatrix.sync.aligned.m8n8.x4.shared.b16 {%0,%1,%2,%3}, [%4];"
        : "=r"(r[0]), "=r"(r[1]), "=r"(r[2]), "=r"(r[3]) : "r"(addr));
}
__device__ __forceinline__ void ldsm_x4_t(uint32_t* r, uint32_t addr) {
    asm volatile("ldmatrix.sync.aligned.m8n8.x4.trans.shared.b16 {%0,%1,%2,%3}, [%4];"
        : "=r"(r[0]), "=r"(r[1]), "=r"(r[2]), "=r"(r[3]) : "r"(addr));
}
__device__ __forceinline__ void mma_f16(float* d, const uint32_t* a,
                                        const uint32_t* b) {
    asm volatile(
        "mma.sync.aligned.m16n8k16.row.col.f32.f16.f16.f32 "
        "{%0,%1,%2,%3}, {%4,%5,%6,%7}, {%8,%9}, {%0,%1,%2,%3};"
        : "+f"(d[0]), "+f"(d[1]), "+f"(d[2]), "+f"(d[3])
        : "r"(a[0]), "r"(a[1]), "r"(a[2]), "r"(a[3]), "r"(b[0]), "r"(b[1]));
}
__device__ __forceinline__ void cp16(uint32_t dst, const void* src) {
    asm volatile("cp.async.cg.shared.global [%0], [%1], 16;"
                 :: "r"(dst), "l"(src));
}
#define CP_COMMIT() asm volatile("cp.async.commit_group;" ::: "memory")
#define CP_WAIT(n)  asm volatile("cp.async.wait_group %0;" :: "n"(n) : "memory")

// split a float2 into fp16 hi pair + fp16 lo (residual) pair
__device__ __forceinline__ void split2h(float x, float y,
                                        uint32_t& hi, uint32_t& lo) {
    __half2 h = __floats2half2_rn(x, y);
    float2 hf = __half22float2(h);
    __half2 l = __floats2half2_rn(x - hf.x, y - hf.y);
    hi = *(uint32_t*)&h;
    lo = *(uint32_t*)&l;
}

// ---------------------------------------------------------------------------
// Conversions: x -> fp16 hi/lo split ; all 4 W -> fp16 (one launch)
// ---------------------------------------------------------------------------
__global__ void split_f16(const float* __restrict__ src,
                          __half* __restrict__ hi, __half* __restrict__ lo,
                          int n4)
{
    int i = blockIdx.x * blockDim.x + threadIdx.x;
    if (i >= n4) return;
    float4 v = ((const float4*)src)[i];
    uint32_t h0, l0, h1, l1;
    split2h(v.x, v.y, h0, l0);
    split2h(v.z, v.w, h1, l1);
    ((uint32_t*)hi)[2 * i + 0] = h0;
    ((uint32_t*)hi)[2 * i + 1] = h1;
    ((uint32_t*)lo)[2 * i + 0] = l0;
    ((uint32_t*)lo)[2 * i + 1] = l1;
}
#define W4_ (C_ * C_ / 4)   // 262144 float4 chunks per weight
__global__ void conv_w4(const float* __restrict__ Wq, const float* __restrict__ Wk,
                        const float* __restrict__ Wv, const float* __restrict__ Wo,
                        __half* __restrict__ dst)
{
    int i = blockIdx.x * blockDim.x + threadIdx.x;   // 0 .. 4*W4_-1
    int wi = i >> 18;                                // /W4_
    int j  = i & (W4_ - 1);
    const float* src = (wi == 0) ? Wq : (wi == 1) ? Wk : (wi == 2) ? Wv : Wo;
    float4 v = ((const float4*)src)[j];
    __half2 a = __floats2half2_rn(v.x, v.y);
    __half2 b = __floats2half2_rn(v.z, v.w);
    ((uint32_t*)dst)[2 * i + 0] = *(uint32_t*)&a;
    ((uint32_t*)dst)[2 * i + 1] = *(uint32_t*)&b;
}

// ---------------------------------------------------------------------------
// HMMA GEMM: out[m,n] = sum_k A[m,k]*W[n,k].
// SPLIT=true:  A = Ah + Al (2 MMA products).  SPLIT=false: A = Ah (1 product).
// CTA 128x128, BK=64, 256 threads (8 warps 64x32), 3-stage cp.async pipeline,
// 128B rows + XOR swizzle.
// MODE 0: fp32 row-major out (Wo),      grid ( 8,64), SPLIT=false, 2 CTA/SM.
// MODE 2: merged K+V head-layout fp16,  grid (16,64), SPLIT=false, 2 CTA/SM.
//         wi = blockIdx.x>>3 selects W (Wbase + wi*C*C) and dest (kh / vh).
// MODE 3: Q head-layout fp16 hi/lo*1/8, grid ( 8,64), SPLIT=true,  1 CTA/SM.
// ---------------------------------------------------------------------------
#define BM 128
#define BN 128
#define BK 64
#define GT_B 16384               // 128 rows x 128 bytes

template<int MODE, bool SPLIT>
__global__ void __launch_bounds__(256, SPLIT ? 1 : 2) gemm_f16(
    const __half* __restrict__ Ah, const __half* __restrict__ Al,
    const __half* __restrict__ Wbase,
    float* __restrict__ out,
    __half* __restrict__ qh, __half* __restrict__ ql,
    __half* __restrict__ kh, __half* __restrict__ vh)
{
    constexpr int NTILE = SPLIT ? 3 : 2;         // Ah, [Al], W
    constexpr uint32_t GSTAGE = NTILE * GT_B;
    constexpr int WSLOT = SPLIT ? 2 : 1;

    extern __shared__ char smc[];
    const uint32_t smb = smem_u32(smc);
    const int tid = threadIdx.x;
    const int wid = tid >> 5;
    const int lane = tid & 31;
    const int bm = blockIdx.y * BM;

    int wi, bn;
    if (MODE == 2) { wi = blockIdx.x >> 3; bn = (blockIdx.x & 7) * BN; }
    else           { wi = 0;               bn = blockIdx.x * BN; }
    const __half* Bh = Wbase + (size_t)wi * C_ * C_;

    const int wm = (wid & 1) * 64;
    const int wn = (wid >> 1) * 32;

    const int ldrow = tid >> 3;
    const int ldc16 = tid & 7;
    const uint32_t st_off = (uint32_t)ldrow * 128
                          + (((uint32_t)ldc16 * 16) ^ ((ldrow & 7) << 4));

    auto load_stage = [&](int ch, int s) {
        uint32_t dst = smb + (uint32_t)s * GSTAGE;
        #pragma unroll
        for (int u = 0; u < 4; u++) {
            int row = ldrow + u * 32;
            uint32_t so = st_off + (uint32_t)u * 32 * 128;
            size_t gA = (size_t)(bm + row) * C_ + ch * BK + ldc16 * 8;
            size_t gB = (size_t)(bn + row) * C_ + ch * BK + ldc16 * 8;
            cp16(dst + 0 * GT_B + so, &Ah[gA]);
            if (SPLIT) cp16(dst + 1 * GT_B + so, &Al[gA]);
            cp16(dst + WSLOT * GT_B + so, &Bh[gB]);
        }
    };

    uint32_t a_base[4], a_swz[4];
    #pragma unroll
    for (int mi = 0; mi < 4; mi++) {
        int r = wm + mi * 16 + (lane & 15);
        a_base[mi] = (uint32_t)r * 128;
        a_swz[mi] = (uint32_t)(r & 7) << 4;
    }
    const uint32_t a_lp = (uint32_t)(lane >> 4) * 16;
    uint32_t b_base[4], b_swz[4];
    #pragma unroll
    for (int ni = 0; ni < 4; ni++) {
        int r = wn + ni * 8 + (lane & 7);
        b_base[ni] = (uint32_t)r * 128;
        b_swz[ni] = (uint32_t)(r & 7) << 4;
    }
    const uint32_t b_lp = (uint32_t)(lane >> 3) * 16;

    float acc[4][4][4];
    #pragma unroll
    for (int mi = 0; mi < 4; mi++)
        #pragma unroll
        for (int ni = 0; ni < 4; ni++)
            #pragma unroll
            for (int r = 0; r < 4; r++) acc[mi][ni][r] = 0.f;

    const int nchunk = C_ / BK;             // 16
    load_stage(0, 0); CP_COMMIT();
    load_stage(1, 1); CP_COMMIT();

    int sbuf = 0;
    for (int ch = 0; ch < nchunk; ch++) {
        CP_WAIT(1);
        __syncthreads();
        if (ch + 2 < nchunk) {
            int s = sbuf + 2; if (s >= 3) s -= 3;
            load_stage(ch + 2, s);
            CP_COMMIT();
        }
        const uint32_t sA_hi = smb + (uint32_t)sbuf * GSTAGE + 0 * GT_B;
        const uint32_t sA_lo = smb + (uint32_t)sbuf * GSTAGE + 1 * GT_B;
        const uint32_t sB    = smb + (uint32_t)sbuf * GSTAGE + WSLOT * GT_B;

        #pragma unroll
        for (int kp = 0; kp < 2; kp++) {
            uint32_t bf[4][4];
            #pragma unroll
            for (int ni = 0; ni < 4; ni++)
                ldsm_x4(bf[ni], sB + b_base[ni]
                        + ((((uint32_t)kp * 64) | b_lp) ^ b_swz[ni]));
            #pragma unroll
            for (int sub = 0; sub < 2; sub++) {
                const uint32_t kc = (uint32_t)(kp * 2 + sub) * 32;
                uint32_t ahf[4][4], alf[4][4];
                #pragma unroll
                for (int mi = 0; mi < 4; mi++) {
                    uint32_t ax = (kc | a_lp) ^ a_swz[mi];
                    ldsm_x4(ahf[mi], sA_hi + a_base[mi] + ax);
                    if (SPLIT) ldsm_x4(alf[mi], sA_lo + a_base[mi] + ax);
                }
                #pragma unroll
                for (int mi = 0; mi < 4; mi++)
                    #pragma unroll
                    for (int ni = 0; ni < 4; ni++) {
                        mma_f16(acc[mi][ni], ahf[mi], &bf[ni][sub * 2]);
                        if (SPLIT)
                            mma_f16(acc[mi][ni], alf[mi], &bf[ni][sub * 2]);
                    }
            }
        }
        if (++sbuf == 3) sbuf = 0;
    }

    // Epilogue
    const int mrow0 = bm + wm + (lane >> 2);
    const int ncol0 = wn + 2 * (lane & 3);
    #pragma unroll
    for (int mi = 0; mi < 4; mi++) {
        #pragma unroll
        for (int ni = 0; ni < 4; ni++) {
            int nl = ncol0 + ni * 8;
            #pragma unroll
            for (int half = 0; half < 2; half++) {
                int m = mrow0 + mi * 16 + half * 8;
                float vx = acc[mi][ni][half * 2];
                float vy = acc[mi][ni][half * 2 + 1];
                if (MODE == 0) {
                    int n = bn + nl;
                    *(float2*)&out[(size_t)m * C_ + n] = make_float2(vx, vy);
                } else {
                    int n = bn + nl;
                    int b = m >> 11;
                    int t = m & (T_ - 1);
                    int hh = n >> 6;
                    int d = n & (HD_ - 1);
                    size_t off = (((size_t)b * H_ + hh) * T_ + t) * HD_ + d;
                    if (MODE == 3) {
                        uint32_t h2, l2;
                        split2h(vx * 0.125f, vy * 0.125f, h2, l2);
                        *(uint32_t*)&qh[off] = h2;
                        *(uint32_t*)&ql[off] = l2;
                    } else {          // MODE 2: K or V
                        __half2 h = __floats2half2_rn(vx, vy);
                        *(uint32_t*)&((wi == 0) ? kh : vh)[off] = *(uint32_t*)&h;
                    }
                }
            }
        }
    }
}

// ---------------------------------------------------------------------------
// HMMA flash attention: causal, BQ=128, kv-tile 64, HD=64, 256 threads,
// 2 CTAs/SM (Q fragments reloaded from smem per tile; 3-stage KV ring).
// Q pre-scaled by 1/8, split fp16 hi/lo (2-product S). K,V single fp16.
// PV single product (P rounded to fp16). Output ctx: fp16 [B,T,C].
// ---------------------------------------------------------------------------
#define FQ_HI 0
#define FQ_LO 16384
#define FSTG(s) (32768 + (s) * 16384)
#define F_K 0
#define F_V 8192
#define FSMEM (32768 + 3 * 16384)   // 81920

__global__ void __launch_bounds__(256, 2) flash_hmma(
    const __half* __restrict__ Qhi, const __half* __restrict__ Qlo,
    const __half* __restrict__ Kh, const __half* __restrict__ Vh,
    __half* __restrict__ ctx_hi)
{
    extern __shared__ char sm[];
    const uint32_t smb = smem_u32(sm);
    const int tid = threadIdx.x;
    const int wid = tid >> 5;
    const int lane = tid & 31;
    const int qb = (int)gridDim.x - 1 - (int)blockIdx.x;   // heavy tiles first
    const int bh = blockIdx.y;
    const size_t base = (size_t)bh * T_ * HD_;
    const int q0 = qb * 128;
    const int nkv = 2 * qb + 2;

    #pragma unroll
    for (int u = 0; u < 4; u++) {
        int c = tid + u * 256;
        int row = c >> 3;
        int c16 = c & 7;
        uint32_t d = (uint32_t)row * 128 + (((uint32_t)c16 * 16) ^ ((row & 7) << 4));
        size_t g = base + (size_t)(q0 + row) * HD_ + c16 * 8;
        cp16(smb + FQ_HI + d, &Qhi[g]);
        cp16(smb + FQ_LO + d, &Qlo[g]);
    }
    CP_COMMIT();

    auto load_kv = [&](int kt) {
        if (kt < nkv) {
            uint32_t dst = smb + FSTG(kt % 3);
            const int k0 = kt * 64;
            #pragma unroll
            for (int u = 0; u < 2; u++) {
                int c = tid + u * 256;
                int row = c >> 3;
                int c16 = c & 7;
                uint32_t d = (uint32_t)row * 128
                           + (((uint32_t)c16 * 16) ^ ((row & 7) << 4));
                size_t g = base + (size_t)(k0 + row) * HD_ + c16 * 8;
                cp16(dst + F_K + d, &Kh[g]);
                cp16(dst + F_V + d, &Vh[g]);
            }
        }
        CP_COMMIT();
    };
    load_kv(0);
    load_kv(1);
    load_kv(2);

    float oacc[8][4];
    #pragma unroll
    for (int nt = 0; nt < 8; nt++)
        #pragma unroll
        for (int r = 0; r < 4; r++) oacc[nt][r] = 0.f;
    float mrow[2] = {-1e30f, -1e30f};
    float lrow[2] = {0.f, 0.f};

    const int arow = wid * 16 + (lane & 7) + ((lane >> 3) & 1) * 8;
    const uint32_t a_base = (uint32_t)arow * 128;
    const uint32_t a_swz = (uint32_t)(arow & 7) << 4;
    const uint32_t a_lp = (uint32_t)(lane >> 4) * 16;

    const int krow = (lane & 7) + (lane >> 4) * 8;
    const uint32_t kcol = (uint32_t)((lane >> 3) & 1) * 16;
    const int vrow = (lane & 7) + ((lane >> 3) & 1) * 8;
    const uint32_t vcol = (uint32_t)(lane >> 4) * 16;

    for (int kb = 0; kb < nkv; kb++) {
        const uint32_t stg = smb + FSTG(kb % 3);
        CP_WAIT(2);
        __syncthreads();

        // ---------- S = Q K^T (2 products; Q frags from smem) ----------
        float sc[8][4];
        #pragma unroll
        for (int nt = 0; nt < 8; nt++)
            #pragma unroll
            for (int r = 0; r < 4; r++) sc[nt][r] = 0.f;

        #pragma unroll
        for (int ks = 0; ks < 4; ks++) {
            uint32_t qhf[4], qlf[4];
            {
                uint32_t ax = (((uint32_t)ks * 32) | a_lp) ^ a_swz;
                ldsm_x4(qhf, smb + FQ_HI + a_base + ax);
                ldsm_x4(qlf, smb + FQ_LO + a_base + ax);
            }
            uint32_t kf[4][4];
            #pragma unroll
            for (int nt2 = 0; nt2 < 4; nt2++) {
                int row = nt2 * 16 + krow;
                uint32_t colb = (uint32_t)ks * 32 + kcol;
                uint32_t ad = (uint32_t)row * 128 + (colb ^ ((row & 7) << 4));
                ldsm_x4(kf[nt2], stg + F_K + ad);
            }
            #pragma unroll
            for (int nt = 0; nt < 8; nt++) {
                const uint32_t* bb = &kf[nt >> 1][(nt & 1) * 2];
                mma_f16(sc[nt], qhf, bb);
                mma_f16(sc[nt], qlf, bb);
            }
        }

        // ---------- causal mask (last two tiles only) ----------
        if (kb >= nkv - 2) {
            int grow0 = q0 + wid * 16 + (lane >> 2);
            int gcol0 = kb * 64 + 2 * (lane & 3);
            #pragma unroll
            for (int nt = 0; nt < 8; nt++)
                #pragma unroll
                for (int e = 0; e < 4; e++) {
                    int col = gcol0 + nt * 8 + (e & 1);
                    int row = grow0 + (e >> 1) * 8;
                    if (col > row) sc[nt][e] = -1e30f;
                }
        }

        // ---------- online softmax ----------
        float mx0 = -1e30f, mx1 = -1e30f;
        #pragma unroll
        for (int nt = 0; nt < 8; nt++) {
            mx0 = fmaxf(mx0, fmaxf(sc[nt][0], sc[nt][1]));
            mx1 = fmaxf(mx1, fmaxf(sc[nt][2], sc[nt][3]));
        }
        mx0 = fmaxf(mx0, __shfl_xor_sync(0xffffffffu, mx0, 1));
        mx0 = fmaxf(mx0, __shfl_xor_sync(0xffffffffu, mx0, 2));
        mx1 = fmaxf(mx1, __shfl_xor_sync(0xffffffffu, mx1, 1));
        mx1 = fmaxf(mx1, __shfl_xor_sync(0xffffffffu, mx1, 2));
        float mn0 = fmaxf(mrow[0], mx0);
        float mn1 = fmaxf(mrow[1], mx1);
        float cs0 = __expf(mrow[0] - mn0);
        float cs1 = __expf(mrow[1] - mn1);
        mrow[0] = mn0; mrow[1] = mn1;

        float sum0 = 0.f, sum1 = 0.f;
        #pragma unroll
        for (int nt = 0; nt < 8; nt++) {
            sc[nt][0] = __expf(sc[nt][0] - mn0); sum0 += sc[nt][0];
            sc[nt][1] = __expf(sc[nt][1] - mn0); sum0 += sc[nt][1];
            sc[nt][2] = __expf(sc[nt][2] - mn1); sum1 += sc[nt][2];
            sc[nt][3] = __expf(sc[nt][3] - mn1); sum1 += sc[nt][3];
        }
        sum0 += __shfl_xor_sync(0xffffffffu, sum0, 1);
        sum0 += __shfl_xor_sync(0xffffffffu, sum0, 2);
        sum1 += __shfl_xor_sync(0xffffffffu, sum1, 1);
        sum1 += __shfl_xor_sync(0xffffffffu, sum1, 2);
        lrow[0] = lrow[0] * cs0 + sum0;
        lrow[1] = lrow[1] * cs1 + sum1;
        #pragma unroll
        for (int nt = 0; nt < 8; nt++) {
            oacc[nt][0] *= cs0; oacc[nt][1] *= cs0;
            oacc[nt][2] *= cs1; oacc[nt][3] *= cs1;
        }

        // ---------- O += P V (single product; P rounded to fp16) ----------
        #pragma unroll
        for (int ks = 0; ks < 4; ks++) {
            uint32_t ph[4];
            {
                __half2 t0 = __floats2half2_rn(sc[2 * ks][0],     sc[2 * ks][1]);
                __half2 t1 = __floats2half2_rn(sc[2 * ks][2],     sc[2 * ks][3]);
                __half2 t2 = __floats2half2_rn(sc[2 * ks + 1][0], sc[2 * ks + 1][1]);
                __half2 t3 = __floats2half2_rn(sc[2 * ks + 1][2], sc[2 * ks + 1][3]);
                ph[0] = *(uint32_t*)&t0; ph[1] = *(uint32_t*)&t1;
                ph[2] = *(uint32_t*)&t2; ph[3] = *(uint32_t*)&t3;
            }
            #pragma unroll
            for (int nt2 = 0; nt2 < 4; nt2++) {
                int row = ks * 16 + vrow;
                uint32_t colb = (uint32_t)nt2 * 32 + vcol;
                uint32_t ad = (uint32_t)row * 128 + (colb ^ ((row & 7) << 4));
                uint32_t vf[4];
                ldsm_x4_t(vf, stg + F_V + ad);
                mma_f16(oacc[2 * nt2],     ph, &vf[0]);
                mma_f16(oacc[2 * nt2 + 1], ph, &vf[2]);
            }
        }

        __syncthreads();
        load_kv(kb + 3);
    }

    // ---------- normalize + store ctx as fp16 ----------
    float inv0 = 1.f / lrow[0];
    float inv1 = 1.f / lrow[1];
    const int b = bh >> 4;
    const int hh = bh & 15;
    #pragma unroll
    for (int h = 0; h < 2; h++) {
        float inv = h ? inv1 : inv0;
        int t = q0 + wid * 16 + (lane >> 2) + h * 8;
        #pragma unroll
        for (int nt = 0; nt < 8; nt++) {
            int col = hh * 64 + nt * 8 + 2 * (lane & 3);
            size_t off = ((size_t)b * T_ + t) * C_ + col;
            __half2 hv = __floats2half2_rn(oacc[nt][2 * h] * inv,
                                           oacc[nt][2 * h + 1] * inv);
            *(uint32_t*)&ctx_hi[off] = *(uint32_t*)&hv;
        }
    }
}

// ---------------------------------------------------------------------------
// kernel_launch
// ---------------------------------------------------------------------------
extern "C" void kernel_launch(void* const* d_in, const int* in_sizes, int n_in,
                              void* d_out, int out_size)
{
    const float* x  = (const float*)d_in[0];
    const float* Wq = (const float*)d_in[1];
    const float* Wk = (const float*)d_in[2];
    const float* Wv = (const float*)d_in[3];
    const float* Wo = (const float*)d_in[4];
    float* out = (float*)d_out;

    __half *xh, *xl, *wh, *qh, *ql, *kh, *vh, *ch;
    cudaGetSymbolAddress((void**)&xh, g_Xh);
    cudaGetSymbolAddress((void**)&xl, g_Xl);
    cudaGetSymbolAddress((void**)&wh, g_Wh);
    cudaGetSymbolAddress((void**)&qh, g_Qh);
    cudaGetSymbolAddress((void**)&ql, g_Ql);
    cudaGetSymbolAddress((void**)&kh, g_Kh);
    cudaGetSymbolAddress((void**)&vh, g_Vh);
    cudaGetSymbolAddress((void**)&ch, g_CTXh);

    cudaFuncSetAttribute(gemm_f16<3, true>,
                         cudaFuncAttributeMaxDynamicSharedMemorySize,
                         3 * 3 * GT_B);
    cudaFuncSetAttribute(gemm_f16<2, false>,
                         cudaFuncAttributeMaxDynamicSharedMemorySize,
                         3 * 2 * GT_B);
    cudaFuncSetAttribute(gemm_f16<0, false>,
                         cudaFuncAttributeMaxDynamicSharedMemorySize,
                         3 * 2 * GT_B);
    cudaFuncSetAttribute(flash_hmma,
                         cudaFuncAttributeMaxDynamicSharedMemorySize, FSMEM);

    // Conversions: 2 launches total
    {
        int n4 = M_ * C_ / 4;
        split_f16<<<n4 / 256, 256>>>(x, xh, xl, n4);
        conv_w4<<<4 * W4_ / 256, 256>>>(Wq, Wk, Wv, Wo, wh);
    }

    // Q projection: split-A 2-product (scores are error-sensitive)
    gemm_f16<3, true><<<dim3(8, M_ / BM), 256, 3 * 3 * GT_B>>>(
        xh, xl, wh + 0 * (size_t)C_ * C_, nullptr, qh, ql, nullptr, nullptr);

    // K+V merged projection: single product, 2 CTAs/SM
    gemm_f16<2, false><<<dim3(16, M_ / BM), 256, 3 * 2 * GT_B>>>(
        xh, nullptr, wh + 1 * (size_t)C_ * C_, nullptr,
        nullptr, nullptr, kh, vh);

    // Causal flash attention (2 CTAs/SM)
    flash_hmma<<<dim3(T_ / 128, B_ * H_), 256, FSMEM>>>(
        qh, ql, kh, vh, ch);

    // Output projection (fp32 out), single-product, 2 CTAs/SM
    gemm_f16<0, false><<<dim3(8, M_ / BM), 256, 3 * 2 * GT_B>>>(
        ch, nullptr, wh + 3 * (size_t)C_ * C_, out,
        nullptr, nullptr, nullptr, nullptr);
}

// round 10
// speedup vs baseline: 8.0571x; 1.0143x over previous
#include <cuda_runtime.h>
#include <cuda_fp16.h>
#include <cstdint>
#include <math.h>

// Problem constants
#define B_  4
#define T_  2048
#define C_  1024
#define H_  16
#define HD_ 64
#define M_  (B_ * T_)   // 8192

// Q prescale: (1/sqrt(64)) * log2(e)  -> scores arrive in log2 domain
#define QSCALE 0.1803368801111204f

// ---------------------------------------------------------------------------
// Scratch (__device__ globals, allocation-free rule)
// ---------------------------------------------------------------------------
__device__ __half g_Xh[(size_t)M_ * C_];
__device__ __half g_Xl[(size_t)M_ * C_];
__device__ __half g_Wh[4][(size_t)C_ * C_];
__device__ __half g_Qh[(size_t)M_ * C_];   // [B,H,T,HD], pre-scaled QSCALE
__device__ __half g_Ql[(size_t)M_ * C_];
__device__ __half g_Kh[(size_t)M_ * C_];   // [B,H,T,HD]
__device__ __half g_Vh[(size_t)M_ * C_];
__device__ __half g_CTXh[(size_t)M_ * C_]; // [B,T,C]

// ---------------------------------------------------------------------------
// PTX helpers
// ---------------------------------------------------------------------------
__device__ __forceinline__ uint32_t smem_u32(const void* p) {
    uint32_t a;
    asm("{ .reg .u64 t; cvta.to.shared.u64 t, %1; cvt.u32.u64 %0, t; }"
        : "=r"(a) : "l"(p));
    return a;
}
__device__ __forceinline__ void ldsm_x4(uint32_t* r, uint32_t addr) {
    asm volatile("ldmatrix.sync.aligned.m8n8.x4.shared.b16 {%0,%1,%2,%3}, [%4];"
        : "=r"(r[0]), "=r"(r[1]), "=r"(r[2]), "=r"(r[3]) : "r"(addr));
}
__device__ __forceinline__ void ldsm_x4_t(uint32_t* r, uint32_t addr) {
    asm volatile("ldmatrix.sync.aligned.m8n8.x4.trans.shared.b16 {%0,%1,%2,%3}, [%4];"
        : "=r"(r[0]), "=r"(r[1]), "=r"(r[2]), "=r"(r[3]) : "r"(addr));
}
__device__ __forceinline__ void mma_f16(float* d, const uint32_t* a,
                                        const uint32_t* b) {
    asm volatile(
        "mma.sync.aligned.m16n8k16.row.col.f32.f16.f16.f32 "
        "{%0,%1,%2,%3}, {%4,%5,%6,%7}, {%8,%9}, {%0,%1,%2,%3};"
        : "+f"(d[0]), "+f"(d[1]), "+f"(d[2]), "+f"(d[3])
        : "r"(a[0]), "r"(a[1]), "r"(a[2]), "r"(a[3]), "r"(b[0]), "r"(b[1]));
}
__device__ __forceinline__ void cp16(uint32_t dst, const void* src) {
    asm volatile("cp.async.cg.shared.global [%0], [%1], 16;"
                 :: "r"(dst), "l"(src));
}
#define CP_COMMIT() asm volatile("cp.async.commit_group;" ::: "memory")
#define CP_WAIT(n)  asm volatile("cp.async.wait_group %0;" :: "n"(n) : "memory")

// split a float2 into fp16 hi pair + fp16 lo (residual) pair
__device__ __forceinline__ void split2h(float x, float y,
                                        uint32_t& hi, uint32_t& lo) {
    __half2 h = __floats2half2_rn(x, y);
    float2 hf = __half22float2(h);
    __half2 l = __floats2half2_rn(x - hf.x, y - hf.y);
    hi = *(uint32_t*)&h;
    lo = *(uint32_t*)&l;
}
// exp2 of two fp32 deltas -> packed fp16 probability pair
__device__ __forceinline__ uint32_t exp2_pack(float x, float y) {
    __half2 e = h2exp2(__floats2half2_rn(x, y));
    return *(uint32_t*)&e;
}

// ---------------------------------------------------------------------------
// Conversions: x -> fp16 hi/lo split ; all 4 W -> fp16 (one launch)
// ---------------------------------------------------------------------------
__global__ void split_f16(const float* __restrict__ src,
                          __half* __restrict__ hi, __half* __restrict__ lo,
                          int n4)
{
    int i = blockIdx.x * blockDim.x + threadIdx.x;
    if (i >= n4) return;
    float4 v = ((const float4*)src)[i];
    uint32_t h0, l0, h1, l1;
    split2h(v.x, v.y, h0, l0);
    split2h(v.z, v.w, h1, l1);
    ((uint32_t*)hi)[2 * i + 0] = h0;
    ((uint32_t*)hi)[2 * i + 1] = h1;
    ((uint32_t*)lo)[2 * i + 0] = l0;
    ((uint32_t*)lo)[2 * i + 1] = l1;
}
#define W4_ (C_ * C_ / 4)   // 262144 float4 chunks per weight
__global__ void conv_w4(const float* __restrict__ Wq, const float* __restrict__ Wk,
                        const float* __restrict__ Wv, const float* __restrict__ Wo,
                        __half* __restrict__ dst)
{
    int i = blockIdx.x * blockDim.x + threadIdx.x;   // 0 .. 4*W4_-1
    int wi = i >> 18;                                // /W4_
    int j  = i & (W4_ - 1);
    const float* src = (wi == 0) ? Wq : (wi == 1) ? Wk : (wi == 2) ? Wv : Wo;
    float4 v = ((const float4*)src)[j];
    __half2 a = __floats2half2_rn(v.x, v.y);
    __half2 b = __floats2half2_rn(v.z, v.w);
    ((uint32_t*)dst)[2 * i + 0] = *(uint32_t*)&a;
    ((uint32_t*)dst)[2 * i + 1] = *(uint32_t*)&b;
}

// ---------------------------------------------------------------------------
// HMMA GEMM: out[m,n] = sum_k A[m,k]*W[n,k].
// SPLIT=true:  A = Ah + Al (2 MMA products).  SPLIT=false: A = Ah (1 product).
// CTA 128x128, BK=64, 256 threads (8 warps 64x32), 3-stage cp.async pipeline,
// 128B rows + XOR swizzle.
// MODE 0: fp32 row-major out (Wo),      grid ( 8,64), SPLIT=false, 2 CTA/SM.
// MODE 2: merged K+V head-layout fp16,  grid (16,64), SPLIT=false, 2 CTA/SM.
// MODE 3: Q head-layout fp16 hi/lo*QSCALE, grid (8,64), SPLIT=true, 1 CTA/SM.
// ---------------------------------------------------------------------------
#define BM 128
#define BN 128
#define BK 64
#define GT_B 16384               // 128 rows x 128 bytes

template<int MODE, bool SPLIT>
__global__ void __launch_bounds__(256, SPLIT ? 1 : 2) gemm_f16(
    const __half* __restrict__ Ah, const __half* __restrict__ Al,
    const __half* __restrict__ Wbase,
    float* __restrict__ out,
    __half* __restrict__ qh, __half* __restrict__ ql,
    __half* __restrict__ kh, __half* __restrict__ vh)
{
    constexpr int NTILE = SPLIT ? 3 : 2;         // Ah, [Al], W
    constexpr uint32_t GSTAGE = NTILE * GT_B;
    constexpr int WSLOT = SPLIT ? 2 : 1;

    extern __shared__ char smc[];
    const uint32_t smb = smem_u32(smc);
    const int tid = threadIdx.x;
    const int wid = tid >> 5;
    const int lane = tid & 31;
    const int bm = blockIdx.y * BM;

    int wi, bn;
    if (MODE == 2) { wi = blockIdx.x >> 3; bn = (blockIdx.x & 7) * BN; }
    else           { wi = 0;               bn = blockIdx.x * BN; }
    const __half* Bh = Wbase + (size_t)wi * C_ * C_;

    const int wm = (wid & 1) * 64;
    const int wn = (wid >> 1) * 32;

    const int ldrow = tid >> 3;
    const int ldc16 = tid & 7;
    const uint32_t st_off = (uint32_t)ldrow * 128
                          + (((uint32_t)ldc16 * 16) ^ ((ldrow & 7) << 4));

    auto load_stage = [&](int ch, int s) {
        uint32_t dst = smb + (uint32_t)s * GSTAGE;
        #pragma unroll
        for (int u = 0; u < 4; u++) {
            int row = ldrow + u * 32;
            uint32_t so = st_off + (uint32_t)u * 32 * 128;
            size_t gA = (size_t)(bm + row) * C_ + ch * BK + ldc16 * 8;
            size_t gB = (size_t)(bn + row) * C_ + ch * BK + ldc16 * 8;
            cp16(dst + 0 * GT_B + so, &Ah[gA]);
            if (SPLIT) cp16(dst + 1 * GT_B + so, &Al[gA]);
            cp16(dst + WSLOT * GT_B + so, &Bh[gB]);
        }
    };

    uint32_t a_base[4], a_swz[4];
    #pragma unroll
    for (int mi = 0; mi < 4; mi++) {
        int r = wm + mi * 16 + (lane & 15);
        a_base[mi] = (uint32_t)r * 128;
        a_swz[mi] = (uint32_t)(r & 7) << 4;
    }
    const uint32_t a_lp = (uint32_t)(lane >> 4) * 16;
    uint32_t b_base[4], b_swz[4];
    #pragma unroll
    for (int ni = 0; ni < 4; ni++) {
        int r = wn + ni * 8 + (lane & 7);
        b_base[ni] = (uint32_t)r * 128;
        b_swz[ni] = (uint32_t)(r & 7) << 4;
    }
    const uint32_t b_lp = (uint32_t)(lane >> 3) * 16;

    float acc[4][4][4];
    #pragma unroll
    for (int mi = 0; mi < 4; mi++)
        #pragma unroll
        for (int ni = 0; ni < 4; ni++)
            #pragma unroll
            for (int r = 0; r < 4; r++) acc[mi][ni][r] = 0.f;

    const int nchunk = C_ / BK;             // 16
    load_stage(0, 0); CP_COMMIT();
    load_stage(1, 1); CP_COMMIT();

    int sbuf = 0;
    for (int ch = 0; ch < nchunk; ch++) {
        CP_WAIT(1);
        __syncthreads();
        if (ch + 2 < nchunk) {
            int s = sbuf + 2; if (s >= 3) s -= 3;
            load_stage(ch + 2, s);
            CP_COMMIT();
        }
        const uint32_t sA_hi = smb + (uint32_t)sbuf * GSTAGE + 0 * GT_B;
        const uint32_t sA_lo = smb + (uint32_t)sbuf * GSTAGE + 1 * GT_B;
        const uint32_t sB    = smb + (uint32_t)sbuf * GSTAGE + WSLOT * GT_B;

        #pragma unroll
        for (int kp = 0; kp < 2; kp++) {
            uint32_t bf[4][4];
            #pragma unroll
            for (int ni = 0; ni < 4; ni++)
                ldsm_x4(bf[ni], sB + b_base[ni]
                        + ((((uint32_t)kp * 64) | b_lp) ^ b_swz[ni]));
            #pragma unroll
            for (int sub = 0; sub < 2; sub++) {
                const uint32_t kc = (uint32_t)(kp * 2 + sub) * 32;
                uint32_t ahf[4][4], alf[4][4];
                #pragma unroll
                for (int mi = 0; mi < 4; mi++) {
                    uint32_t ax = (kc | a_lp) ^ a_swz[mi];
                    ldsm_x4(ahf[mi], sA_hi + a_base[mi] + ax);
                    if (SPLIT) ldsm_x4(alf[mi], sA_lo + a_base[mi] + ax);
                }
                #pragma unroll
                for (int mi = 0; mi < 4; mi++)
                    #pragma unroll
                    for (int ni = 0; ni < 4; ni++) {
                        mma_f16(acc[mi][ni], ahf[mi], &bf[ni][sub * 2]);
                        if (SPLIT)
                            mma_f16(acc[mi][ni], alf[mi], &bf[ni][sub * 2]);
                    }
            }
        }
        if (++sbuf == 3) sbuf = 0;
    }

    // Epilogue
    const int mrow0 = bm + wm + (lane >> 2);
    const int ncol0 = wn + 2 * (lane & 3);
    #pragma unroll
    for (int mi = 0; mi < 4; mi++) {
        #pragma unroll
        for (int ni = 0; ni < 4; ni++) {
            int nl = ncol0 + ni * 8;
            #pragma unroll
            for (int half = 0; half < 2; half++) {
                int m = mrow0 + mi * 16 + half * 8;
                float vx = acc[mi][ni][half * 2];
                float vy = acc[mi][ni][half * 2 + 1];
                if (MODE == 0) {
                    int n = bn + nl;
                    *(float2*)&out[(size_t)m * C_ + n] = make_float2(vx, vy);
                } else {
                    int n = bn + nl;
                    int b = m >> 11;
                    int t = m & (T_ - 1);
                    int hh = n >> 6;
                    int d = n & (HD_ - 1);
                    size_t off = (((size_t)b * H_ + hh) * T_ + t) * HD_ + d;
                    if (MODE == 3) {
                        uint32_t h2, l2;
                        split2h(vx * QSCALE, vy * QSCALE, h2, l2);
                        *(uint32_t*)&qh[off] = h2;
                        *(uint32_t*)&ql[off] = l2;
                    } else {          // MODE 2: K or V
                        __half2 h = __floats2half2_rn(vx, vy);
                        *(uint32_t*)&((wi == 0) ? kh : vh)[off] = *(uint32_t*)&h;
                    }
                }
            }
        }
    }
}

// ---------------------------------------------------------------------------
// HMMA flash attention: causal, BQ=128, kv-tile 64, HD=64, 256 threads,
// 2 CTAs/SM, 3-stage KV ring. Scores in LOG2 domain (Q pre-scaled QSCALE).
// Softmax: fp32 max, h2exp2 packed fp16 P, row sums via ones-matrix MMA.
// S = (Qh+Ql)K (2 products). PV single product. Output ctx: fp16 [B,T,C].
// ---------------------------------------------------------------------------
#define FQ_HI 0
#define FQ_LO 16384
#define FSTG(s) (32768 + (s) * 16384)
#define F_K 0
#define F_V 8192
#define FSMEM (32768 + 3 * 16384)   // 81920

__global__ void __launch_bounds__(256, 2) flash_hmma(
    const __half* __restrict__ Qhi, const __half* __restrict__ Qlo,
    const __half* __restrict__ Kh, const __half* __restrict__ Vh,
    __half* __restrict__ ctx_hi)
{
    extern __shared__ char sm[];
    const uint32_t smb = smem_u32(sm);
    const int tid = threadIdx.x;
    const int wid = tid >> 5;
    const int lane = tid & 31;
    const int qb = (int)gridDim.x - 1 - (int)blockIdx.x;   // heavy tiles first
    const int bh = blockIdx.y;
    const size_t base = (size_t)bh * T_ * HD_;
    const int q0 = qb * 128;
    const int nkv = 2 * qb + 2;

    #pragma unroll
    for (int u = 0; u < 4; u++) {
        int c = tid + u * 256;
        int row = c >> 3;
        int c16 = c & 7;
        uint32_t d = (uint32_t)row * 128 + (((uint32_t)c16 * 16) ^ ((row & 7) << 4));
        size_t g = base + (size_t)(q0 + row) * HD_ + c16 * 8;
        cp16(smb + FQ_HI + d, &Qhi[g]);
        cp16(smb + FQ_LO + d, &Qlo[g]);
    }
    CP_COMMIT();

    auto load_kv = [&](int kt) {
        if (kt < nkv) {
            uint32_t dst = smb + FSTG(kt % 3);
            const int k0 = kt * 64;
            #pragma unroll
            for (int u = 0; u < 2; u++) {
                int c = tid + u * 256;
                int row = c >> 3;
                int c16 = c & 7;
                uint32_t d = (uint32_t)row * 128
                           + (((uint32_t)c16 * 16) ^ ((row & 7) << 4));
                size_t g = base + (size_t)(k0 + row) * HD_ + c16 * 8;
                cp16(dst + F_K + d, &Kh[g]);
                cp16(dst + F_V + d, &Vh[g]);
            }
        }
        CP_COMMIT();
    };
    load_kv(0);
    load_kv(1);
    load_kv(2);

    float oacc[8][4];
    #pragma unroll
    for (int nt = 0; nt < 8; nt++)
        #pragma unroll
        for (int r = 0; r < 4; r++) oacc[nt][r] = 0.f;
    float mrow[2] = {-1e30f, -1e30f};
    float lrow[2] = {0.f, 0.f};

    const int arow = wid * 16 + (lane & 7) + ((lane >> 3) & 1) * 8;
    const uint32_t a_base = (uint32_t)arow * 128;
    const uint32_t a_swz = (uint32_t)(arow & 7) << 4;
    const uint32_t a_lp = (uint32_t)(lane >> 4) * 16;

    const int krow = (lane & 7) + (lane >> 4) * 8;
    const uint32_t kcol = (uint32_t)((lane >> 3) & 1) * 16;
    const int vrow = (lane & 7) + ((lane >> 3) & 1) * 8;
    const uint32_t vcol = (uint32_t)(lane >> 4) * 16;

    const uint32_t onesb[2] = {0x3C003C00u, 0x3C003C00u};   // fp16 1.0 pairs

    for (int kb = 0; kb < nkv; kb++) {
        const uint32_t stg = smb + FSTG(kb % 3);
        CP_WAIT(2);
        __syncthreads();

        // ---------- S = Q K^T (2 products; Q frags from smem) ----------
        float sc[8][4];
        #pragma unroll
        for (int nt = 0; nt < 8; nt++)
            #pragma unroll
            for (int r = 0; r < 4; r++) sc[nt][r] = 0.f;

        #pragma unroll
        for (int ks = 0; ks < 4; ks++) {
            uint32_t qhf[4], qlf[4];
            {
                uint32_t ax = (((uint32_t)ks * 32) | a_lp) ^ a_swz;
                ldsm_x4(qhf, smb + FQ_HI + a_base + ax);
                ldsm_x4(qlf, smb + FQ_LO + a_base + ax);
            }
            uint32_t kf[4][4];
            #pragma unroll
            for (int nt2 = 0; nt2 < 4; nt2++) {
                int row = nt2 * 16 + krow;
                uint32_t colb = (uint32_t)ks * 32 + kcol;
                uint32_t ad = (uint32_t)row * 128 + (colb ^ ((row & 7) << 4));
                ldsm_x4(kf[nt2], stg + F_K + ad);
            }
            #pragma unroll
            for (int nt = 0; nt < 8; nt++) {
                const uint32_t* bb = &kf[nt >> 1][(nt & 1) * 2];
                mma_f16(sc[nt], qhf, bb);
                mma_f16(sc[nt], qlf, bb);
            }
        }

        // ---------- causal mask (last two tiles only) ----------
        if (kb >= nkv - 2) {
            int grow0 = q0 + wid * 16 + (lane >> 2);
            int gcol0 = kb * 64 + 2 * (lane & 3);
            #pragma unroll
            for (int nt = 0; nt < 8; nt++)
                #pragma unroll
                for (int e = 0; e < 4; e++) {
                    int col = gcol0 + nt * 8 + (e & 1);
                    int row = grow0 + (e >> 1) * 8;
                    if (col > row) sc[nt][e] = -1e30f;
                }
        }

        // ---------- online softmax (log2 domain) ----------
        float mx0 = -1e30f, mx1 = -1e30f;
        #pragma unroll
        for (int nt = 0; nt < 8; nt++) {
            mx0 = fmaxf(mx0, fmaxf(sc[nt][0], sc[nt][1]));
            mx1 = fmaxf(mx1, fmaxf(sc[nt][2], sc[nt][3]));
        }
        mx0 = fmaxf(mx0, __shfl_xor_sync(0xffffffffu, mx0, 1));
        mx0 = fmaxf(mx0, __shfl_xor_sync(0xffffffffu, mx0, 2));
        mx1 = fmaxf(mx1, __shfl_xor_sync(0xffffffffu, mx1, 1));
        mx1 = fmaxf(mx1, __shfl_xor_sync(0xffffffffu, mx1, 2));
        float mn0 = fmaxf(mrow[0], mx0);
        float mn1 = fmaxf(mrow[1], mx1);
        float cs0 = exp2f(mrow[0] - mn0);
        float cs1 = exp2f(mrow[1] - mn1);
        mrow[0] = mn0; mrow[1] = mn1;

        // P = exp2(s - m), packed fp16 pairs (A-fragment layout);
        // row sums via ones-matrix MMA (cross-thread reduction in HW).
        uint32_t pk[4][4];
        float lacc[4] = {0.f, 0.f, 0.f, 0.f};
        #pragma unroll
        for (int ks = 0; ks < 4; ks++) {
            pk[ks][0] = exp2_pack(sc[2 * ks][0] - mn0,     sc[2 * ks][1] - mn0);
            pk[ks][1] = exp2_pack(sc[2 * ks][2] - mn1,     sc[2 * ks][3] - mn1);
            pk[ks][2] = exp2_pack(sc[2 * ks + 1][0] - mn0, sc[2 * ks + 1][1] - mn0);
            pk[ks][3] = exp2_pack(sc[2 * ks + 1][2] - mn1, sc[2 * ks + 1][3] - mn1);
            mma_f16(lacc, pk[ks], onesb);
        }
        lrow[0] = lrow[0] * cs0 + lacc[0];
        lrow[1] = lrow[1] * cs1 + lacc[2];
        #pragma unroll
        for (int nt = 0; nt < 8; nt++) {
            oacc[nt][0] *= cs0; oacc[nt][1] *= cs0;
            oacc[nt][2] *= cs1; oacc[nt][3] *= cs1;
        }

        // ---------- O += P V (single product; P already packed) ----------
        #pragma unroll
        for (int ks = 0; ks < 4; ks++) {
            #pragma unroll
            for (int nt2 = 0; nt2 < 4; nt2++) {
                int row = ks * 16 + vrow;
                uint32_t colb = (uint32_t)nt2 * 32 + vcol;
                uint32_t ad = (uint32_t)row * 128 + (colb ^ ((row & 7) << 4));
                uint32_t vf[4];
                ldsm_x4_t(vf, stg + F_V + ad);
                mma_f16(oacc[2 * nt2],     pk[ks], &vf[0]);
                mma_f16(oacc[2 * nt2 + 1], pk[ks], &vf[2]);
            }
        }

        __syncthreads();
        load_kv(kb + 3);
    }

    // ---------- normalize + store ctx as fp16 ----------
    float inv0 = 1.f / lrow[0];
    float inv1 = 1.f / lrow[1];
    const int b = bh >> 4;
    const int hh = bh & 15;
    #pragma unroll
    for (int h = 0; h < 2; h++) {
        float inv = h ? inv1 : inv0;
        int t = q0 + wid * 16 + (lane >> 2) + h * 8;
        #pragma unroll
        for (int nt = 0; nt < 8; nt++) {
            int col = hh * 64 + nt * 8 + 2 * (lane & 3);
            size_t off = ((size_t)b * T_ + t) * C_ + col;
            __half2 hv = __floats2half2_rn(oacc[nt][2 * h] * inv,
                                           oacc[nt][2 * h + 1] * inv);
            *(uint32_t*)&ctx_hi[off] = *(uint32_t*)&hv;
        }
    }
}

// ---------------------------------------------------------------------------
// kernel_launch
// ---------------------------------------------------------------------------
extern "C" void kernel_launch(void* const* d_in, const int* in_sizes, int n_in,
                              void* d_out, int out_size)
{
    const float* x  = (const float*)d_in[0];
    const float* Wq = (const float*)d_in[1];
    const float* Wk = (const float*)d_in[2];
    const float* Wv = (const float*)d_in[3];
    const float* Wo = (const float*)d_in[4];
    float* out = (float*)d_out;

    __half *xh, *xl, *wh, *qh, *ql, *kh, *vh, *ch;
    cudaGetSymbolAddress((void**)&xh, g_Xh);
    cudaGetSymbolAddress((void**)&xl, g_Xl);
    cudaGetSymbolAddress((void**)&wh, g_Wh);
    cudaGetSymbolAddress((void**)&qh, g_Qh);
    cudaGetSymbolAddress((void**)&ql, g_Ql);
    cudaGetSymbolAddress((void**)&kh, g_Kh);
    cudaGetSymbolAddress((void**)&vh, g_Vh);
    cudaGetSymbolAddress((void**)&ch, g_CTXh);

    cudaFuncSetAttribute(gemm_f16<3, true>,
                         cudaFuncAttributeMaxDynamicSharedMemorySize,
                         3 * 3 * GT_B);
    cudaFuncSetAttribute(gemm_f16<2, false>,
                         cudaFuncAttributeMaxDynamicSharedMemorySize,
                         3 * 2 * GT_B);
    cudaFuncSetAttribute(gemm_f16<0, false>,
                         cudaFuncAttributeMaxDynamicSharedMemorySize,
                         3 * 2 * GT_B);
    cudaFuncSetAttribute(flash_hmma,
                         cudaFuncAttributeMaxDynamicSharedMemorySize, FSMEM);

    // Conversions: 2 launches total
    {
        int n4 = M_ * C_ / 4;
        split_f16<<<n4 / 256, 256>>>(x, xh, xl, n4);
        conv_w4<<<4 * W4_ / 256, 256>>>(Wq, Wk, Wv, Wo, wh);
    }

    // Q projection: split-A 2-product (scores are error-sensitive)
    gemm_f16<3, true><<<dim3(8, M_ / BM), 256, 3 * 3 * GT_B>>>(
        xh, xl, wh + 0 * (size_t)C_ * C_, nullptr, qh, ql, nullptr, nullptr);

    // K+V merged projection: single product, 2 CTAs/SM
    gemm_f16<2, false><<<dim3(16, M_ / BM), 256, 3 * 2 * GT_B>>>(
        xh, nullptr, wh + 1 * (size_t)C_ * C_, nullptr,
        nullptr, nullptr, kh, vh);

    // Causal flash attention (2 CTAs/SM, log2-domain softmax)
    flash_hmma<<<dim3(T_ / 128, B_ * H_), 256, FSMEM>>>(
        qh, ql, kh, vh, ch);

    // Output projection (fp32 out), single-product, 2 CTAs/SM
    gemm_f16<0, false><<<dim3(8, M_ / BM), 256, 3 * 2 * GT_B>>>(
        ch, nullptr, wh + 3 * (size_t)C_ * C_, out,
        nullptr, nullptr, nullptr, nullptr);
}